// round 1
// baseline (speedup 1.0000x reference)
#include <cuda_runtime.h>
#include <math.h>

// Problem dims
#define BB 2
#define SS 2048
#define DD 1024
#define HH 16
#define DH 64
#define FF 4096
#define EE 8
#define NT (BB*SS)   // 4096 tokens

// ---------------- scratch (device globals; no allocation allowed) ----------------
__device__ float g_h[NT*DD];          // layernorm output
__device__ float g_q[NT*DD];
__device__ float g_k[NT*DD];
__device__ float g_v[NT*DD];
__device__ float g_attn[NT*DD];       // attention output (pre O-proj)
__device__ float g_x1[NT*DD];         // x + attn@Wo (residual 1)
__device__ int   g_cnt[EE];
__device__ int   g_tok[EE*NT];
__device__ int   g_slotid[EE*NT];
__device__ float g_wt[EE*NT];
__device__ float g_h1[(size_t)EE*NT*FF];       // 512 MB fp32 expert hidden
__device__ float g_contrib[(size_t)2*NT*DD];   // per-(token,k) weighted expert out

// ---------------- layernorm ----------------
__global__ void ln_kernel(const float* __restrict__ x, const float* __restrict__ g,
                          const float* __restrict__ b) {
    __shared__ float red[256];
    int t = blockIdx.x, tid = threadIdx.x;
    const float* xr = x + (size_t)t * DD;
    float v[4], s = 0.f, s2 = 0.f;
#pragma unroll
    for (int i = 0; i < 4; i++) {
        float vv = xr[tid + i*256];
        v[i] = vv; s += vv; s2 += vv*vv;
    }
    red[tid] = s; __syncthreads();
    for (int o = 128; o > 0; o >>= 1) { if (tid < o) red[tid] += red[tid+o]; __syncthreads(); }
    float mean = red[0] * (1.f/DD);
    __syncthreads();
    red[tid] = s2; __syncthreads();
    for (int o = 128; o > 0; o >>= 1) { if (tid < o) red[tid] += red[tid+o]; __syncthreads(); }
    float var = red[0] * (1.f/DD) - mean*mean;
    float rs = rsqrtf(var + 1e-5f);
    float* out = g_h + (size_t)t * DD;
#pragma unroll
    for (int i = 0; i < 4; i++) {
        int c = tid + i*256;
        out[c] = (v[i]-mean)*rs*g[c] + b[c];
    }
}

// ---------------- generic tiled SGEMM: C[M,N] = A[M,K]@B[K,N] (+residual) ----------------
// BM=BN=64, BK=16, 256 threads, 4x4 microtile. M%64==0, N%64==0, K%16==0.
__global__ void sgemm_kernel(const float* __restrict__ A, const float* __restrict__ B,
                             float* __restrict__ C, int M, int N, int Kd,
                             const float* __restrict__ residual) {
    __shared__ float As[16][68];   // As[k][m] (transposed)
    __shared__ float Bs[16][68];
    int tid = threadIdx.x;
    int m0 = blockIdx.y * 64, n0 = blockIdx.x * 64;
    int tx = tid & 15, ty = tid >> 4;
    int la_row = tid >> 2, la_seg = tid & 3;
    int lb_row = tid >> 4, lb_c4 = tid & 15;
    float acc[4][4] = {};
    for (int k0 = 0; k0 < Kd; k0 += 16) {
        float4 av = *(const float4*)&A[(size_t)(m0+la_row)*Kd + k0 + la_seg*4];
        float4 bv = *(const float4*)&B[(size_t)(k0+lb_row)*N + n0 + lb_c4*4];
        As[la_seg*4+0][la_row] = av.x;
        As[la_seg*4+1][la_row] = av.y;
        As[la_seg*4+2][la_row] = av.z;
        As[la_seg*4+3][la_row] = av.w;
        *(float4*)&Bs[lb_row][lb_c4*4] = bv;
        __syncthreads();
#pragma unroll
        for (int kk = 0; kk < 16; kk++) {
            float4 a4 = *(const float4*)&As[kk][ty*4];
            float4 b4 = *(const float4*)&Bs[kk][tx*4];
            acc[0][0] += a4.x*b4.x; acc[0][1] += a4.x*b4.y; acc[0][2] += a4.x*b4.z; acc[0][3] += a4.x*b4.w;
            acc[1][0] += a4.y*b4.x; acc[1][1] += a4.y*b4.y; acc[1][2] += a4.y*b4.z; acc[1][3] += a4.y*b4.w;
            acc[2][0] += a4.z*b4.x; acc[2][1] += a4.z*b4.y; acc[2][2] += a4.z*b4.z; acc[2][3] += a4.z*b4.w;
            acc[3][0] += a4.w*b4.x; acc[3][1] += a4.w*b4.y; acc[3][2] += a4.w*b4.z; acc[3][3] += a4.w*b4.w;
        }
        __syncthreads();
    }
#pragma unroll
    for (int i = 0; i < 4; i++) {
        size_t row = (size_t)(m0 + ty*4 + i);
#pragma unroll
        for (int j = 0; j < 4; j++) {
            int col = n0 + tx*4 + j;
            float v = acc[i][j];
            if (residual) v += residual[row*N + col];
            C[row*N + col] = v;
        }
    }
}

// ---------------- flash attention: per (b,h), 64-row Q tiles, online softmax ----------------
__global__ void attn_kernel(const float* __restrict__ Q, const float* __restrict__ Kp,
                            const float* __restrict__ Vp, float* __restrict__ O) {
    extern __shared__ float sm[];
    float* Qs  = sm;              // [64][68]  Qs[tok][d]
    float* KsT = sm + 64*68;      // [64][68]  KsT[d][tok]
    float* Vs  = sm + 2*64*68;    // [64][68]  Vs[tok][d]
    float* Ss  = sm + 3*64*68;    // [64][68]  scores/probs
    __shared__ float m_s[64], l_s[64], alpha_s[64];

    int tid = threadIdx.x;
    int bh = blockIdx.y; int b = bh >> 4, h = bh & 15;
    int q0 = blockIdx.x * 64;
    int r = tid >> 2, qq = tid & 3;
    const size_t base = ((size_t)b*SS)*DD + h*DH;

    { // load Q tile
        int lr = tid >> 2, seg = tid & 3;
        const float* src = Q + base + (size_t)(q0+lr)*DD + seg*16;
#pragma unroll
        for (int i = 0; i < 4; i++) {
            float4 v = *(const float4*)(src + i*4);
            *(float4*)&Qs[lr*68 + seg*16 + i*4] = v;
        }
    }
    if (tid < 64) { m_s[tid] = -1e30f; l_s[tid] = 0.f; }
    float acc[16];
#pragma unroll
    for (int i = 0; i < 16; i++) acc[i] = 0.f;

    for (int kt = 0; kt < SS/64; kt++) {
        __syncthreads();
        { // load K (transposed) + V tiles
            int lr = tid >> 2, seg = tid & 3;
            const float* ksrc = Kp + base + (size_t)(kt*64+lr)*DD + seg*16;
            const float* vsrc = Vp + base + (size_t)(kt*64+lr)*DD + seg*16;
#pragma unroll
            for (int i = 0; i < 4; i++) {
                float4 kv = *(const float4*)(ksrc + i*4);
                int c = seg*16 + i*4;
                KsT[(c+0)*68 + lr] = kv.x;
                KsT[(c+1)*68 + lr] = kv.y;
                KsT[(c+2)*68 + lr] = kv.z;
                KsT[(c+3)*68 + lr] = kv.w;
                float4 vv = *(const float4*)(vsrc + i*4);
                *(float4*)&Vs[lr*68 + c] = vv;
            }
        }
        __syncthreads();
        { // scores: Ss[r][c] = 0.125 * sum_d Qs[r][d]*K[c][d]
            float accs[16];
#pragma unroll
            for (int i = 0; i < 16; i++) accs[i] = 0.f;
#pragma unroll 8
            for (int d = 0; d < 64; d++) {
                float qv = Qs[r*68 + d];
#pragma unroll
                for (int m = 0; m < 4; m++) {
                    float4 kv = *(const float4*)&KsT[d*68 + m*16 + qq*4];
                    accs[m*4+0] += qv*kv.x; accs[m*4+1] += qv*kv.y;
                    accs[m*4+2] += qv*kv.z; accs[m*4+3] += qv*kv.w;
                }
            }
#pragma unroll
            for (int m = 0; m < 4; m++) {
                float4 o4 = make_float4(accs[m*4+0]*0.125f, accs[m*4+1]*0.125f,
                                        accs[m*4+2]*0.125f, accs[m*4+3]*0.125f);
                *(float4*)&Ss[r*68 + m*16 + qq*4] = o4;
            }
        }
        __syncthreads();
        if (tid < 64) { // online softmax per row
            int rr = tid;
            float mo = m_s[rr], mx = mo;
            for (int j = 0; j < 64; j++) mx = fmaxf(mx, Ss[rr*68+j]);
            float a = __expf(mo - mx);
            float s = 0.f;
            for (int j = 0; j < 64; j++) {
                float e = __expf(Ss[rr*68+j] - mx);
                Ss[rr*68+j] = e; s += e;
            }
            m_s[rr] = mx; l_s[rr] = l_s[rr]*a + s; alpha_s[rr] = a;
        }
        __syncthreads();
        { // acc = acc*alpha + P@V
            float a = alpha_s[r];
#pragma unroll
            for (int i = 0; i < 16; i++) acc[i] *= a;
#pragma unroll 8
            for (int kk = 0; kk < 64; kk++) {
                float p = Ss[r*68 + kk];
#pragma unroll
                for (int m = 0; m < 4; m++) {
                    float4 vv = *(const float4*)&Vs[kk*68 + m*16 + qq*4];
                    acc[m*4+0] += p*vv.x; acc[m*4+1] += p*vv.y;
                    acc[m*4+2] += p*vv.z; acc[m*4+3] += p*vv.w;
                }
            }
        }
    }
    __syncthreads();
    float inv = 1.f / l_s[r];
    float* dst = O + base + (size_t)(q0+r)*DD;
#pragma unroll
    for (int m = 0; m < 4; m++) {
        int c = m*16 + qq*4;
        float4 o4 = make_float4(acc[m*4+0]*inv, acc[m*4+1]*inv,
                                acc[m*4+2]*inv, acc[m*4+3]*inv);
        *(float4*)&dst[c] = o4;
    }
}

// ---------------- gate: logits, softmax-top2, expert binning ----------------
__global__ void zero_cnt_kernel() { if (threadIdx.x < EE) g_cnt[threadIdx.x] = 0; }

__global__ void gate_kernel(const float* __restrict__ xin, const float* __restrict__ Wg) {
    __shared__ float lg[EE];
    int t = blockIdx.x, tid = threadIdx.x;
    int w = tid >> 5, lane = tid & 31;
    const float* xr = xin + (size_t)t * DD;
    float s = 0.f;
    for (int d = lane; d < DD; d += 32) s += xr[d] * Wg[d*EE + w];
#pragma unroll
    for (int o = 16; o > 0; o >>= 1) s += __shfl_down_sync(0xffffffffu, s, o);
    if (lane == 0) lg[w] = s;
    __syncthreads();
    if (tid == 0) {
        float v0 = -1e30f; int i0 = 0;
        for (int e = 0; e < EE; e++) if (lg[e] > v0) { v0 = lg[e]; i0 = e; }
        float v1 = -1e30f; int i1 = 0;
        for (int e = 0; e < EE; e++) if (e != i0 && lg[e] > v1) { v1 = lg[e]; i1 = e; }
        float e1 = __expf(v1 - v0);
        float w0 = 1.f / (1.f + e1);
        float w1 = e1 / (1.f + e1);
        int p0 = atomicAdd(&g_cnt[i0], 1);
        g_tok[i0*NT + p0] = t; g_slotid[i0*NT + p0] = 2*t;     g_wt[i0*NT + p0] = w0;
        int p1 = atomicAdd(&g_cnt[i1], 1);
        g_tok[i1*NT + p1] = t; g_slotid[i1*NT + p1] = 2*t + 1; g_wt[i1*NT + p1] = w1;
    }
}

// ---------------- MoE FFN1: h1 = gelu(gather(x) @ W1[e] + b1[e]) ----------------
__global__ void moe_ffn1_kernel(const float* __restrict__ xin, const float* __restrict__ W1,
                                const float* __restrict__ b1) {
    int e = blockIdx.z;
    int cnt = g_cnt[e];
    int m0 = blockIdx.y * 64;
    if (m0 >= cnt) return;
    int n0 = blockIdx.x * 64;
    __shared__ float As[16][68];
    __shared__ float Bs[16][68];
    __shared__ int toks[64];
    int tid = threadIdx.x;
    if (tid < 64) {
        int r = m0 + tid; if (r > cnt-1) r = cnt-1;
        toks[tid] = g_tok[e*NT + r];
    }
    __syncthreads();
    const float* Bp = W1 + (size_t)e * DD * FF;
    int tx = tid & 15, ty = tid >> 4;
    int la_row = tid >> 2, la_seg = tid & 3;
    int lb_row = tid >> 4, lb_c4 = tid & 15;
    float acc[4][4] = {};
    for (int k0 = 0; k0 < DD; k0 += 16) {
        float4 av = *(const float4*)&xin[(size_t)toks[la_row]*DD + k0 + la_seg*4];
        float4 bv = *(const float4*)&Bp[(size_t)(k0+lb_row)*FF + n0 + lb_c4*4];
        As[la_seg*4+0][la_row] = av.x;
        As[la_seg*4+1][la_row] = av.y;
        As[la_seg*4+2][la_row] = av.z;
        As[la_seg*4+3][la_row] = av.w;
        *(float4*)&Bs[lb_row][lb_c4*4] = bv;
        __syncthreads();
#pragma unroll
        for (int kk = 0; kk < 16; kk++) {
            float4 a4 = *(const float4*)&As[kk][ty*4];
            float4 b4 = *(const float4*)&Bs[kk][tx*4];
            acc[0][0] += a4.x*b4.x; acc[0][1] += a4.x*b4.y; acc[0][2] += a4.x*b4.z; acc[0][3] += a4.x*b4.w;
            acc[1][0] += a4.y*b4.x; acc[1][1] += a4.y*b4.y; acc[1][2] += a4.y*b4.z; acc[1][3] += a4.y*b4.w;
            acc[2][0] += a4.z*b4.x; acc[2][1] += a4.z*b4.y; acc[2][2] += a4.z*b4.z; acc[2][3] += a4.z*b4.w;
            acc[3][0] += a4.w*b4.x; acc[3][1] += a4.w*b4.y; acc[3][2] += a4.w*b4.z; acc[3][3] += a4.w*b4.w;
        }
        __syncthreads();
    }
#pragma unroll
    for (int i = 0; i < 4; i++) {
        int rr = m0 + ty*4 + i;
        if (rr >= cnt) continue;
        float* dst = g_h1 + ((size_t)e*NT + rr)*FF + n0;
#pragma unroll
        for (int j = 0; j < 4; j++) {
            int c = n0 + tx*4 + j;
            float u = acc[i][j] + b1[e*FF + c];
            float u3 = u*u*u;
            dst[tx*4+j] = 0.5f*u*(1.f + tanhf(0.7978845608028654f*(u + 0.044715f*u3)));
        }
    }
}

// ---------------- MoE FFN2: contrib[slot] = w * (h1 @ W2[e] + b2[e]) ----------------
__global__ void moe_ffn2_kernel(const float* __restrict__ W2, const float* __restrict__ b2) {
    int e = blockIdx.z;
    int cnt = g_cnt[e];
    int m0 = blockIdx.y * 64;
    if (m0 >= cnt) return;
    int n0 = blockIdx.x * 64;
    __shared__ float As[16][68];
    __shared__ float Bs[16][68];
    int tid = threadIdx.x;
    const float* Ap = g_h1 + (size_t)e * NT * FF;
    const float* Bp = W2 + (size_t)e * FF * DD;
    int tx = tid & 15, ty = tid >> 4;
    int la_row = tid >> 2, la_seg = tid & 3;
    int lb_row = tid >> 4, lb_c4 = tid & 15;
    float acc[4][4] = {};
    for (int k0 = 0; k0 < FF; k0 += 16) {
        float4 av = *(const float4*)&Ap[(size_t)(m0+la_row)*FF + k0 + la_seg*4];
        float4 bv = *(const float4*)&Bp[(size_t)(k0+lb_row)*DD + n0 + lb_c4*4];
        As[la_seg*4+0][la_row] = av.x;
        As[la_seg*4+1][la_row] = av.y;
        As[la_seg*4+2][la_row] = av.z;
        As[la_seg*4+3][la_row] = av.w;
        *(float4*)&Bs[lb_row][lb_c4*4] = bv;
        __syncthreads();
#pragma unroll
        for (int kk = 0; kk < 16; kk++) {
            float4 a4 = *(const float4*)&As[kk][ty*4];
            float4 b4 = *(const float4*)&Bs[kk][tx*4];
            acc[0][0] += a4.x*b4.x; acc[0][1] += a4.x*b4.y; acc[0][2] += a4.x*b4.z; acc[0][3] += a4.x*b4.w;
            acc[1][0] += a4.y*b4.x; acc[1][1] += a4.y*b4.y; acc[1][2] += a4.y*b4.z; acc[1][3] += a4.y*b4.w;
            acc[2][0] += a4.z*b4.x; acc[2][1] += a4.z*b4.y; acc[2][2] += a4.z*b4.z; acc[2][3] += a4.z*b4.w;
            acc[3][0] += a4.w*b4.x; acc[3][1] += a4.w*b4.y; acc[3][2] += a4.w*b4.z; acc[3][3] += a4.w*b4.w;
        }
        __syncthreads();
    }
#pragma unroll
    for (int i = 0; i < 4; i++) {
        int rr = m0 + ty*4 + i;
        if (rr >= cnt) continue;
        int slot = g_slotid[e*NT + rr];
        float w = g_wt[e*NT + rr];
        float* dst = g_contrib + (size_t)slot * DD;
#pragma unroll
        for (int j = 0; j < 4; j++) {
            int c = n0 + tx*4 + j;
            dst[c] = w * (acc[i][j] + b2[e*DD + c]);
        }
    }
}

// ---------------- final combine: out = x1 + contrib(2t) + contrib(2t+1) ----------------
__global__ void combine_kernel(float* __restrict__ out) {
    int t = blockIdx.x;                  // one token per block (1024 floats)
    int c = threadIdx.x * 4;
    size_t idx = (size_t)t * DD + c;
    float4 a  = *(const float4*)&g_x1[idx];
    float4 c0 = *(const float4*)&g_contrib[(size_t)(2*t)*DD + c];
    float4 c1 = *(const float4*)&g_contrib[(size_t)(2*t+1)*DD + c];
    float4 o = make_float4(a.x+c0.x+c1.x, a.y+c0.y+c1.y, a.z+c0.z+c1.z, a.w+c0.w+c1.w);
    *(float4*)&out[idx] = o;
}

// ---------------- launch ----------------
extern "C" void kernel_launch(void* const* d_in, const int* in_sizes, int n_in,
                              void* d_out, int out_size) {
    const float* x    = (const float*)d_in[0];
    const float* ln_g = (const float*)d_in[1];
    const float* ln_b = (const float*)d_in[2];
    const float* Wq   = (const float*)d_in[3];
    const float* Wk   = (const float*)d_in[4];
    const float* Wv   = (const float*)d_in[5];
    const float* Wo   = (const float*)d_in[6];
    const float* Wg   = (const float*)d_in[7];
    const float* W1   = (const float*)d_in[8];
    const float* b1   = (const float*)d_in[9];
    const float* W2   = (const float*)d_in[10];
    const float* b2   = (const float*)d_in[11];
    float* out = (float*)d_out;

    float *p_h, *p_q, *p_k, *p_v, *p_attn, *p_x1;
    cudaGetSymbolAddress((void**)&p_h,    g_h);
    cudaGetSymbolAddress((void**)&p_q,    g_q);
    cudaGetSymbolAddress((void**)&p_k,    g_k);
    cudaGetSymbolAddress((void**)&p_v,    g_v);
    cudaGetSymbolAddress((void**)&p_attn, g_attn);
    cudaGetSymbolAddress((void**)&p_x1,   g_x1);

    const int ATT_SMEM = 4*64*68*4;   // 69632 bytes
    cudaFuncSetAttribute(attn_kernel, cudaFuncAttributeMaxDynamicSharedMemorySize, ATT_SMEM);

    // 1) layernorm
    ln_kernel<<<NT, 256>>>(x, ln_g, ln_b);
    // 2) QKV projections
    dim3 gQKV(DD/64, NT/64);
    sgemm_kernel<<<gQKV, 256>>>(p_h, Wq, p_q, NT, DD, DD, nullptr);
    sgemm_kernel<<<gQKV, 256>>>(p_h, Wk, p_k, NT, DD, DD, nullptr);
    sgemm_kernel<<<gQKV, 256>>>(p_h, Wv, p_v, NT, DD, DD, nullptr);
    // 3) attention
    attn_kernel<<<dim3(SS/64, BB*HH), 256, ATT_SMEM>>>(p_q, p_k, p_v, p_attn);
    // 4) O projection + residual
    sgemm_kernel<<<gQKV, 256>>>(p_attn, Wo, p_x1, NT, DD, DD, x);
    // 5) gate + binning
    zero_cnt_kernel<<<1, 32>>>();
    gate_kernel<<<NT, 256>>>(p_x1, Wg);
    // 6) grouped expert FFN
    moe_ffn1_kernel<<<dim3(FF/64, NT/64, EE), 256>>>(p_x1, W1, b1);
    moe_ffn2_kernel<<<dim3(DD/64, NT/64, EE), 256>>>(W2, b2);
    // 7) combine + residual 2
    combine_kernel<<<NT, 256>>>(out);
}

// round 2
// speedup vs baseline: 1.6294x; 1.6294x over previous
#include <cuda_runtime.h>
#include <math.h>

// Problem dims
#define BB 2
#define SS 2048
#define DD 1024
#define HH 16
#define DH 64
#define FF 4096
#define EE 8
#define NT (BB*SS)   // 4096 tokens

// ---------------- scratch (device globals; no allocation allowed) ----------------
__device__ float g_h[NT*DD];          // layernorm output
__device__ float g_q[NT*DD];
__device__ float g_k[NT*DD];
__device__ float g_v[NT*DD];
__device__ float g_attn[NT*DD];       // attention output (pre O-proj)
__device__ float g_x1[NT*DD];         // x + attn@Wo (residual 1)
__device__ int   g_cnt[EE];
__device__ int   g_tok[EE*NT];
__device__ int   g_slotid[EE*NT];
__device__ float g_wt[EE*NT];
__device__ float g_h1[(size_t)EE*NT*FF];       // fp32 expert hidden
__device__ float g_contrib[(size_t)2*NT*DD];   // per-(token,k) weighted expert out

// ---------------- helpers ----------------
__device__ __forceinline__ unsigned f2tf(float f) {
    unsigned u; asm("cvt.rna.tf32.f32 %0, %1;" : "=r"(u) : "f"(f)); return u;
}

// mma compute over one BK=16 slab. As[128][20] (m-major), Bs[16][132] (k-major).
__device__ __forceinline__ void mma_tile(const unsigned (*As)[20], const unsigned (*Bs)[132],
                                         int lane, int wm, int wn, float (&acc)[4][4][4]) {
    const int g = lane >> 2, q = lane & 3;
#pragma unroll
    for (int ks = 0; ks < 2; ks++) {
        const int kb = ks * 8;
        unsigned a[4][4], b[4][2];
#pragma unroll
        for (int i = 0; i < 4; i++) {
            int m = wm + i*16 + g;
            a[i][0] = As[m][kb + q];
            a[i][1] = As[m+8][kb + q];
            a[i][2] = As[m][kb + 4 + q];
            a[i][3] = As[m+8][kb + 4 + q];
        }
#pragma unroll
        for (int j = 0; j < 4; j++) {
            int n = wn + j*8 + g;
            b[j][0] = Bs[kb + q][n];
            b[j][1] = Bs[kb + 4 + q][n];
        }
#pragma unroll
        for (int i = 0; i < 4; i++)
#pragma unroll
            for (int j = 0; j < 4; j++)
                asm volatile("mma.sync.aligned.m16n8k8.row.col.f32.tf32.tf32.f32 "
                    "{%0,%1,%2,%3}, {%4,%5,%6,%7}, {%8,%9}, {%0,%1,%2,%3};"
                    : "+f"(acc[i][j][0]), "+f"(acc[i][j][1]),
                      "+f"(acc[i][j][2]), "+f"(acc[i][j][3])
                    : "r"(a[i][0]), "r"(a[i][1]), "r"(a[i][2]), "r"(a[i][3]),
                      "r"(b[j][0]), "r"(b[j][1]));
    }
}

// Core mainloop: C_tile(128x128) += A(128,K) @ B(K, Ndim) at column offset n0.
// aptr = this thread's A row base (row = tid>>1). Register-prefetch pipeline.
__device__ __forceinline__ void gemm_core(const float* __restrict__ aptr,
                                          const float* __restrict__ Bg,
                                          int Kdim, int Ndim, int n0,
                                          float (&acc)[4][4][4],
                                          unsigned (*As)[20], unsigned (*Bs)[132]) {
    const int t = threadIdx.x;
    const int lane = t & 31, warp = t >> 5;
    const int wm = (warp >> 2) * 64, wn = (warp & 3) * 32;
    const int abase = 8 * (t & 1);         // col offset within A row slab
    const int arow_s = t >> 1;
    const int brow_s = t >> 4;
    const int bcol = 8 * (t & 15);

    float4 ra0 = *(const float4*)(aptr + abase);
    float4 ra1 = *(const float4*)(aptr + abase + 4);
    const float* bp0 = Bg + (size_t)brow_s * Ndim + n0 + bcol;
    float4 rb0 = *(const float4*)(bp0);
    float4 rb1 = *(const float4*)(bp0 + 4);

    const int steps = Kdim / 16;
    for (int kt = 0; kt < steps; kt++) {
        *(uint4*)&As[arow_s][abase]     = make_uint4(f2tf(ra0.x), f2tf(ra0.y), f2tf(ra0.z), f2tf(ra0.w));
        *(uint4*)&As[arow_s][abase + 4] = make_uint4(f2tf(ra1.x), f2tf(ra1.y), f2tf(ra1.z), f2tf(ra1.w));
        *(uint4*)&Bs[brow_s][bcol]      = make_uint4(f2tf(rb0.x), f2tf(rb0.y), f2tf(rb0.z), f2tf(rb0.w));
        *(uint4*)&Bs[brow_s][bcol + 4]  = make_uint4(f2tf(rb1.x), f2tf(rb1.y), f2tf(rb1.z), f2tf(rb1.w));
        __syncthreads();
        if (kt + 1 < steps) {
            const float* ap = aptr + (kt + 1) * 16 + abase;
            ra0 = *(const float4*)ap;
            ra1 = *(const float4*)(ap + 4);
            const float* bp = Bg + (size_t)((kt + 1) * 16 + brow_s) * Ndim + n0 + bcol;
            rb0 = *(const float4*)bp;
            rb1 = *(const float4*)(bp + 4);
        }
        mma_tile(As, Bs, lane, wm, wn, acc);
        __syncthreads();
    }
}

// ---------------- layernorm ----------------
__global__ void ln_kernel(const float* __restrict__ x, const float* __restrict__ g,
                          const float* __restrict__ b) {
    __shared__ float red[256];
    int t = blockIdx.x, tid = threadIdx.x;
    const float* xr = x + (size_t)t * DD;
    float v[4], s = 0.f, s2 = 0.f;
#pragma unroll
    for (int i = 0; i < 4; i++) {
        float vv = xr[tid + i*256];
        v[i] = vv; s += vv; s2 += vv*vv;
    }
    red[tid] = s; __syncthreads();
    for (int o = 128; o > 0; o >>= 1) { if (tid < o) red[tid] += red[tid+o]; __syncthreads(); }
    float mean = red[0] * (1.f/DD);
    __syncthreads();
    red[tid] = s2; __syncthreads();
    for (int o = 128; o > 0; o >>= 1) { if (tid < o) red[tid] += red[tid+o]; __syncthreads(); }
    float var = red[0] * (1.f/DD) - mean*mean;
    float rs = rsqrtf(var + 1e-5f);
    float* out = g_h + (size_t)t * DD;
#pragma unroll
    for (int i = 0; i < 4; i++) {
        int c = tid + i*256;
        out[c] = (v[i]-mean)*rs*g[c] + b[c];
    }
}

// ---------------- fused QKV projection (tensor core) ----------------
__global__ void tc_qkv(const float* __restrict__ A,
                       const float* __restrict__ Bq, const float* __restrict__ Bk,
                       const float* __restrict__ Bv,
                       float* __restrict__ Cq, float* __restrict__ Ck, float* __restrict__ Cv) {
    __shared__ unsigned As[128][20];
    __shared__ unsigned Bs[16][132];
    const float* B = blockIdx.z == 0 ? Bq : blockIdx.z == 1 ? Bk : Bv;
    float* C = blockIdx.z == 0 ? Cq : blockIdx.z == 1 ? Ck : Cv;
    const int m0 = blockIdx.y * 128, n0 = blockIdx.x * 128;
    const int t = threadIdx.x, lane = t & 31, warp = t >> 5;
    const int wm = (warp >> 2) * 64, wn = (warp & 3) * 32;
    float acc[4][4][4] = {};
    const float* aptr = A + (size_t)(m0 + (t >> 1)) * DD;
    gemm_core(aptr, B, DD, DD, n0, acc, As, Bs);
#pragma unroll
    for (int i = 0; i < 4; i++) {
        int r0 = m0 + wm + i*16 + (lane >> 2);
#pragma unroll
        for (int j = 0; j < 4; j++) {
            int c0 = n0 + wn + j*8 + (lane & 3) * 2;
            *(float2*)&C[(size_t)r0 * DD + c0]       = make_float2(acc[i][j][0], acc[i][j][1]);
            *(float2*)&C[(size_t)(r0 + 8) * DD + c0] = make_float2(acc[i][j][2], acc[i][j][3]);
        }
    }
}

// ---------------- O projection + residual (tensor core) ----------------
__global__ void tc_oproj(const float* __restrict__ A, const float* __restrict__ B,
                         const float* __restrict__ R, float* __restrict__ C) {
    __shared__ unsigned As[128][20];
    __shared__ unsigned Bs[16][132];
    const int m0 = blockIdx.y * 128, n0 = blockIdx.x * 128;
    const int t = threadIdx.x, lane = t & 31, warp = t >> 5;
    const int wm = (warp >> 2) * 64, wn = (warp & 3) * 32;
    float acc[4][4][4] = {};
    const float* aptr = A + (size_t)(m0 + (t >> 1)) * DD;
    gemm_core(aptr, B, DD, DD, n0, acc, As, Bs);
#pragma unroll
    for (int i = 0; i < 4; i++) {
        int r0 = m0 + wm + i*16 + (lane >> 2);
#pragma unroll
        for (int j = 0; j < 4; j++) {
            int c0 = n0 + wn + j*8 + (lane & 3) * 2;
            size_t i0 = (size_t)r0 * DD + c0;
            size_t i1 = (size_t)(r0 + 8) * DD + c0;
            float2 u0 = *(const float2*)&R[i0];
            float2 u1 = *(const float2*)&R[i1];
            *(float2*)&C[i0] = make_float2(acc[i][j][0] + u0.x, acc[i][j][1] + u0.y);
            *(float2*)&C[i1] = make_float2(acc[i][j][2] + u1.x, acc[i][j][3] + u1.y);
        }
    }
}

// ---------------- flash attention (unchanged fp32) ----------------
__global__ void attn_kernel(const float* __restrict__ Q, const float* __restrict__ Kp,
                            const float* __restrict__ Vp, float* __restrict__ O) {
    extern __shared__ float sm[];
    float* Qs  = sm;              // [64][68]
    float* KsT = sm + 64*68;      // [64][68]
    float* Vs  = sm + 2*64*68;    // [64][68]
    float* Ss  = sm + 3*64*68;    // [64][68]
    __shared__ float m_s[64], l_s[64], alpha_s[64];

    int tid = threadIdx.x;
    int bh = blockIdx.y; int b = bh >> 4, h = bh & 15;
    int q0 = blockIdx.x * 64;
    int r = tid >> 2, qq = tid & 3;
    const size_t base = ((size_t)b*SS)*DD + h*DH;

    {
        int lr = tid >> 2, seg = tid & 3;
        const float* src = Q + base + (size_t)(q0+lr)*DD + seg*16;
#pragma unroll
        for (int i = 0; i < 4; i++) {
            float4 v = *(const float4*)(src + i*4);
            *(float4*)&Qs[lr*68 + seg*16 + i*4] = v;
        }
    }
    if (tid < 64) { m_s[tid] = -1e30f; l_s[tid] = 0.f; }
    float acc[16];
#pragma unroll
    for (int i = 0; i < 16; i++) acc[i] = 0.f;

    for (int kt = 0; kt < SS/64; kt++) {
        __syncthreads();
        {
            int lr = tid >> 2, seg = tid & 3;
            const float* ksrc = Kp + base + (size_t)(kt*64+lr)*DD + seg*16;
            const float* vsrc = Vp + base + (size_t)(kt*64+lr)*DD + seg*16;
#pragma unroll
            for (int i = 0; i < 4; i++) {
                float4 kv = *(const float4*)(ksrc + i*4);
                int c = seg*16 + i*4;
                KsT[(c+0)*68 + lr] = kv.x;
                KsT[(c+1)*68 + lr] = kv.y;
                KsT[(c+2)*68 + lr] = kv.z;
                KsT[(c+3)*68 + lr] = kv.w;
                float4 vv = *(const float4*)(vsrc + i*4);
                *(float4*)&Vs[lr*68 + c] = vv;
            }
        }
        __syncthreads();
        {
            float accs[16];
#pragma unroll
            for (int i = 0; i < 16; i++) accs[i] = 0.f;
#pragma unroll 8
            for (int d = 0; d < 64; d++) {
                float qv = Qs[r*68 + d];
#pragma unroll
                for (int m = 0; m < 4; m++) {
                    float4 kv = *(const float4*)&KsT[d*68 + m*16 + qq*4];
                    accs[m*4+0] += qv*kv.x; accs[m*4+1] += qv*kv.y;
                    accs[m*4+2] += qv*kv.z; accs[m*4+3] += qv*kv.w;
                }
            }
#pragma unroll
            for (int m = 0; m < 4; m++) {
                float4 o4 = make_float4(accs[m*4+0]*0.125f, accs[m*4+1]*0.125f,
                                        accs[m*4+2]*0.125f, accs[m*4+3]*0.125f);
                *(float4*)&Ss[r*68 + m*16 + qq*4] = o4;
            }
        }
        __syncthreads();
        if (tid < 64) {
            int rr = tid;
            float mo = m_s[rr], mx = mo;
            for (int j = 0; j < 64; j++) mx = fmaxf(mx, Ss[rr*68+j]);
            float a = __expf(mo - mx);
            float s = 0.f;
            for (int j = 0; j < 64; j++) {
                float e = __expf(Ss[rr*68+j] - mx);
                Ss[rr*68+j] = e; s += e;
            }
            m_s[rr] = mx; l_s[rr] = l_s[rr]*a + s; alpha_s[rr] = a;
        }
        __syncthreads();
        {
            float a = alpha_s[r];
#pragma unroll
            for (int i = 0; i < 16; i++) acc[i] *= a;
#pragma unroll 8
            for (int kk = 0; kk < 64; kk++) {
                float p = Ss[r*68 + kk];
#pragma unroll
                for (int m = 0; m < 4; m++) {
                    float4 vv = *(const float4*)&Vs[kk*68 + m*16 + qq*4];
                    acc[m*4+0] += p*vv.x; acc[m*4+1] += p*vv.y;
                    acc[m*4+2] += p*vv.z; acc[m*4+3] += p*vv.w;
                }
            }
        }
    }
    __syncthreads();
    float inv = 1.f / l_s[r];
    float* dst = O + base + (size_t)(q0+r)*DD;
#pragma unroll
    for (int m = 0; m < 4; m++) {
        int c = m*16 + qq*4;
        float4 o4 = make_float4(acc[m*4+0]*inv, acc[m*4+1]*inv,
                                acc[m*4+2]*inv, acc[m*4+3]*inv);
        *(float4*)&dst[c] = o4;
    }
}

// ---------------- gate ----------------
__global__ void zero_cnt_kernel() { if (threadIdx.x < EE) g_cnt[threadIdx.x] = 0; }

__global__ void gate_kernel(const float* __restrict__ xin, const float* __restrict__ Wg) {
    __shared__ float lg[EE];
    int t = blockIdx.x, tid = threadIdx.x;
    int w = tid >> 5, lane = tid & 31;
    const float* xr = xin + (size_t)t * DD;
    float s = 0.f;
    for (int d = lane; d < DD; d += 32) s += xr[d] * Wg[d*EE + w];
#pragma unroll
    for (int o = 16; o > 0; o >>= 1) s += __shfl_down_sync(0xffffffffu, s, o);
    if (lane == 0) lg[w] = s;
    __syncthreads();
    if (tid == 0) {
        float v0 = -1e30f; int i0 = 0;
        for (int e = 0; e < EE; e++) if (lg[e] > v0) { v0 = lg[e]; i0 = e; }
        float v1 = -1e30f; int i1 = 0;
        for (int e = 0; e < EE; e++) if (e != i0 && lg[e] > v1) { v1 = lg[e]; i1 = e; }
        float e1 = __expf(v1 - v0);
        float w0 = 1.f / (1.f + e1);
        float w1 = e1 / (1.f + e1);
        int p0 = atomicAdd(&g_cnt[i0], 1);
        g_tok[i0*NT + p0] = t; g_slotid[i0*NT + p0] = 2*t;     g_wt[i0*NT + p0] = w0;
        int p1 = atomicAdd(&g_cnt[i1], 1);
        g_tok[i1*NT + p1] = t; g_slotid[i1*NT + p1] = 2*t + 1; g_wt[i1*NT + p1] = w1;
    }
}

// ---------------- MoE FFN1 (tensor core): h1 = gelu(gather(x) @ W1[e] + b1[e]) ----------------
__global__ void tc_ffn1(const float* __restrict__ xin, const float* __restrict__ W1,
                        const float* __restrict__ b1) {
    const int e = blockIdx.z;
    const int cnt = g_cnt[e];
    const int m0 = blockIdx.y * 128;
    if (m0 >= cnt) return;
    __shared__ unsigned As[128][20];
    __shared__ unsigned Bs[16][132];
    const int n0 = blockIdx.x * 128;
    const int t = threadIdx.x, lane = t & 31, warp = t >> 5;
    const int wm = (warp >> 2) * 64, wn = (warp & 3) * 32;
    float acc[4][4][4] = {};
    int r = m0 + (t >> 1); if (r > cnt - 1) r = cnt - 1;
    const float* aptr = xin + (size_t)g_tok[e*NT + r] * DD;
    gemm_core(aptr, W1 + (size_t)e * DD * FF, DD, FF, n0, acc, As, Bs);
#pragma unroll
    for (int i = 0; i < 4; i++) {
        int r0 = m0 + wm + i*16 + (lane >> 2);
#pragma unroll
        for (int j = 0; j < 4; j++) {
            int c0 = n0 + wn + j*8 + (lane & 3) * 2;
            float bb0 = b1[e*FF + c0], bb1 = b1[e*FF + c0 + 1];
#pragma unroll
            for (int half = 0; half < 2; half++) {
                int rr = r0 + half * 8;
                if (rr >= cnt) continue;
                float u0 = acc[i][j][half*2+0] + bb0;
                float u1 = acc[i][j][half*2+1] + bb1;
                float g0 = 0.5f*u0*(1.f + tanhf(0.7978845608028654f*(u0 + 0.044715f*u0*u0*u0)));
                float g1 = 0.5f*u1*(1.f + tanhf(0.7978845608028654f*(u1 + 0.044715f*u1*u1*u1)));
                *(float2*)&g_h1[((size_t)e*NT + rr)*FF + c0] = make_float2(g0, g1);
            }
        }
    }
}

// ---------------- MoE FFN2 (tensor core): contrib = w*(h1 @ W2[e] + b2[e]) ----------------
__global__ void tc_ffn2(const float* __restrict__ W2, const float* __restrict__ b2) {
    const int e = blockIdx.z;
    const int cnt = g_cnt[e];
    const int m0 = blockIdx.y * 128;
    if (m0 >= cnt) return;
    __shared__ unsigned As[128][20];
    __shared__ unsigned Bs[16][132];
    const int n0 = blockIdx.x * 128;
    const int t = threadIdx.x, lane = t & 31, warp = t >> 5;
    const int wm = (warp >> 2) * 64, wn = (warp & 3) * 32;
    float acc[4][4][4] = {};
    int r = m0 + (t >> 1); if (r > cnt - 1) r = cnt - 1;
    const float* aptr = g_h1 + ((size_t)e*NT + r) * FF;
    gemm_core(aptr, W2 + (size_t)e * FF * DD, FF, DD, n0, acc, As, Bs);
#pragma unroll
    for (int i = 0; i < 4; i++) {
        int r0 = m0 + wm + i*16 + (lane >> 2);
#pragma unroll
        for (int j = 0; j < 4; j++) {
            int c0 = n0 + wn + j*8 + (lane & 3) * 2;
            float bb0 = b2[e*DD + c0], bb1 = b2[e*DD + c0 + 1];
#pragma unroll
            for (int half = 0; half < 2; half++) {
                int rr = r0 + half * 8;
                if (rr >= cnt) continue;
                int slot = g_slotid[e*NT + rr];
                float w  = g_wt[e*NT + rr];
                float v0 = w * (acc[i][j][half*2+0] + bb0);
                float v1 = w * (acc[i][j][half*2+1] + bb1);
                *(float2*)&g_contrib[(size_t)slot * DD + c0] = make_float2(v0, v1);
            }
        }
    }
}

// ---------------- final combine ----------------
__global__ void combine_kernel(float* __restrict__ out) {
    int t = blockIdx.x;
    int c = threadIdx.x * 4;
    size_t idx = (size_t)t * DD + c;
    float4 a  = *(const float4*)&g_x1[idx];
    float4 c0 = *(const float4*)&g_contrib[(size_t)(2*t)*DD + c];
    float4 c1 = *(const float4*)&g_contrib[(size_t)(2*t+1)*DD + c];
    float4 o = make_float4(a.x+c0.x+c1.x, a.y+c0.y+c1.y, a.z+c0.z+c1.z, a.w+c0.w+c1.w);
    *(float4*)&out[idx] = o;
}

// ---------------- launch ----------------
extern "C" void kernel_launch(void* const* d_in, const int* in_sizes, int n_in,
                              void* d_out, int out_size) {
    const float* x    = (const float*)d_in[0];
    const float* ln_g = (const float*)d_in[1];
    const float* ln_b = (const float*)d_in[2];
    const float* Wq   = (const float*)d_in[3];
    const float* Wk   = (const float*)d_in[4];
    const float* Wv   = (const float*)d_in[5];
    const float* Wo   = (const float*)d_in[6];
    const float* Wg   = (const float*)d_in[7];
    const float* W1   = (const float*)d_in[8];
    const float* b1   = (const float*)d_in[9];
    const float* W2   = (const float*)d_in[10];
    const float* b2   = (const float*)d_in[11];
    float* out = (float*)d_out;

    float *p_h, *p_q, *p_k, *p_v, *p_attn, *p_x1;
    cudaGetSymbolAddress((void**)&p_h,    g_h);
    cudaGetSymbolAddress((void**)&p_q,    g_q);
    cudaGetSymbolAddress((void**)&p_k,    g_k);
    cudaGetSymbolAddress((void**)&p_v,    g_v);
    cudaGetSymbolAddress((void**)&p_attn, g_attn);
    cudaGetSymbolAddress((void**)&p_x1,   g_x1);

    const int ATT_SMEM = 4*64*68*4;
    cudaFuncSetAttribute(attn_kernel, cudaFuncAttributeMaxDynamicSharedMemorySize, ATT_SMEM);

    // 1) layernorm
    ln_kernel<<<NT, 256>>>(x, ln_g, ln_b);
    // 2) fused QKV projections (tensor core)
    tc_qkv<<<dim3(DD/128, NT/128, 3), 256>>>(p_h, Wq, Wk, Wv, p_q, p_k, p_v);
    // 3) attention
    attn_kernel<<<dim3(SS/64, BB*HH), 256, ATT_SMEM>>>(p_q, p_k, p_v, p_attn);
    // 4) O projection + residual
    tc_oproj<<<dim3(DD/128, NT/128), 256>>>(p_attn, Wo, x, p_x1);
    // 5) gate + binning
    zero_cnt_kernel<<<1, 32>>>();
    gate_kernel<<<NT, 256>>>(p_x1, Wg);
    // 6) grouped expert FFN (tensor core)
    tc_ffn1<<<dim3(FF/128, NT/128, EE), 256>>>(p_x1, W1, b1);
    tc_ffn2<<<dim3(DD/128, NT/128, EE), 256>>>(W2, b2);
    // 7) combine + residual 2
    combine_kernel<<<NT, 256>>>(out);
}

// round 4
// speedup vs baseline: 2.6334x; 1.6162x over previous
#include <cuda_runtime.h>
#include <math.h>

// Problem dims
#define BB 2
#define SS 2048
#define DD 1024
#define HH 16
#define DH 64
#define FF 4096
#define EE 8
#define NT (BB*SS)   // 4096 tokens

// ---------------- scratch ----------------
__device__ float g_h[NT*DD];
__device__ float g_q[NT*DD];
__device__ float g_k[NT*DD];
__device__ float g_v[NT*DD];
__device__ float g_attn[NT*DD];
__device__ float g_x1[NT*DD];
__device__ int   g_cnt[EE];
__device__ int   g_tok[EE*NT];
__device__ int   g_slotid[EE*NT];
__device__ float g_wt[EE*NT];
__device__ float g_h1[(size_t)EE*NT*FF];
__device__ float g_contrib[(size_t)2*NT*DD];

// ---------------- helpers ----------------
__device__ __forceinline__ unsigned f2tf(float f) {
    unsigned u; asm("cvt.rna.tf32.f32 %0, %1;" : "=r"(u) : "f"(f)); return u;
}

__device__ __forceinline__ void mma8(float (&c)[4], const unsigned (&a)[4],
                                     unsigned b0, unsigned b1) {
    asm volatile("mma.sync.aligned.m16n8k8.row.col.f32.tf32.tf32.f32 "
        "{%0,%1,%2,%3}, {%4,%5,%6,%7}, {%8,%9}, {%0,%1,%2,%3};"
        : "+f"(c[0]), "+f"(c[1]), "+f"(c[2]), "+f"(c[3])
        : "r"(a[0]), "r"(a[1]), "r"(a[2]), "r"(a[3]), "r"(b0), "r"(b1));
}

// mma compute over one BK=16 slab. As[128][20] (m-major), Bs[16][132] (k-major).
__device__ __forceinline__ void mma_tile(const unsigned (*As)[20], const unsigned (*Bs)[132],
                                         int lane, int wm, int wn, float (&acc)[4][4][4]) {
    const int g = lane >> 2, q = lane & 3;
#pragma unroll
    for (int ks = 0; ks < 2; ks++) {
        const int kb = ks * 8;
        unsigned a[4][4], b[4][2];
#pragma unroll
        for (int i = 0; i < 4; i++) {
            int m = wm + i*16 + g;
            a[i][0] = As[m][kb + q];
            a[i][1] = As[m+8][kb + q];
            a[i][2] = As[m][kb + 4 + q];
            a[i][3] = As[m+8][kb + 4 + q];
        }
#pragma unroll
        for (int j = 0; j < 4; j++) {
            int n = wn + j*8 + g;
            b[j][0] = Bs[kb + q][n];
            b[j][1] = Bs[kb + 4 + q][n];
        }
#pragma unroll
        for (int i = 0; i < 4; i++)
#pragma unroll
            for (int j = 0; j < 4; j++)
                mma8(acc[i][j], a[i], b[j][0], b[j][1]);
    }
}

// Double-buffered mainloop: C_tile(128x128) += A(128,K) @ B(K,Ndim) at col n0.
__device__ __forceinline__ void gemm_core(const float* __restrict__ aptr,
                                          const float* __restrict__ Bg,
                                          int Kdim, int Ndim, int n0,
                                          float (&acc)[4][4][4],
                                          unsigned (*As)[128][20], unsigned (*Bs)[16][132]) {
    const int t = threadIdx.x;
    const int lane = t & 31, warp = t >> 5;
    const int wm = (warp >> 2) * 64, wn = (warp & 3) * 32;
    const int abase = 8 * (t & 1);
    const int arow_s = t >> 1;
    const int brow_s = t >> 4;
    const int bcol = 8 * (t & 15);

    float4 ra0 = *(const float4*)(aptr + abase);
    float4 ra1 = *(const float4*)(aptr + abase + 4);
    const float* bp0 = Bg + (size_t)brow_s * Ndim + n0 + bcol;
    float4 rb0 = *(const float4*)(bp0);
    float4 rb1 = *(const float4*)(bp0 + 4);

    *(uint4*)&As[0][arow_s][abase]     = make_uint4(f2tf(ra0.x), f2tf(ra0.y), f2tf(ra0.z), f2tf(ra0.w));
    *(uint4*)&As[0][arow_s][abase + 4] = make_uint4(f2tf(ra1.x), f2tf(ra1.y), f2tf(ra1.z), f2tf(ra1.w));
    *(uint4*)&Bs[0][brow_s][bcol]      = make_uint4(f2tf(rb0.x), f2tf(rb0.y), f2tf(rb0.z), f2tf(rb0.w));
    *(uint4*)&Bs[0][brow_s][bcol + 4]  = make_uint4(f2tf(rb1.x), f2tf(rb1.y), f2tf(rb1.z), f2tf(rb1.w));
    __syncthreads();

    const int steps = Kdim / 16;
    for (int kt = 0; kt < steps; kt++) {
        const int cur = kt & 1;
        const bool more = (kt + 1 < steps);
        if (more) {
            const float* ap = aptr + (kt + 1) * 16 + abase;
            ra0 = *(const float4*)ap;
            ra1 = *(const float4*)(ap + 4);
            const float* bp = Bg + (size_t)((kt + 1) * 16 + brow_s) * Ndim + n0 + bcol;
            rb0 = *(const float4*)bp;
            rb1 = *(const float4*)(bp + 4);
        }
        mma_tile(As[cur], Bs[cur], lane, wm, wn, acc);
        if (more) {
            const int nxt = cur ^ 1;
            *(uint4*)&As[nxt][arow_s][abase]     = make_uint4(f2tf(ra0.x), f2tf(ra0.y), f2tf(ra0.z), f2tf(ra0.w));
            *(uint4*)&As[nxt][arow_s][abase + 4] = make_uint4(f2tf(ra1.x), f2tf(ra1.y), f2tf(ra1.z), f2tf(ra1.w));
            *(uint4*)&Bs[nxt][brow_s][bcol]      = make_uint4(f2tf(rb0.x), f2tf(rb0.y), f2tf(rb0.z), f2tf(rb0.w));
            *(uint4*)&Bs[nxt][brow_s][bcol + 4]  = make_uint4(f2tf(rb1.x), f2tf(rb1.y), f2tf(rb1.z), f2tf(rb1.w));
            __syncthreads();
        }
    }
}

// ---------------- layernorm ----------------
__global__ void ln_kernel(const float* __restrict__ x, const float* __restrict__ g,
                          const float* __restrict__ b) {
    __shared__ float red[256];
    int t = blockIdx.x, tid = threadIdx.x;
    const float* xr = x + (size_t)t * DD;
    float v[4], s = 0.f, s2 = 0.f;
#pragma unroll
    for (int i = 0; i < 4; i++) {
        float vv = xr[tid + i*256];
        v[i] = vv; s += vv; s2 += vv*vv;
    }
    red[tid] = s; __syncthreads();
    for (int o = 128; o > 0; o >>= 1) { if (tid < o) red[tid] += red[tid+o]; __syncthreads(); }
    float mean = red[0] * (1.f/DD);
    __syncthreads();
    red[tid] = s2; __syncthreads();
    for (int o = 128; o > 0; o >>= 1) { if (tid < o) red[tid] += red[tid+o]; __syncthreads(); }
    float var = red[0] * (1.f/DD) - mean*mean;
    float rs = rsqrtf(var + 1e-5f);
    float* out = g_h + (size_t)t * DD;
#pragma unroll
    for (int i = 0; i < 4; i++) {
        int c = tid + i*256;
        out[c] = (v[i]-mean)*rs*g[c] + b[c];
    }
}

// ---------------- fused QKV projection ----------------
__global__ void tc_qkv(const float* __restrict__ A,
                       const float* __restrict__ Bq, const float* __restrict__ Bk,
                       const float* __restrict__ Bv,
                       float* __restrict__ Cq, float* __restrict__ Ck, float* __restrict__ Cv) {
    __shared__ unsigned As[2][128][20];
    __shared__ unsigned Bs[2][16][132];
    const float* B = blockIdx.z == 0 ? Bq : blockIdx.z == 1 ? Bk : Bv;
    float* C = blockIdx.z == 0 ? Cq : blockIdx.z == 1 ? Ck : Cv;
    const int m0 = blockIdx.y * 128, n0 = blockIdx.x * 128;
    const int t = threadIdx.x, lane = t & 31, warp = t >> 5;
    const int wm = (warp >> 2) * 64, wn = (warp & 3) * 32;
    float acc[4][4][4] = {};
    const float* aptr = A + (size_t)(m0 + (t >> 1)) * DD;
    gemm_core(aptr, B, DD, DD, n0, acc, As, Bs);
#pragma unroll
    for (int i = 0; i < 4; i++) {
        int r0 = m0 + wm + i*16 + (lane >> 2);
#pragma unroll
        for (int j = 0; j < 4; j++) {
            int c0 = n0 + wn + j*8 + (lane & 3) * 2;
            *(float2*)&C[(size_t)r0 * DD + c0]       = make_float2(acc[i][j][0], acc[i][j][1]);
            *(float2*)&C[(size_t)(r0 + 8) * DD + c0] = make_float2(acc[i][j][2], acc[i][j][3]);
        }
    }
}

// ---------------- O projection + residual ----------------
__global__ void tc_oproj(const float* __restrict__ A, const float* __restrict__ B,
                         const float* __restrict__ R, float* __restrict__ C) {
    __shared__ unsigned As[2][128][20];
    __shared__ unsigned Bs[2][16][132];
    const int m0 = blockIdx.y * 128, n0 = blockIdx.x * 128;
    const int t = threadIdx.x, lane = t & 31, warp = t >> 5;
    const int wm = (warp >> 2) * 64, wn = (warp & 3) * 32;
    float acc[4][4][4] = {};
    const float* aptr = A + (size_t)(m0 + (t >> 1)) * DD;
    gemm_core(aptr, B, DD, DD, n0, acc, As, Bs);
#pragma unroll
    for (int i = 0; i < 4; i++) {
        int r0 = m0 + wm + i*16 + (lane >> 2);
#pragma unroll
        for (int j = 0; j < 4; j++) {
            int c0 = n0 + wn + j*8 + (lane & 3) * 2;
            size_t i0 = (size_t)r0 * DD + c0;
            size_t i1 = (size_t)(r0 + 8) * DD + c0;
            float2 u0 = *(const float2*)&R[i0];
            float2 u1 = *(const float2*)&R[i1];
            *(float2*)&C[i0] = make_float2(acc[i][j][0] + u0.x, acc[i][j][1] + u0.y);
            *(float2*)&C[i1] = make_float2(acc[i][j][2] + u1.x, acc[i][j][3] + u1.y);
        }
    }
}

// ---------------- tensor-core flash attention ----------------
// 128 threads (4 warps). Q tile 64 rows; warp w owns rows [w*16, w*16+16).
// Scores + PV via m16n8k8 tf32; online softmax in registers (quad shuffles).
// Ps is [64][68]: full 64 P-columns per row (R3 bug: was [64][20] -> OOB).
__global__ void attn_tc(const float* __restrict__ Q, const float* __restrict__ Kp,
                        const float* __restrict__ Vp, float* __restrict__ O) {
    extern __shared__ unsigned smu[];
    unsigned (*Qs)[68]  = (unsigned(*)[68])smu;              // [64][68]
    unsigned (*KsT)[68] = (unsigned(*)[68])(smu + 64*68);    // [64][68] KsT[d][kk]
    unsigned (*Vs)[68]  = (unsigned(*)[68])(smu + 2*64*68);  // [64][68] Vs[kk][d]
    unsigned (*Ps)[68]  = (unsigned(*)[68])(smu + 3*64*68);  // [64][68] P tile

    const int tid = threadIdx.x;
    const int lane = tid & 31, w = tid >> 5;
    const int g = lane >> 2, q = lane & 3;
    const int bh = blockIdx.y, b = bh >> 4, h = bh & 15;
    const int q0 = blockIdx.x * 64;
    const size_t base = ((size_t)b*SS)*DD + h*DH;

    { // load Q tile as tf32
        int r = tid >> 1, c0 = (tid & 1) * 32;
        const float* src = Q + base + (size_t)(q0 + r)*DD + c0;
#pragma unroll
        for (int i = 0; i < 8; i++) {
            float4 v = *(const float4*)(src + i*4);
            Qs[r][c0+i*4+0] = f2tf(v.x); Qs[r][c0+i*4+1] = f2tf(v.y);
            Qs[r][c0+i*4+2] = f2tf(v.z); Qs[r][c0+i*4+3] = f2tf(v.w);
        }
    }
    __syncthreads();
    unsigned aq[8][4];
    {
        const int m0 = w * 16;
#pragma unroll
        for (int ks = 0; ks < 8; ks++) {
            int k = ks * 8;
            aq[ks][0] = Qs[m0+g][k+q];
            aq[ks][1] = Qs[m0+8+g][k+q];
            aq[ks][2] = Qs[m0+g][k+4+q];
            aq[ks][3] = Qs[m0+8+g][k+4+q];
        }
    }
    __syncthreads();

    float m0r = -1e30f, m1r = -1e30f, l0 = 0.f, l1 = 0.f;
    float acc_o[8][4];
#pragma unroll
    for (int j = 0; j < 8; j++) { acc_o[j][0]=0.f; acc_o[j][1]=0.f; acc_o[j][2]=0.f; acc_o[j][3]=0.f; }
    const int pr = w * 16;

    for (int kt = 0; kt < SS/64; kt++) {
        { // load K (transposed) + V tiles as tf32
            int r = tid >> 1, c0 = (tid & 1) * 32;
            const float* ksrc = Kp + base + (size_t)(kt*64 + r)*DD + c0;
            const float* vsrc = Vp + base + (size_t)(kt*64 + r)*DD + c0;
#pragma unroll
            for (int i = 0; i < 8; i++) {
                float4 kv = *(const float4*)(ksrc + i*4);
                int c = c0 + i*4;
                KsT[c+0][r] = f2tf(kv.x); KsT[c+1][r] = f2tf(kv.y);
                KsT[c+2][r] = f2tf(kv.z); KsT[c+3][r] = f2tf(kv.w);
                float4 vv = *(const float4*)(vsrc + i*4);
                Vs[r][c+0] = f2tf(vv.x); Vs[r][c+1] = f2tf(vv.y);
                Vs[r][c+2] = f2tf(vv.z); Vs[r][c+3] = f2tf(vv.w);
            }
        }
        __syncthreads();

        // scores: s[j] covers cols j*8.. of this 64-key tile, rows (g, g+8)
        float s[8][4];
#pragma unroll
        for (int j = 0; j < 8; j++) { s[j][0]=0.f; s[j][1]=0.f; s[j][2]=0.f; s[j][3]=0.f; }
#pragma unroll
        for (int ks = 0; ks < 8; ks++) {
            int kb = ks * 8;
#pragma unroll
            for (int j = 0; j < 8; j++) {
                unsigned b0 = KsT[kb+q][j*8+g];
                unsigned b1 = KsT[kb+4+q][j*8+g];
                mma8(s[j], aq[ks], b0, b1);
            }
        }
        // online softmax (scale 0.125)
        float mx0 = m0r, mx1 = m1r;
#pragma unroll
        for (int j = 0; j < 8; j++) {
            s[j][0] *= 0.125f; s[j][1] *= 0.125f; s[j][2] *= 0.125f; s[j][3] *= 0.125f;
            mx0 = fmaxf(mx0, fmaxf(s[j][0], s[j][1]));
            mx1 = fmaxf(mx1, fmaxf(s[j][2], s[j][3]));
        }
        mx0 = fmaxf(mx0, __shfl_xor_sync(0xffffffffu, mx0, 1));
        mx0 = fmaxf(mx0, __shfl_xor_sync(0xffffffffu, mx0, 2));
        mx1 = fmaxf(mx1, __shfl_xor_sync(0xffffffffu, mx1, 1));
        mx1 = fmaxf(mx1, __shfl_xor_sync(0xffffffffu, mx1, 2));
        float alpha0 = __expf(m0r - mx0), alpha1 = __expf(m1r - mx1);
        m0r = mx0; m1r = mx1;
        float ps0 = 0.f, ps1 = 0.f;
#pragma unroll
        for (int j = 0; j < 8; j++) {
            s[j][0] = __expf(s[j][0] - mx0); ps0 += s[j][0];
            s[j][1] = __expf(s[j][1] - mx0); ps0 += s[j][1];
            s[j][2] = __expf(s[j][2] - mx1); ps1 += s[j][2];
            s[j][3] = __expf(s[j][3] - mx1); ps1 += s[j][3];
        }
        ps0 += __shfl_xor_sync(0xffffffffu, ps0, 1);
        ps0 += __shfl_xor_sync(0xffffffffu, ps0, 2);
        ps1 += __shfl_xor_sync(0xffffffffu, ps1, 1);
        ps1 += __shfl_xor_sync(0xffffffffu, ps1, 2);
        l0 = l0 * alpha0 + ps0;
        l1 = l1 * alpha1 + ps1;
#pragma unroll
        for (int j = 0; j < 8; j++) {
            acc_o[j][0] *= alpha0; acc_o[j][1] *= alpha0;
            acc_o[j][2] *= alpha1; acc_o[j][3] *= alpha1;
        }
        // stash P (tf32) into warp-local smem rows [pr, pr+16)
#pragma unroll
        for (int j = 0; j < 8; j++) {
            *(uint2*)&Ps[pr+g][j*8 + 2*q]   = make_uint2(f2tf(s[j][0]), f2tf(s[j][1]));
            *(uint2*)&Ps[pr+8+g][j*8 + 2*q] = make_uint2(f2tf(s[j][2]), f2tf(s[j][3]));
        }
        __syncwarp();
        // PV
#pragma unroll
        for (int ks = 0; ks < 8; ks++) {
            int kb = ks * 8;
            unsigned ap[4];
            ap[0] = Ps[pr+g][kb+q];
            ap[1] = Ps[pr+8+g][kb+q];
            ap[2] = Ps[pr+g][kb+4+q];
            ap[3] = Ps[pr+8+g][kb+4+q];
#pragma unroll
            for (int j = 0; j < 8; j++) {
                unsigned b0 = Vs[kb+q][j*8+g];
                unsigned b1 = Vs[kb+4+q][j*8+g];
                mma8(acc_o[j], ap, b0, b1);
            }
        }
        __syncthreads();
    }
    // epilogue
    float inv0 = 1.f / l0, inv1 = 1.f / l1;
    int row0 = q0 + pr + g;
#pragma unroll
    for (int j = 0; j < 8; j++) {
        int col = j*8 + 2*q;
        *(float2*)&O[base + (size_t)row0 * DD + col] =
            make_float2(acc_o[j][0]*inv0, acc_o[j][1]*inv0);
        *(float2*)&O[base + (size_t)(row0+8) * DD + col] =
            make_float2(acc_o[j][2]*inv1, acc_o[j][3]*inv1);
    }
}

// ---------------- gate ----------------
__global__ void zero_cnt_kernel() { if (threadIdx.x < EE) g_cnt[threadIdx.x] = 0; }

__global__ void gate_kernel(const float* __restrict__ xin, const float* __restrict__ Wg) {
    __shared__ float lg[EE];
    int t = blockIdx.x, tid = threadIdx.x;
    int w = tid >> 5, lane = tid & 31;
    const float* xr = xin + (size_t)t * DD;
    float s = 0.f;
    for (int d = lane; d < DD; d += 32) s += xr[d] * Wg[d*EE + w];
#pragma unroll
    for (int o = 16; o > 0; o >>= 1) s += __shfl_down_sync(0xffffffffu, s, o);
    if (lane == 0) lg[w] = s;
    __syncthreads();
    if (tid == 0) {
        float v0 = -1e30f; int i0 = 0;
        for (int e = 0; e < EE; e++) if (lg[e] > v0) { v0 = lg[e]; i0 = e; }
        float v1 = -1e30f; int i1 = 0;
        for (int e = 0; e < EE; e++) if (e != i0 && lg[e] > v1) { v1 = lg[e]; i1 = e; }
        float e1 = __expf(v1 - v0);
        float w0 = 1.f / (1.f + e1);
        float w1 = e1 / (1.f + e1);
        int p0 = atomicAdd(&g_cnt[i0], 1);
        g_tok[i0*NT + p0] = t; g_slotid[i0*NT + p0] = 2*t;     g_wt[i0*NT + p0] = w0;
        int p1 = atomicAdd(&g_cnt[i1], 1);
        g_tok[i1*NT + p1] = t; g_slotid[i1*NT + p1] = 2*t + 1; g_wt[i1*NT + p1] = w1;
    }
}

// ---------------- MoE FFN1 ----------------
__global__ void tc_ffn1(const float* __restrict__ xin, const float* __restrict__ W1,
                        const float* __restrict__ b1) {
    const int e = blockIdx.z;
    const int cnt = g_cnt[e];
    const int m0 = blockIdx.y * 128;
    if (m0 >= cnt) return;
    __shared__ unsigned As[2][128][20];
    __shared__ unsigned Bs[2][16][132];
    const int n0 = blockIdx.x * 128;
    const int t = threadIdx.x, lane = t & 31, warp = t >> 5;
    const int wm = (warp >> 2) * 64, wn = (warp & 3) * 32;
    float acc[4][4][4] = {};
    int r = m0 + (t >> 1); if (r > cnt - 1) r = cnt - 1;
    const float* aptr = xin + (size_t)g_tok[e*NT + r] * DD;
    gemm_core(aptr, W1 + (size_t)e * DD * FF, DD, FF, n0, acc, As, Bs);
#pragma unroll
    for (int i = 0; i < 4; i++) {
        int r0 = m0 + wm + i*16 + (lane >> 2);
#pragma unroll
        for (int j = 0; j < 4; j++) {
            int c0 = n0 + wn + j*8 + (lane & 3) * 2;
            float bb0 = b1[e*FF + c0], bb1 = b1[e*FF + c0 + 1];
#pragma unroll
            for (int half = 0; half < 2; half++) {
                int rr = r0 + half * 8;
                if (rr >= cnt) continue;
                float u0 = acc[i][j][half*2+0] + bb0;
                float u1 = acc[i][j][half*2+1] + bb1;
                float g0 = 0.5f*u0*(1.f + tanhf(0.7978845608028654f*(u0 + 0.044715f*u0*u0*u0)));
                float g1 = 0.5f*u1*(1.f + tanhf(0.7978845608028654f*(u1 + 0.044715f*u1*u1*u1)));
                *(float2*)&g_h1[((size_t)e*NT + rr)*FF + c0] = make_float2(g0, g1);
            }
        }
    }
}

// ---------------- MoE FFN2 ----------------
__global__ void tc_ffn2(const float* __restrict__ W2, const float* __restrict__ b2) {
    const int e = blockIdx.z;
    const int cnt = g_cnt[e];
    const int m0 = blockIdx.y * 128;
    if (m0 >= cnt) return;
    __shared__ unsigned As[2][128][20];
    __shared__ unsigned Bs[2][16][132];
    const int n0 = blockIdx.x * 128;
    const int t = threadIdx.x, lane = t & 31, warp = t >> 5;
    const int wm = (warp >> 2) * 64, wn = (warp & 3) * 32;
    float acc[4][4][4] = {};
    int r = m0 + (t >> 1); if (r > cnt - 1) r = cnt - 1;
    const float* aptr = g_h1 + ((size_t)e*NT + r) * FF;
    gemm_core(aptr, W2 + (size_t)e * FF * DD, FF, DD, n0, acc, As, Bs);
#pragma unroll
    for (int i = 0; i < 4; i++) {
        int r0 = m0 + wm + i*16 + (lane >> 2);
#pragma unroll
        for (int j = 0; j < 4; j++) {
            int c0 = n0 + wn + j*8 + (lane & 3) * 2;
            float bb0 = b2[e*DD + c0], bb1 = b2[e*DD + c0 + 1];
#pragma unroll
            for (int half = 0; half < 2; half++) {
                int rr = r0 + half * 8;
                if (rr >= cnt) continue;
                int slot = g_slotid[e*NT + rr];
                float w  = g_wt[e*NT + rr];
                float v0 = w * (acc[i][j][half*2+0] + bb0);
                float v1 = w * (acc[i][j][half*2+1] + bb1);
                *(float2*)&g_contrib[(size_t)slot * DD + c0] = make_float2(v0, v1);
            }
        }
    }
}

// ---------------- final combine ----------------
__global__ void combine_kernel(float* __restrict__ out) {
    int t = blockIdx.x;
    int c = threadIdx.x * 4;
    size_t idx = (size_t)t * DD + c;
    float4 a  = *(const float4*)&g_x1[idx];
    float4 c0 = *(const float4*)&g_contrib[(size_t)(2*t)*DD + c];
    float4 c1 = *(const float4*)&g_contrib[(size_t)(2*t+1)*DD + c];
    float4 o = make_float4(a.x+c0.x+c1.x, a.y+c0.y+c1.y, a.z+c0.z+c1.z, a.w+c0.w+c1.w);
    *(float4*)&out[idx] = o;
}

// ---------------- launch ----------------
extern "C" void kernel_launch(void* const* d_in, const int* in_sizes, int n_in,
                              void* d_out, int out_size) {
    const float* x    = (const float*)d_in[0];
    const float* ln_g = (const float*)d_in[1];
    const float* ln_b = (const float*)d_in[2];
    const float* Wq   = (const float*)d_in[3];
    const float* Wk   = (const float*)d_in[4];
    const float* Wv   = (const float*)d_in[5];
    const float* Wo   = (const float*)d_in[6];
    const float* Wg   = (const float*)d_in[7];
    const float* W1   = (const float*)d_in[8];
    const float* b1   = (const float*)d_in[9];
    const float* W2   = (const float*)d_in[10];
    const float* b2   = (const float*)d_in[11];
    float* out = (float*)d_out;

    float *p_h, *p_q, *p_k, *p_v, *p_attn, *p_x1;
    cudaGetSymbolAddress((void**)&p_h,    g_h);
    cudaGetSymbolAddress((void**)&p_q,    g_q);
    cudaGetSymbolAddress((void**)&p_k,    g_k);
    cudaGetSymbolAddress((void**)&p_v,    g_v);
    cudaGetSymbolAddress((void**)&p_attn, g_attn);
    cudaGetSymbolAddress((void**)&p_x1,   g_x1);

    const int ATT_SMEM = 4*64*68*4;   // 69632 bytes
    cudaFuncSetAttribute(attn_tc, cudaFuncAttributeMaxDynamicSharedMemorySize, ATT_SMEM);

    // 1) layernorm
    ln_kernel<<<NT, 256>>>(x, ln_g, ln_b);
    // 2) fused QKV projections
    tc_qkv<<<dim3(DD/128, NT/128, 3), 256>>>(p_h, Wq, Wk, Wv, p_q, p_k, p_v);
    // 3) tensor-core flash attention
    attn_tc<<<dim3(SS/64, BB*HH), 128, ATT_SMEM>>>(p_q, p_k, p_v, p_attn);
    // 4) O projection + residual
    tc_oproj<<<dim3(DD/128, NT/128), 256>>>(p_attn, Wo, x, p_x1);
    // 5) gate + binning
    zero_cnt_kernel<<<1, 32>>>();
    gate_kernel<<<NT, 256>>>(p_x1, Wg);
    // 6) grouped expert FFN
    tc_ffn1<<<dim3(FF/128, NT/128, EE), 256>>>(p_x1, W1, b1);
    tc_ffn2<<<dim3(DD/128, NT/128, EE), 256>>>(W2, b2);
    // 7) combine + residual 2
    combine_kernel<<<NT, 256>>>(out);
}

// round 5
// speedup vs baseline: 3.4210x; 1.2991x over previous
#include <cuda_runtime.h>
#include <math.h>

// Problem dims
#define BB 2
#define SS 2048
#define DD 1024
#define HH 16
#define DH 64
#define FF 4096
#define EE 8
#define NT (BB*SS)   // 4096 tokens

// ---------------- scratch ----------------
__device__ float g_h[NT*DD];
__device__ float g_q[NT*DD];
__device__ float g_k[NT*DD];
__device__ float g_v[NT*DD];
__device__ float g_attn[NT*DD];
__device__ float g_x1[NT*DD];
__device__ int   g_cnt[EE];
__device__ int   g_tok[EE*NT];
__device__ int   g_slotid[EE*NT];
__device__ float g_wt[EE*NT];
__device__ float g_h1[(size_t)EE*NT*FF];
__device__ float g_contrib[(size_t)2*NT*DD];

// ---------------- cp.async helpers ----------------
__device__ __forceinline__ void cpa16(const void* dst, const void* src) {
    unsigned d = (unsigned)__cvta_generic_to_shared(dst);
    asm volatile("cp.async.cg.shared.global [%0], [%1], 16;" :: "r"(d), "l"(src));
}
#define CPA_COMMIT()  asm volatile("cp.async.commit_group;")
#define CPA_WAIT(N)   asm volatile("cp.async.wait_group %0;" :: "n"(N))

__device__ __forceinline__ void mma8(float (&c)[4], const unsigned (&a)[4],
                                     unsigned b0, unsigned b1) {
    asm volatile("mma.sync.aligned.m16n8k8.row.col.f32.tf32.tf32.f32 "
        "{%0,%1,%2,%3}, {%4,%5,%6,%7}, {%8,%9}, {%0,%1,%2,%3};"
        : "+f"(c[0]), "+f"(c[1]), "+f"(c[2]), "+f"(c[3])
        : "r"(a[0]), "r"(a[1]), "r"(a[2]), "r"(a[3]), "r"(b0), "r"(b1));
}

// mma compute over one BK=16 slab. As[128][20] raw f32, Bs[16][136] raw f32.
__device__ __forceinline__ void mma_tile(const float (*As)[20], const float (*Bs)[136],
                                         int lane, int wm, int wn, float (&acc)[4][4][4]) {
    const int g = lane >> 2, q = lane & 3;
#pragma unroll
    for (int ks = 0; ks < 2; ks++) {
        const int kb = ks * 8;
        unsigned a[4][4], b[4][2];
#pragma unroll
        for (int i = 0; i < 4; i++) {
            int m = wm + i*16 + g;
            a[i][0] = __float_as_uint(As[m][kb + q]);
            a[i][1] = __float_as_uint(As[m+8][kb + q]);
            a[i][2] = __float_as_uint(As[m][kb + 4 + q]);
            a[i][3] = __float_as_uint(As[m+8][kb + 4 + q]);
        }
#pragma unroll
        for (int j = 0; j < 4; j++) {
            int n = wn + j*8 + g;
            b[j][0] = __float_as_uint(Bs[kb + q][n]);
            b[j][1] = __float_as_uint(Bs[kb + 4 + q][n]);
        }
#pragma unroll
        for (int i = 0; i < 4; i++)
#pragma unroll
            for (int j = 0; j < 4; j++)
                mma8(acc[i][j], a[i], b[j][0], b[j][1]);
    }
}

#define GSTAGES 4
#define GEMM_SMEM ((GSTAGES*128*20 + GSTAGES*16*136) * 4)

// 4-stage cp.async pipelined mainloop: C_tile(128x128) += A(128,K)@B(K,Ndim) at col n0.
__device__ __forceinline__ void gemm_core(const float* __restrict__ aptr,
                                          const float* __restrict__ Bg,
                                          int Kdim, int Ndim, int n0,
                                          float (&acc)[4][4][4],
                                          float (*As)[128][20], float (*Bs)[16][136]) {
    const int t = threadIdx.x;
    const int lane = t & 31, warp = t >> 5;
    const int wm = (warp >> 2) * 64, wn = (warp & 3) * 32;
    const int arow = t >> 1, abase = 8 * (t & 1);
    const int brow = t >> 4, bcol = 8 * (t & 15);
    const int steps = Kdim / 16;

#pragma unroll
    for (int s = 0; s < GSTAGES - 1; s++) {
        if (s < steps) {
            const float* ap = aptr + s*16 + abase;
            cpa16(&As[s][arow][abase],     ap);
            cpa16(&As[s][arow][abase + 4], ap + 4);
            const float* bp = Bg + (size_t)(s*16 + brow) * Ndim + n0 + bcol;
            cpa16(&Bs[s][brow][bcol],     bp);
            cpa16(&Bs[s][brow][bcol + 4], bp + 4);
        }
        CPA_COMMIT();
    }
    for (int kt = 0; kt < steps; kt++) {
        CPA_WAIT(2);
        __syncthreads();
        const int nk = kt + GSTAGES - 1;
        if (nk < steps) {
            const int nb = nk & (GSTAGES - 1);
            const float* ap = aptr + nk*16 + abase;
            cpa16(&As[nb][arow][abase],     ap);
            cpa16(&As[nb][arow][abase + 4], ap + 4);
            const float* bp = Bg + (size_t)(nk*16 + brow) * Ndim + n0 + bcol;
            cpa16(&Bs[nb][brow][bcol],     bp);
            cpa16(&Bs[nb][brow][bcol + 4], bp + 4);
        }
        CPA_COMMIT();
        mma_tile(As[kt & (GSTAGES-1)], Bs[kt & (GSTAGES-1)], lane, wm, wn, acc);
    }
}

// ---------------- layernorm ----------------
__global__ void ln_kernel(const float* __restrict__ x, const float* __restrict__ g,
                          const float* __restrict__ b) {
    __shared__ float red[256];
    int t = blockIdx.x, tid = threadIdx.x;
    const float* xr = x + (size_t)t * DD;
    float v[4], s = 0.f, s2 = 0.f;
#pragma unroll
    for (int i = 0; i < 4; i++) {
        float vv = xr[tid + i*256];
        v[i] = vv; s += vv; s2 += vv*vv;
    }
    red[tid] = s; __syncthreads();
    for (int o = 128; o > 0; o >>= 1) { if (tid < o) red[tid] += red[tid+o]; __syncthreads(); }
    float mean = red[0] * (1.f/DD);
    __syncthreads();
    red[tid] = s2; __syncthreads();
    for (int o = 128; o > 0; o >>= 1) { if (tid < o) red[tid] += red[tid+o]; __syncthreads(); }
    float var = red[0] * (1.f/DD) - mean*mean;
    float rs = rsqrtf(var + 1e-5f);
    float* out = g_h + (size_t)t * DD;
#pragma unroll
    for (int i = 0; i < 4; i++) {
        int c = tid + i*256;
        out[c] = (v[i]-mean)*rs*g[c] + b[c];
    }
}

// ---------------- fused QKV projection ----------------
__global__ void tc_qkv(const float* __restrict__ A,
                       const float* __restrict__ Bq, const float* __restrict__ Bk,
                       const float* __restrict__ Bv,
                       float* __restrict__ Cq, float* __restrict__ Ck, float* __restrict__ Cv) {
    extern __shared__ float dynf[];
    float (*As)[128][20] = (float(*)[128][20])dynf;
    float (*Bs)[16][136] = (float(*)[16][136])(dynf + GSTAGES*128*20);
    const float* B = blockIdx.z == 0 ? Bq : blockIdx.z == 1 ? Bk : Bv;
    float* C = blockIdx.z == 0 ? Cq : blockIdx.z == 1 ? Ck : Cv;
    const int m0 = blockIdx.y * 128, n0 = blockIdx.x * 128;
    const int t = threadIdx.x, lane = t & 31, warp = t >> 5;
    const int wm = (warp >> 2) * 64, wn = (warp & 3) * 32;
    float acc[4][4][4] = {};
    const float* aptr = A + (size_t)(m0 + (t >> 1)) * DD;
    gemm_core(aptr, B, DD, DD, n0, acc, As, Bs);
#pragma unroll
    for (int i = 0; i < 4; i++) {
        int r0 = m0 + wm + i*16 + (lane >> 2);
#pragma unroll
        for (int j = 0; j < 4; j++) {
            int c0 = n0 + wn + j*8 + (lane & 3) * 2;
            *(float2*)&C[(size_t)r0 * DD + c0]       = make_float2(acc[i][j][0], acc[i][j][1]);
            *(float2*)&C[(size_t)(r0 + 8) * DD + c0] = make_float2(acc[i][j][2], acc[i][j][3]);
        }
    }
}

// ---------------- O projection + residual ----------------
__global__ void tc_oproj(const float* __restrict__ A, const float* __restrict__ B,
                         const float* __restrict__ R, float* __restrict__ C) {
    extern __shared__ float dynf[];
    float (*As)[128][20] = (float(*)[128][20])dynf;
    float (*Bs)[16][136] = (float(*)[16][136])(dynf + GSTAGES*128*20);
    const int m0 = blockIdx.y * 128, n0 = blockIdx.x * 128;
    const int t = threadIdx.x, lane = t & 31, warp = t >> 5;
    const int wm = (warp >> 2) * 64, wn = (warp & 3) * 32;
    float acc[4][4][4] = {};
    const float* aptr = A + (size_t)(m0 + (t >> 1)) * DD;
    gemm_core(aptr, B, DD, DD, n0, acc, As, Bs);
#pragma unroll
    for (int i = 0; i < 4; i++) {
        int r0 = m0 + wm + i*16 + (lane >> 2);
#pragma unroll
        for (int j = 0; j < 4; j++) {
            int c0 = n0 + wn + j*8 + (lane & 3) * 2;
            size_t i0 = (size_t)r0 * DD + c0;
            size_t i1 = (size_t)(r0 + 8) * DD + c0;
            float2 u0 = *(const float2*)&R[i0];
            float2 u1 = *(const float2*)&R[i1];
            *(float2*)&C[i0] = make_float2(acc[i][j][0] + u0.x, acc[i][j][1] + u0.y);
            *(float2*)&C[i1] = make_float2(acc[i][j][2] + u1.x, acc[i][j][3] + u1.y);
        }
    }
}

// ---------------- tensor-core flash attention (cp.async double-buffered K/V) ----------------
// 256 threads (8 warps); Q tile 128 rows; warp w owns rows [16w,16w+16).
// K kept row-major: B-frag read Ks[n][k] is conflict-free (stride 68); V stride 72.
#define ATT_SMEM ((128*68 + 2*64*68 + 2*64*72) * 4)
__global__ void attn_tc(const float* __restrict__ Q, const float* __restrict__ Kp,
                        const float* __restrict__ Vp, float* __restrict__ O) {
    extern __shared__ float sm[];
    float (*Qs)[68] = (float(*)[68])sm;                         // [128][68]; reused as P tile
    float (*Ks)[64][68] = (float(*)[64][68])(sm + 128*68);      // [2][64][68]
    float (*Vs)[64][72] = (float(*)[64][72])(sm + 128*68 + 2*64*68); // [2][64][72]

    const int tid = threadIdx.x;
    const int lane = tid & 31, w = tid >> 5;
    const int g = lane >> 2, q = lane & 3;
    const int bh = blockIdx.y, b = bh >> 4, h = bh & 15;
    const int q0 = blockIdx.x * 128;
    const size_t base = ((size_t)b*SS)*DD + h*DH;
    const int pr = w * 16;

    { // Q tile load (group 0, together with KV tile 0)
        int r = tid >> 1, c0 = (tid & 1) * 32;
        const float* src = Q + base + (size_t)(q0 + r)*DD + c0;
#pragma unroll
        for (int i = 0; i < 8; i++) cpa16(&Qs[r][c0 + i*4], src + i*4);
    }
    { // KV tile 0
        int r = tid >> 2, c0 = (tid & 3) * 16;
        const float* ksrc = Kp + base + (size_t)r*DD + c0;
        const float* vsrc = Vp + base + (size_t)r*DD + c0;
#pragma unroll
        for (int i = 0; i < 4; i++) cpa16(&Ks[0][r][c0 + i*4], ksrc + i*4);
#pragma unroll
        for (int i = 0; i < 4; i++) cpa16(&Vs[0][r][c0 + i*4], vsrc + i*4);
    }
    CPA_COMMIT();
    { // KV tile 1
        int r = tid >> 2, c0 = (tid & 3) * 16;
        const float* ksrc = Kp + base + (size_t)(64 + r)*DD + c0;
        const float* vsrc = Vp + base + (size_t)(64 + r)*DD + c0;
#pragma unroll
        for (int i = 0; i < 4; i++) cpa16(&Ks[1][r][c0 + i*4], ksrc + i*4);
#pragma unroll
        for (int i = 0; i < 4; i++) cpa16(&Vs[1][r][c0 + i*4], vsrc + i*4);
    }
    CPA_COMMIT();

    CPA_WAIT(1);            // group 0 (Q + KV0) done
    __syncthreads();

    unsigned aq[8][4];      // Q fragments for this warp's 16 rows
#pragma unroll
    for (int ks = 0; ks < 8; ks++) {
        int k = ks * 8;
        aq[ks][0] = __float_as_uint(Qs[pr+g][k+q]);
        aq[ks][1] = __float_as_uint(Qs[pr+8+g][k+q]);
        aq[ks][2] = __float_as_uint(Qs[pr+g][k+4+q]);
        aq[ks][3] = __float_as_uint(Qs[pr+8+g][k+4+q]);
    }
    float (*Ps)[68] = Qs;   // Q region now dead; reuse for P

    float m0r = -1e30f, m1r = -1e30f, l0 = 0.f, l1 = 0.f;
    float acc_o[8][4];
#pragma unroll
    for (int j = 0; j < 8; j++) { acc_o[j][0]=0.f; acc_o[j][1]=0.f; acc_o[j][2]=0.f; acc_o[j][3]=0.f; }

    for (int kt = 0; kt < SS/64; kt++) {
        CPA_WAIT(1);        // KV tile kt done
        __syncthreads();
        const int buf = kt & 1;

        // scores
        float s[8][4];
#pragma unroll
        for (int j = 0; j < 8; j++) { s[j][0]=0.f; s[j][1]=0.f; s[j][2]=0.f; s[j][3]=0.f; }
#pragma unroll
        for (int ks = 0; ks < 8; ks++) {
            int kb = ks * 8;
#pragma unroll
            for (int j = 0; j < 8; j++) {
                unsigned b0 = __float_as_uint(Ks[buf][j*8+g][kb+q]);
                unsigned b1 = __float_as_uint(Ks[buf][j*8+g][kb+4+q]);
                mma8(s[j], aq[ks], b0, b1);
            }
        }
        // online softmax (scale 0.125)
        float mx0 = m0r, mx1 = m1r;
#pragma unroll
        for (int j = 0; j < 8; j++) {
            s[j][0] *= 0.125f; s[j][1] *= 0.125f; s[j][2] *= 0.125f; s[j][3] *= 0.125f;
            mx0 = fmaxf(mx0, fmaxf(s[j][0], s[j][1]));
            mx1 = fmaxf(mx1, fmaxf(s[j][2], s[j][3]));
        }
        mx0 = fmaxf(mx0, __shfl_xor_sync(0xffffffffu, mx0, 1));
        mx0 = fmaxf(mx0, __shfl_xor_sync(0xffffffffu, mx0, 2));
        mx1 = fmaxf(mx1, __shfl_xor_sync(0xffffffffu, mx1, 1));
        mx1 = fmaxf(mx1, __shfl_xor_sync(0xffffffffu, mx1, 2));
        float alpha0 = __expf(m0r - mx0), alpha1 = __expf(m1r - mx1);
        m0r = mx0; m1r = mx1;
        float ps0 = 0.f, ps1 = 0.f;
#pragma unroll
        for (int j = 0; j < 8; j++) {
            s[j][0] = __expf(s[j][0] - mx0); ps0 += s[j][0];
            s[j][1] = __expf(s[j][1] - mx0); ps0 += s[j][1];
            s[j][2] = __expf(s[j][2] - mx1); ps1 += s[j][2];
            s[j][3] = __expf(s[j][3] - mx1); ps1 += s[j][3];
        }
        ps0 += __shfl_xor_sync(0xffffffffu, ps0, 1);
        ps0 += __shfl_xor_sync(0xffffffffu, ps0, 2);
        ps1 += __shfl_xor_sync(0xffffffffu, ps1, 1);
        ps1 += __shfl_xor_sync(0xffffffffu, ps1, 2);
        l0 = l0 * alpha0 + ps0;
        l1 = l1 * alpha1 + ps1;
#pragma unroll
        for (int j = 0; j < 8; j++) {
            acc_o[j][0] *= alpha0; acc_o[j][1] *= alpha0;
            acc_o[j][2] *= alpha1; acc_o[j][3] *= alpha1;
        }
        // stash P into warp-local rows [pr, pr+16)
#pragma unroll
        for (int j = 0; j < 8; j++) {
            *(float2*)&Ps[pr+g][j*8 + 2*q]   = make_float2(s[j][0], s[j][1]);
            *(float2*)&Ps[pr+8+g][j*8 + 2*q] = make_float2(s[j][2], s[j][3]);
        }
        __syncwarp();
        // PV
#pragma unroll
        for (int ks = 0; ks < 8; ks++) {
            int kb = ks * 8;
            unsigned ap[4];
            ap[0] = __float_as_uint(Ps[pr+g][kb+q]);
            ap[1] = __float_as_uint(Ps[pr+8+g][kb+q]);
            ap[2] = __float_as_uint(Ps[pr+g][kb+4+q]);
            ap[3] = __float_as_uint(Ps[pr+8+g][kb+4+q]);
#pragma unroll
            for (int j = 0; j < 8; j++) {
                unsigned b0 = __float_as_uint(Vs[buf][kb+q][j*8+g]);
                unsigned b1 = __float_as_uint(Vs[buf][kb+4+q][j*8+g]);
                mma8(acc_o[j], ap, b0, b1);
            }
        }
        __syncthreads();    // all warps done with buf before refill
        if (kt + 2 < SS/64) {
            int r = tid >> 2, c0 = (tid & 3) * 16;
            const float* ksrc = Kp + base + (size_t)((kt+2)*64 + r)*DD + c0;
            const float* vsrc = Vp + base + (size_t)((kt+2)*64 + r)*DD + c0;
#pragma unroll
            for (int i = 0; i < 4; i++) cpa16(&Ks[buf][r][c0 + i*4], ksrc + i*4);
#pragma unroll
            for (int i = 0; i < 4; i++) cpa16(&Vs[buf][r][c0 + i*4], vsrc + i*4);
        }
        CPA_COMMIT();
    }
    // epilogue
    float inv0 = 1.f / l0, inv1 = 1.f / l1;
    int row0 = q0 + pr + g;
#pragma unroll
    for (int j = 0; j < 8; j++) {
        int col = j*8 + 2*q;
        *(float2*)&O[base + (size_t)row0 * DD + col] =
            make_float2(acc_o[j][0]*inv0, acc_o[j][1]*inv0);
        *(float2*)&O[base + (size_t)(row0+8) * DD + col] =
            make_float2(acc_o[j][2]*inv1, acc_o[j][3]*inv1);
    }
}

// ---------------- gate ----------------
__global__ void zero_cnt_kernel() { if (threadIdx.x < EE) g_cnt[threadIdx.x] = 0; }

__global__ void gate_kernel(const float* __restrict__ xin, const float* __restrict__ Wg) {
    __shared__ float lg[EE];
    int t = blockIdx.x, tid = threadIdx.x;
    int w = tid >> 5, lane = tid & 31;
    const float* xr = xin + (size_t)t * DD;
    float s = 0.f;
    for (int d = lane; d < DD; d += 32) s += xr[d] * Wg[d*EE + w];
#pragma unroll
    for (int o = 16; o > 0; o >>= 1) s += __shfl_down_sync(0xffffffffu, s, o);
    if (lane == 0) lg[w] = s;
    __syncthreads();
    if (tid == 0) {
        float v0 = -1e30f; int i0 = 0;
        for (int e = 0; e < EE; e++) if (lg[e] > v0) { v0 = lg[e]; i0 = e; }
        float v1 = -1e30f; int i1 = 0;
        for (int e = 0; e < EE; e++) if (e != i0 && lg[e] > v1) { v1 = lg[e]; i1 = e; }
        float e1 = __expf(v1 - v0);
        float w0 = 1.f / (1.f + e1);
        float w1 = e1 / (1.f + e1);
        int p0 = atomicAdd(&g_cnt[i0], 1);
        g_tok[i0*NT + p0] = t; g_slotid[i0*NT + p0] = 2*t;     g_wt[i0*NT + p0] = w0;
        int p1 = atomicAdd(&g_cnt[i1], 1);
        g_tok[i1*NT + p1] = t; g_slotid[i1*NT + p1] = 2*t + 1; g_wt[i1*NT + p1] = w1;
    }
}

// ---------------- MoE FFN1 ----------------
__global__ void tc_ffn1(const float* __restrict__ xin, const float* __restrict__ W1,
                        const float* __restrict__ b1) {
    const int e = blockIdx.z;
    const int cnt = g_cnt[e];
    const int m0 = blockIdx.y * 128;
    if (m0 >= cnt) return;
    extern __shared__ float dynf[];
    float (*As)[128][20] = (float(*)[128][20])dynf;
    float (*Bs)[16][136] = (float(*)[16][136])(dynf + GSTAGES*128*20);
    const int n0 = blockIdx.x * 128;
    const int t = threadIdx.x, lane = t & 31, warp = t >> 5;
    const int wm = (warp >> 2) * 64, wn = (warp & 3) * 32;
    float acc[4][4][4] = {};
    int r = m0 + (t >> 1); if (r > cnt - 1) r = cnt - 1;
    const float* aptr = xin + (size_t)g_tok[e*NT + r] * DD;
    gemm_core(aptr, W1 + (size_t)e * DD * FF, DD, FF, n0, acc, As, Bs);
#pragma unroll
    for (int i = 0; i < 4; i++) {
        int r0 = m0 + wm + i*16 + (lane >> 2);
#pragma unroll
        for (int j = 0; j < 4; j++) {
            int c0 = n0 + wn + j*8 + (lane & 3) * 2;
            float bb0 = b1[e*FF + c0], bb1 = b1[e*FF + c0 + 1];
#pragma unroll
            for (int half = 0; half < 2; half++) {
                int rr = r0 + half * 8;
                if (rr >= cnt) continue;
                float u0 = acc[i][j][half*2+0] + bb0;
                float u1 = acc[i][j][half*2+1] + bb1;
                float g0 = 0.5f*u0*(1.f + tanhf(0.7978845608028654f*(u0 + 0.044715f*u0*u0*u0)));
                float g1 = 0.5f*u1*(1.f + tanhf(0.7978845608028654f*(u1 + 0.044715f*u1*u1*u1)));
                *(float2*)&g_h1[((size_t)e*NT + rr)*FF + c0] = make_float2(g0, g1);
            }
        }
    }
}

// ---------------- MoE FFN2 ----------------
__global__ void tc_ffn2(const float* __restrict__ W2, const float* __restrict__ b2) {
    const int e = blockIdx.z;
    const int cnt = g_cnt[e];
    const int m0 = blockIdx.y * 128;
    if (m0 >= cnt) return;
    extern __shared__ float dynf[];
    float (*As)[128][20] = (float(*)[128][20])dynf;
    float (*Bs)[16][136] = (float(*)[16][136])(dynf + GSTAGES*128*20);
    const int n0 = blockIdx.x * 128;
    const int t = threadIdx.x, lane = t & 31, warp = t >> 5;
    const int wm = (warp >> 2) * 64, wn = (warp & 3) * 32;
    float acc[4][4][4] = {};
    int r = m0 + (t >> 1); if (r > cnt - 1) r = cnt - 1;
    const float* aptr = g_h1 + ((size_t)e*NT + r) * FF;
    gemm_core(aptr, W2 + (size_t)e * FF * DD, FF, DD, n0, acc, As, Bs);
#pragma unroll
    for (int i = 0; i < 4; i++) {
        int r0 = m0 + wm + i*16 + (lane >> 2);
#pragma unroll
        for (int j = 0; j < 4; j++) {
            int c0 = n0 + wn + j*8 + (lane & 3) * 2;
            float bb0 = b2[e*DD + c0], bb1 = b2[e*DD + c0 + 1];
#pragma unroll
            for (int half = 0; half < 2; half++) {
                int rr = r0 + half * 8;
                if (rr >= cnt) continue;
                int slot = g_slotid[e*NT + rr];
                float w  = g_wt[e*NT + rr];
                float v0 = w * (acc[i][j][half*2+0] + bb0);
                float v1 = w * (acc[i][j][half*2+1] + bb1);
                *(float2*)&g_contrib[(size_t)slot * DD + c0] = make_float2(v0, v1);
            }
        }
    }
}

// ---------------- final combine ----------------
__global__ void combine_kernel(float* __restrict__ out) {
    int t = blockIdx.x;
    int c = threadIdx.x * 4;
    size_t idx = (size_t)t * DD + c;
    float4 a  = *(const float4*)&g_x1[idx];
    float4 c0 = *(const float4*)&g_contrib[(size_t)(2*t)*DD + c];
    float4 c1 = *(const float4*)&g_contrib[(size_t)(2*t+1)*DD + c];
    float4 o = make_float4(a.x+c0.x+c1.x, a.y+c0.y+c1.y, a.z+c0.z+c1.z, a.w+c0.w+c1.w);
    *(float4*)&out[idx] = o;
}

// ---------------- launch ----------------
extern "C" void kernel_launch(void* const* d_in, const int* in_sizes, int n_in,
                              void* d_out, int out_size) {
    const float* x    = (const float*)d_in[0];
    const float* ln_g = (const float*)d_in[1];
    const float* ln_b = (const float*)d_in[2];
    const float* Wq   = (const float*)d_in[3];
    const float* Wk   = (const float*)d_in[4];
    const float* Wv   = (const float*)d_in[5];
    const float* Wo   = (const float*)d_in[6];
    const float* Wg   = (const float*)d_in[7];
    const float* W1   = (const float*)d_in[8];
    const float* b1   = (const float*)d_in[9];
    const float* W2   = (const float*)d_in[10];
    const float* b2   = (const float*)d_in[11];
    float* out = (float*)d_out;

    float *p_h, *p_q, *p_k, *p_v, *p_attn, *p_x1;
    cudaGetSymbolAddress((void**)&p_h,    g_h);
    cudaGetSymbolAddress((void**)&p_q,    g_q);
    cudaGetSymbolAddress((void**)&p_k,    g_k);
    cudaGetSymbolAddress((void**)&p_v,    g_v);
    cudaGetSymbolAddress((void**)&p_attn, g_attn);
    cudaGetSymbolAddress((void**)&p_x1,   g_x1);

    cudaFuncSetAttribute(tc_qkv,   cudaFuncAttributeMaxDynamicSharedMemorySize, GEMM_SMEM);
    cudaFuncSetAttribute(tc_oproj, cudaFuncAttributeMaxDynamicSharedMemorySize, GEMM_SMEM);
    cudaFuncSetAttribute(tc_ffn1,  cudaFuncAttributeMaxDynamicSharedMemorySize, GEMM_SMEM);
    cudaFuncSetAttribute(tc_ffn2,  cudaFuncAttributeMaxDynamicSharedMemorySize, GEMM_SMEM);
    cudaFuncSetAttribute(attn_tc,  cudaFuncAttributeMaxDynamicSharedMemorySize, ATT_SMEM);

    // 1) layernorm
    ln_kernel<<<NT, 256>>>(x, ln_g, ln_b);
    // 2) fused QKV projections
    tc_qkv<<<dim3(DD/128, NT/128, 3), 256, GEMM_SMEM>>>(p_h, Wq, Wk, Wv, p_q, p_k, p_v);
    // 3) tensor-core flash attention
    attn_tc<<<dim3(SS/128, BB*HH), 256, ATT_SMEM>>>(p_q, p_k, p_v, p_attn);
    // 4) O projection + residual
    tc_oproj<<<dim3(DD/128, NT/128), 256, GEMM_SMEM>>>(p_attn, Wo, x, p_x1);
    // 5) gate + binning
    zero_cnt_kernel<<<1, 32>>>();
    gate_kernel<<<NT, 256>>>(p_x1, Wg);
    // 6) grouped expert FFN
    tc_ffn1<<<dim3(FF/128, NT/128, EE), 256, GEMM_SMEM>>>(p_x1, W1, b1);
    tc_ffn2<<<dim3(DD/128, NT/128, EE), 256, GEMM_SMEM>>>(W2, b2);
    // 7) combine + residual 2
    combine_kernel<<<NT, 256>>>(out);
}

// round 8
// speedup vs baseline: 4.9632x; 1.4508x over previous
#include <cuda_runtime.h>
#include <cuda_fp16.h>
#include <cstdint>
#include <math.h>

// Problem dims
#define BB 2
#define SS 2048
#define DD 1024
#define HH 16
#define DH 64
#define FF 4096
#define EE 8
#define NT (BB*SS)   // 4096 tokens

// ---------------- scratch ----------------
__device__ __half g_h16[NT*DD];            // LN output (fp16, A of QKV)
__device__ float  g_q[NT*DD];
__device__ float  g_k[NT*DD];
__device__ float  g_v[NT*DD];
__device__ __half g_attn16[NT*DD];         // attention out (fp16, A of O-proj)
__device__ float  g_x1[NT*DD];             // x + attn@Wo (fp32: residual+gate)
__device__ __half g_x116[NT*DD];           // fp16 shadow (A of FFN1)
__device__ int    g_cnt[EE];
__device__ int    g_tok[EE*NT];
__device__ int    g_slotid[EE*NT];
__device__ float  g_wt[EE*NT];
__device__ __half g_h116[(size_t)EE*NT*FF];    // expert hidden (fp16, A of FFN2)
__device__ float  g_contrib[(size_t)2*NT*DD];
// fp16 transposed weights: [n][k] K-major (= .col B operand layout)
__device__ __half g_WqT16[DD*DD];
__device__ __half g_WkT16[DD*DD];
__device__ __half g_WvT16[DD*DD];
__device__ __half g_WoT16[DD*DD];
__device__ __half g_W1T16[(size_t)EE*(size_t)FF*DD];   // [e][F][D]
__device__ __half g_W2T16[(size_t)EE*(size_t)DD*FF];   // [e][D][F]

// ---------------- cp.async helpers ----------------
__device__ __forceinline__ void cpa16(const void* dst, const void* src) {
    unsigned d = (unsigned)__cvta_generic_to_shared(dst);
    asm volatile("cp.async.cg.shared.global [%0], [%1], 16;" :: "r"(d), "l"(src));
}
#define CPA_COMMIT()  asm volatile("cp.async.commit_group;")
#define CPA_WAIT(N)   asm volatile("cp.async.wait_group %0;" :: "n"(N))

// ---------------- mma helpers ----------------
// fp16 m16n8k16, fp32 accum
__device__ __forceinline__ void mma16(float (&c)[4], const uint32_t (&a)[4],
                                      uint32_t b0, uint32_t b1) {
    asm volatile("mma.sync.aligned.m16n8k16.row.col.f32.f16.f16.f32 "
        "{%0,%1,%2,%3}, {%4,%5,%6,%7}, {%8,%9}, {%0,%1,%2,%3};"
        : "+f"(c[0]), "+f"(c[1]), "+f"(c[2]), "+f"(c[3])
        : "r"(a[0]), "r"(a[1]), "r"(a[2]), "r"(a[3]), "r"(b0), "r"(b1));
}
// tf32 m16n8k8 (attention only)
__device__ __forceinline__ void mma8(float (&c)[4], const unsigned (&a)[4],
                                     unsigned b0, unsigned b1) {
    asm volatile("mma.sync.aligned.m16n8k8.row.col.f32.tf32.tf32.f32 "
        "{%0,%1,%2,%3}, {%4,%5,%6,%7}, {%8,%9}, {%0,%1,%2,%3};"
        : "+f"(c[0]), "+f"(c[1]), "+f"(c[2]), "+f"(c[3])
        : "r"(a[0]), "r"(a[1]), "r"(a[2]), "r"(a[3]), "r"(b0), "r"(b1));
}

// ---------------- fp16 GEMM core ----------------
// 256 threads, CTA tile 128x128, BK=32 per stage, 4-stage cp.async.
// A: [m][k] fp16 global; B: [n][k] fp16 global (transposed weights).
// smem rows stride 40 halves (80B) -> frag LDS bank pattern 20g+q: conflict-free.
#define HSTR 40
#define STG_HALVES (128*HSTR)          // 5120 halves = 10240 B per stage
#define GEMM16_SMEM (8*STG_HALVES*2)   // 4 A stages + 4 B stages = 81920 B

__device__ __forceinline__ void gemm16_core(const __half* a_src, const __half* b_src,
                                            int Kd, float (&acc)[4][4][4], __half* smem) {
    const int t = threadIdx.x;
    const int lane = t & 31, warp = t >> 5;
    const int g = lane >> 2, q = lane & 3;
    const int wm = (warp >> 2) * 64, wn = (warp & 3) * 32;
    const int r = t >> 1, h = t & 1;

    __half* Asm = smem;
    __half* Bsm = smem + 4 * STG_HALVES;
    __half* ad0 = Asm + (size_t)r * HSTR + h * 16;
    __half* bd0 = Bsm + (size_t)r * HSTR + h * 16;

#define LD_STAGE(s, buf) { \
        const __half* as_ = a_src + (s) * 32; \
        const __half* bs_ = b_src + (s) * 32; \
        __half* ad_ = ad0 + (buf) * STG_HALVES; \
        __half* bd_ = bd0 + (buf) * STG_HALVES; \
        cpa16(ad_, as_); cpa16(ad_ + 8, as_ + 8); \
        cpa16(bd_, bs_); cpa16(bd_ + 8, bs_ + 8); }

    const int steps = Kd / 32;
    LD_STAGE(0, 0); CPA_COMMIT();
    LD_STAGE(1, 1); CPA_COMMIT();
    LD_STAGE(2, 2); CPA_COMMIT();

    for (int s = 0; s < steps; s++) {
        CPA_WAIT(2);
        __syncthreads();
        const int nx = s + 3;
        if (nx < steps) LD_STAGE(nx, nx & 3);
        CPA_COMMIT();
        const __half* As = Asm + (s & 3) * STG_HALVES;
        const __half* Bs = Bsm + (s & 3) * STG_HALVES;
#pragma unroll
        for (int ks = 0; ks < 2; ks++) {
            const int ko = ks * 16 + 2 * q;
            uint32_t a[4][4], bf[4][2];
#pragma unroll
            for (int i = 0; i < 4; i++) {
                const __half* ar = As + (wm + i*16 + g) * HSTR;
                a[i][0] = *(const uint32_t*)(ar + ko);
                a[i][1] = *(const uint32_t*)(ar + 8*HSTR + ko);
                a[i][2] = *(const uint32_t*)(ar + ko + 8);
                a[i][3] = *(const uint32_t*)(ar + 8*HSTR + ko + 8);
            }
#pragma unroll
            for (int j = 0; j < 4; j++) {
                const __half* br = Bs + (wn + j*8 + g) * HSTR;
                bf[j][0] = *(const uint32_t*)(br + ko);
                bf[j][1] = *(const uint32_t*)(br + ko + 8);
            }
#pragma unroll
            for (int i = 0; i < 4; i++)
#pragma unroll
                for (int j = 0; j < 4; j++)
                    mma16(acc[i][j], a[i], bf[j][0], bf[j][1]);
        }
        __syncthreads();
    }
#undef LD_STAGE
}

// ---------------- transpose + fp32->fp16: dst[C][R] = half(src[R][C]) ----------------
__global__ void tr16_kernel(const float* __restrict__ src, __half* __restrict__ dst,
                            int R, int C) {
    __shared__ float tl[32][33];
    const size_t zsrc = (size_t)blockIdx.z * R * C;
    const int bx = blockIdx.x * 32, by = blockIdx.y * 32;
    const int tx = threadIdx.x, ty = threadIdx.y;
#pragma unroll
    for (int i = 0; i < 32; i += 8)
        tl[ty + i][tx] = src[zsrc + (size_t)(by + ty + i) * C + bx + tx];
    __syncthreads();
#pragma unroll
    for (int i = 0; i < 32; i += 8)
        dst[zsrc + (size_t)(bx + ty + i) * R + by + tx] = __float2half(tl[tx][ty + i]);
}

// ---------------- layernorm (fp16 out) ----------------
__global__ void ln_kernel(const float* __restrict__ x, const float* __restrict__ g,
                          const float* __restrict__ b) {
    __shared__ float red[256];
    int t = blockIdx.x, tid = threadIdx.x;
    const float* xr = x + (size_t)t * DD;
    float v[4], s = 0.f, s2 = 0.f;
#pragma unroll
    for (int i = 0; i < 4; i++) {
        float vv = xr[tid + i*256];
        v[i] = vv; s += vv; s2 += vv*vv;
    }
    red[tid] = s; __syncthreads();
    for (int o = 128; o > 0; o >>= 1) { if (tid < o) red[tid] += red[tid+o]; __syncthreads(); }
    float mean = red[0] * (1.f/DD);
    __syncthreads();
    red[tid] = s2; __syncthreads();
    for (int o = 128; o > 0; o >>= 1) { if (tid < o) red[tid] += red[tid+o]; __syncthreads(); }
    float var = red[0] * (1.f/DD) - mean*mean;
    float rs = rsqrtf(var + 1e-5f);
    __half* out = g_h16 + (size_t)t * DD;
#pragma unroll
    for (int i = 0; i < 4; i++) {
        int c = tid + i*256;
        out[c] = __float2half((v[i]-mean)*rs*g[c] + b[c]);
    }
}

// ---------------- QKV (fp16 mma, fp32 out for attention) ----------------
__global__ void tc16_qkv(const __half* __restrict__ BqT, const __half* __restrict__ BkT,
                         const __half* __restrict__ BvT) {
    extern __shared__ __half smh[];
    const __half* BT = blockIdx.z == 0 ? BqT : blockIdx.z == 1 ? BkT : BvT;
    float* C = blockIdx.z == 0 ? g_q : blockIdx.z == 1 ? g_k : g_v;
    const int m0 = blockIdx.y * 128, n0 = blockIdx.x * 128;
    const int t = threadIdx.x, lane = t & 31, warp = t >> 5;
    const int g = lane >> 2, q = lane & 3;
    const int wm = (warp >> 2) * 64, wn = (warp & 3) * 32;
    const int r = t >> 1, h = t & 1;
    float acc[4][4][4] = {};
    const __half* a_src = g_h16 + (size_t)(m0 + r) * DD + h * 16;
    const __half* b_src = BT + (size_t)(n0 + r) * DD + h * 16;
    gemm16_core(a_src, b_src, DD, acc, smh);
#pragma unroll
    for (int i = 0; i < 4; i++) {
        int r0 = m0 + wm + i*16 + g;
#pragma unroll
        for (int j = 0; j < 4; j++) {
            int c0 = n0 + wn + j*8 + 2*q;
            *(float2*)&C[(size_t)r0 * DD + c0]       = make_float2(acc[i][j][0], acc[i][j][1]);
            *(float2*)&C[(size_t)(r0 + 8) * DD + c0] = make_float2(acc[i][j][2], acc[i][j][3]);
        }
    }
}

// ---------------- O-proj + residual (fp32 x1 + fp16 shadow) ----------------
__global__ void tc16_oproj(const __half* __restrict__ BT, const float* __restrict__ Rres) {
    extern __shared__ __half smh[];
    const int m0 = blockIdx.y * 128, n0 = blockIdx.x * 128;
    const int t = threadIdx.x, lane = t & 31, warp = t >> 5;
    const int g = lane >> 2, q = lane & 3;
    const int wm = (warp >> 2) * 64, wn = (warp & 3) * 32;
    const int r = t >> 1, h = t & 1;
    float acc[4][4][4] = {};
    const __half* a_src = g_attn16 + (size_t)(m0 + r) * DD + h * 16;
    const __half* b_src = BT + (size_t)(n0 + r) * DD + h * 16;
    gemm16_core(a_src, b_src, DD, acc, smh);
#pragma unroll
    for (int i = 0; i < 4; i++) {
        int r0 = m0 + wm + i*16 + g;
#pragma unroll
        for (int j = 0; j < 4; j++) {
            int c0 = n0 + wn + j*8 + 2*q;
#pragma unroll
            for (int half_i = 0; half_i < 2; half_i++) {
                size_t idx = (size_t)(r0 + half_i*8) * DD + c0;
                float2 u = *(const float2*)&Rres[idx];
                float v0 = acc[i][j][half_i*2+0] + u.x;
                float v1 = acc[i][j][half_i*2+1] + u.y;
                *(float2*)&g_x1[idx] = make_float2(v0, v1);
                *(__half2*)&g_x116[idx] = __floats2half2_rn(v0, v1);
            }
        }
    }
}

// ---------------- FFN1: gelu(gather(x16) @ W1T + b1) -> h1 fp16 ----------------
__global__ void tc16_ffn1(const __half* __restrict__ W1T, const float* __restrict__ b1) {
    const int e = blockIdx.z;
    const int cnt = g_cnt[e];
    const int m0 = blockIdx.y * 128;
    if (m0 >= cnt) return;
    extern __shared__ __half smh[];
    const int n0 = blockIdx.x * 128;
    const int t = threadIdx.x, lane = t & 31, warp = t >> 5;
    const int g = lane >> 2, q = lane & 3;
    const int wm = (warp >> 2) * 64, wn = (warp & 3) * 32;
    const int r = t >> 1, h = t & 1;
    int ar = m0 + r; if (ar > cnt - 1) ar = cnt - 1;
    const int tok = g_tok[e * NT + ar];
    float acc[4][4][4] = {};
    const __half* a_src = g_x116 + (size_t)tok * DD + h * 16;
    const __half* b_src = W1T + (size_t)e * FF * DD + (size_t)(n0 + r) * DD + h * 16;
    gemm16_core(a_src, b_src, DD, acc, smh);
#pragma unroll
    for (int i = 0; i < 4; i++) {
        int r0 = m0 + wm + i*16 + g;
#pragma unroll
        for (int j = 0; j < 4; j++) {
            int c0 = n0 + wn + j*8 + 2*q;
            float bb0 = b1[e*FF + c0], bb1 = b1[e*FF + c0 + 1];
#pragma unroll
            for (int half_i = 0; half_i < 2; half_i++) {
                int rr = r0 + half_i*8;
                if (rr >= cnt) continue;
                float u0 = acc[i][j][half_i*2+0] + bb0;
                float u1 = acc[i][j][half_i*2+1] + bb1;
                float g0 = 0.5f*u0*(1.f + tanhf(0.7978845608028654f*(u0 + 0.044715f*u0*u0*u0)));
                float g1 = 0.5f*u1*(1.f + tanhf(0.7978845608028654f*(u1 + 0.044715f*u1*u1*u1)));
                *(__half2*)&g_h116[((size_t)e*NT + rr)*FF + c0] = __floats2half2_rn(g0, g1);
            }
        }
    }
}

// ---------------- FFN2: w * (h1 @ W2T + b2) -> contrib fp32 ----------------
__global__ void tc16_ffn2(const __half* __restrict__ W2T, const float* __restrict__ b2) {
    const int e = blockIdx.z;
    const int cnt = g_cnt[e];
    const int m0 = blockIdx.y * 128;
    if (m0 >= cnt) return;
    extern __shared__ __half smh[];
    const int n0 = blockIdx.x * 128;
    const int t = threadIdx.x, lane = t & 31, warp = t >> 5;
    const int g = lane >> 2, q = lane & 3;
    const int wm = (warp >> 2) * 64, wn = (warp & 3) * 32;
    const int r = t >> 1, h = t & 1;
    int ar = m0 + r; if (ar > cnt - 1) ar = cnt - 1;
    float acc[4][4][4] = {};
    const __half* a_src = g_h116 + ((size_t)e*NT + ar) * FF + h * 16;
    const __half* b_src = W2T + (size_t)e * DD * FF + (size_t)(n0 + r) * FF + h * 16;
    gemm16_core(a_src, b_src, FF, acc, smh);
#pragma unroll
    for (int i = 0; i < 4; i++) {
        int r0 = m0 + wm + i*16 + g;
#pragma unroll
        for (int j = 0; j < 4; j++) {
            int c0 = n0 + wn + j*8 + 2*q;
            float bb0 = b2[e*DD + c0], bb1 = b2[e*DD + c0 + 1];
#pragma unroll
            for (int half_i = 0; half_i < 2; half_i++) {
                int rr = r0 + half_i*8;
                if (rr >= cnt) continue;
                int slot = g_slotid[e*NT + rr];
                float w  = g_wt[e*NT + rr];
                *(float2*)&g_contrib[(size_t)slot * DD + c0] =
                    make_float2(w * (acc[i][j][half_i*2+0] + bb0),
                                w * (acc[i][j][half_i*2+1] + bb1));
            }
        }
    }
}

// ---------------- flash attention (tf32 mma, fp32 q/k/v in, fp16 out) ----------------
#define ATT_SMEM ((128*68 + 2*64*68 + 2*64*72) * 4)
__global__ void attn_tc(const float* __restrict__ Q, const float* __restrict__ Kp,
                        const float* __restrict__ Vp) {
    extern __shared__ float sm[];
    float (*Qs)[68] = (float(*)[68])sm;
    float (*Ks)[64][68] = (float(*)[64][68])(sm + 128*68);
    float (*Vs)[64][72] = (float(*)[64][72])(sm + 128*68 + 2*64*68);

    const int tid = threadIdx.x;
    const int lane = tid & 31, w = tid >> 5;
    const int g = lane >> 2, q = lane & 3;
    const int bh = blockIdx.y, b = bh >> 4, h = bh & 15;
    const int q0 = blockIdx.x * 128;
    const size_t base = ((size_t)b*SS)*DD + h*DH;
    const int pr = w * 16;

    {
        int r = tid >> 1, c0 = (tid & 1) * 32;
        const float* src = Q + base + (size_t)(q0 + r)*DD + c0;
#pragma unroll
        for (int i = 0; i < 8; i++) cpa16(&Qs[r][c0 + i*4], src + i*4);
    }
    {
        int r = tid >> 2, c0 = (tid & 3) * 16;
        const float* ksrc = Kp + base + (size_t)r*DD + c0;
        const float* vsrc = Vp + base + (size_t)r*DD + c0;
#pragma unroll
        for (int i = 0; i < 4; i++) cpa16(&Ks[0][r][c0 + i*4], ksrc + i*4);
#pragma unroll
        for (int i = 0; i < 4; i++) cpa16(&Vs[0][r][c0 + i*4], vsrc + i*4);
    }
    CPA_COMMIT();
    {
        int r = tid >> 2, c0 = (tid & 3) * 16;
        const float* ksrc = Kp + base + (size_t)(64 + r)*DD + c0;
        const float* vsrc = Vp + base + (size_t)(64 + r)*DD + c0;
#pragma unroll
        for (int i = 0; i < 4; i++) cpa16(&Ks[1][r][c0 + i*4], ksrc + i*4);
#pragma unroll
        for (int i = 0; i < 4; i++) cpa16(&Vs[1][r][c0 + i*4], vsrc + i*4);
    }
    CPA_COMMIT();

    CPA_WAIT(1);
    __syncthreads();

    unsigned aq[8][4];
#pragma unroll
    for (int ks = 0; ks < 8; ks++) {
        int k = ks * 8;
        aq[ks][0] = __float_as_uint(Qs[pr+g][k+q]);
        aq[ks][1] = __float_as_uint(Qs[pr+8+g][k+q]);
        aq[ks][2] = __float_as_uint(Qs[pr+g][k+4+q]);
        aq[ks][3] = __float_as_uint(Qs[pr+8+g][k+4+q]);
    }
    float (*Ps)[68] = Qs;

    float m0r = -1e30f, m1r = -1e30f, l0 = 0.f, l1 = 0.f;
    float acc_o[8][4];
#pragma unroll
    for (int j = 0; j < 8; j++) { acc_o[j][0]=0.f; acc_o[j][1]=0.f; acc_o[j][2]=0.f; acc_o[j][3]=0.f; }

    for (int kt = 0; kt < SS/64; kt++) {
        CPA_WAIT(1);
        __syncthreads();
        const int buf = kt & 1;

        float s[8][4];
#pragma unroll
        for (int j = 0; j < 8; j++) { s[j][0]=0.f; s[j][1]=0.f; s[j][2]=0.f; s[j][3]=0.f; }
#pragma unroll
        for (int ks = 0; ks < 8; ks++) {
            int kb = ks * 8;
#pragma unroll
            for (int j = 0; j < 8; j++) {
                unsigned b0 = __float_as_uint(Ks[buf][j*8+g][kb+q]);
                unsigned b1 = __float_as_uint(Ks[buf][j*8+g][kb+4+q]);
                mma8(s[j], aq[ks], b0, b1);
            }
        }
        float mx0 = m0r, mx1 = m1r;
#pragma unroll
        for (int j = 0; j < 8; j++) {
            s[j][0] *= 0.125f; s[j][1] *= 0.125f; s[j][2] *= 0.125f; s[j][3] *= 0.125f;
            mx0 = fmaxf(mx0, fmaxf(s[j][0], s[j][1]));
            mx1 = fmaxf(mx1, fmaxf(s[j][2], s[j][3]));
        }
        mx0 = fmaxf(mx0, __shfl_xor_sync(0xffffffffu, mx0, 1));
        mx0 = fmaxf(mx0, __shfl_xor_sync(0xffffffffu, mx0, 2));
        mx1 = fmaxf(mx1, __shfl_xor_sync(0xffffffffu, mx1, 1));
        mx1 = fmaxf(mx1, __shfl_xor_sync(0xffffffffu, mx1, 2));
        float alpha0 = __expf(m0r - mx0), alpha1 = __expf(m1r - mx1);
        m0r = mx0; m1r = mx1;
        float ps0 = 0.f, ps1 = 0.f;
#pragma unroll
        for (int j = 0; j < 8; j++) {
            s[j][0] = __expf(s[j][0] - mx0); ps0 += s[j][0];
            s[j][1] = __expf(s[j][1] - mx0); ps0 += s[j][1];
            s[j][2] = __expf(s[j][2] - mx1); ps1 += s[j][2];
            s[j][3] = __expf(s[j][3] - mx1); ps1 += s[j][3];
        }
        ps0 += __shfl_xor_sync(0xffffffffu, ps0, 1);
        ps0 += __shfl_xor_sync(0xffffffffu, ps0, 2);
        ps1 += __shfl_xor_sync(0xffffffffu, ps1, 1);
        ps1 += __shfl_xor_sync(0xffffffffu, ps1, 2);
        l0 = l0 * alpha0 + ps0;
        l1 = l1 * alpha1 + ps1;
#pragma unroll
        for (int j = 0; j < 8; j++) {
            acc_o[j][0] *= alpha0; acc_o[j][1] *= alpha0;
            acc_o[j][2] *= alpha1; acc_o[j][3] *= alpha1;
        }
#pragma unroll
        for (int j = 0; j < 8; j++) {
            *(float2*)&Ps[pr+g][j*8 + 2*q]   = make_float2(s[j][0], s[j][1]);
            *(float2*)&Ps[pr+8+g][j*8 + 2*q] = make_float2(s[j][2], s[j][3]);
        }
        __syncwarp();
#pragma unroll
        for (int ks = 0; ks < 8; ks++) {
            int kb = ks * 8;
            unsigned ap[4];
            ap[0] = __float_as_uint(Ps[pr+g][kb+q]);
            ap[1] = __float_as_uint(Ps[pr+8+g][kb+q]);
            ap[2] = __float_as_uint(Ps[pr+g][kb+4+q]);
            ap[3] = __float_as_uint(Ps[pr+8+g][kb+4+q]);
#pragma unroll
            for (int j = 0; j < 8; j++) {
                unsigned b0 = __float_as_uint(Vs[buf][kb+q][j*8+g]);
                unsigned b1 = __float_as_uint(Vs[buf][kb+4+q][j*8+g]);
                mma8(acc_o[j], ap, b0, b1);
            }
        }
        __syncthreads();
        if (kt + 2 < SS/64) {
            int r = tid >> 2, c0 = (tid & 3) * 16;
            const float* ksrc = Kp + base + (size_t)((kt+2)*64 + r)*DD + c0;
            const float* vsrc = Vp + base + (size_t)((kt+2)*64 + r)*DD + c0;
#pragma unroll
            for (int i = 0; i < 4; i++) cpa16(&Ks[buf][r][c0 + i*4], ksrc + i*4);
#pragma unroll
            for (int i = 0; i < 4; i++) cpa16(&Vs[buf][r][c0 + i*4], vsrc + i*4);
        }
        CPA_COMMIT();
    }
    float inv0 = 1.f / l0, inv1 = 1.f / l1;
    int row0 = q0 + pr + g;
#pragma unroll
    for (int j = 0; j < 8; j++) {
        int col = j*8 + 2*q;
        *(__half2*)&g_attn16[base + (size_t)row0 * DD + col] =
            __floats2half2_rn(acc_o[j][0]*inv0, acc_o[j][1]*inv0);
        *(__half2*)&g_attn16[base + (size_t)(row0+8) * DD + col] =
            __floats2half2_rn(acc_o[j][2]*inv1, acc_o[j][3]*inv1);
    }
}

// ---------------- gate ----------------
__global__ void zero_cnt_kernel() { if (threadIdx.x < EE) g_cnt[threadIdx.x] = 0; }

__global__ void gate_kernel(const float* __restrict__ Wg) {
    __shared__ float lg[EE];
    int t = blockIdx.x, tid = threadIdx.x;
    int w = tid >> 5, lane = tid & 31;
    const float* xr = g_x1 + (size_t)t * DD;
    float s = 0.f;
    for (int d = lane; d < DD; d += 32) s += xr[d] * Wg[d*EE + w];
#pragma unroll
    for (int o = 16; o > 0; o >>= 1) s += __shfl_down_sync(0xffffffffu, s, o);
    if (lane == 0) lg[w] = s;
    __syncthreads();
    if (tid == 0) {
        float v0 = -1e30f; int i0 = 0;
        for (int e = 0; e < EE; e++) if (lg[e] > v0) { v0 = lg[e]; i0 = e; }
        float v1 = -1e30f; int i1 = 0;
        for (int e = 0; e < EE; e++) if (e != i0 && lg[e] > v1) { v1 = lg[e]; i1 = e; }
        float e1 = __expf(v1 - v0);
        float w0 = 1.f / (1.f + e1);
        float w1 = e1 / (1.f + e1);
        int p0 = atomicAdd(&g_cnt[i0], 1);
        g_tok[i0*NT + p0] = t; g_slotid[i0*NT + p0] = 2*t;     g_wt[i0*NT + p0] = w0;
        int p1 = atomicAdd(&g_cnt[i1], 1);
        g_tok[i1*NT + p1] = t; g_slotid[i1*NT + p1] = 2*t + 1; g_wt[i1*NT + p1] = w1;
    }
}

// ---------------- final combine ----------------
__global__ void combine_kernel(float* __restrict__ out) {
    int t = blockIdx.x;
    int c = threadIdx.x * 4;
    size_t idx = (size_t)t * DD + c;
    float4 a  = *(const float4*)&g_x1[idx];
    float4 c0 = *(const float4*)&g_contrib[(size_t)(2*t)*DD + c];
    float4 c1 = *(const float4*)&g_contrib[(size_t)(2*t+1)*DD + c];
    float4 o = make_float4(a.x+c0.x+c1.x, a.y+c0.y+c1.y, a.z+c0.z+c1.z, a.w+c0.w+c1.w);
    *(float4*)&out[idx] = o;
}

// ---------------- launch ----------------
extern "C" void kernel_launch(void* const* d_in, const int* in_sizes, int n_in,
                              void* d_out, int out_size) {
    const float* x    = (const float*)d_in[0];
    const float* ln_g = (const float*)d_in[1];
    const float* ln_b = (const float*)d_in[2];
    const float* Wq   = (const float*)d_in[3];
    const float* Wk   = (const float*)d_in[4];
    const float* Wv   = (const float*)d_in[5];
    const float* Wo   = (const float*)d_in[6];
    const float* Wg   = (const float*)d_in[7];
    const float* W1   = (const float*)d_in[8];
    const float* b1   = (const float*)d_in[9];
    const float* W2   = (const float*)d_in[10];
    const float* b2   = (const float*)d_in[11];
    float* out = (float*)d_out;

    float *p_q, *p_k, *p_v;
    __half *p_WqT, *p_WkT, *p_WvT, *p_WoT, *p_W1T, *p_W2T;
    cudaGetSymbolAddress((void**)&p_q,   g_q);
    cudaGetSymbolAddress((void**)&p_k,   g_k);
    cudaGetSymbolAddress((void**)&p_v,   g_v);
    cudaGetSymbolAddress((void**)&p_WqT, g_WqT16);
    cudaGetSymbolAddress((void**)&p_WkT, g_WkT16);
    cudaGetSymbolAddress((void**)&p_WvT, g_WvT16);
    cudaGetSymbolAddress((void**)&p_WoT, g_WoT16);
    cudaGetSymbolAddress((void**)&p_W1T, g_W1T16);
    cudaGetSymbolAddress((void**)&p_W2T, g_W2T16);

    cudaFuncSetAttribute(tc16_qkv,   cudaFuncAttributeMaxDynamicSharedMemorySize, GEMM16_SMEM);
    cudaFuncSetAttribute(tc16_oproj, cudaFuncAttributeMaxDynamicSharedMemorySize, GEMM16_SMEM);
    cudaFuncSetAttribute(tc16_ffn1,  cudaFuncAttributeMaxDynamicSharedMemorySize, GEMM16_SMEM);
    cudaFuncSetAttribute(tc16_ffn2,  cudaFuncAttributeMaxDynamicSharedMemorySize, GEMM16_SMEM);
    cudaFuncSetAttribute(attn_tc,    cudaFuncAttributeMaxDynamicSharedMemorySize, ATT_SMEM);

    // 0) weight transpose + fp16 convert
    dim3 trt(32, 8);
    tr16_kernel<<<dim3(32, 32, 1), trt>>>(Wq, p_WqT, DD, DD);
    tr16_kernel<<<dim3(32, 32, 1), trt>>>(Wk, p_WkT, DD, DD);
    tr16_kernel<<<dim3(32, 32, 1), trt>>>(Wv, p_WvT, DD, DD);
    tr16_kernel<<<dim3(32, 32, 1), trt>>>(Wo, p_WoT, DD, DD);
    tr16_kernel<<<dim3(FF/32, DD/32, EE), trt>>>(W1, p_W1T, DD, FF);
    tr16_kernel<<<dim3(DD/32, FF/32, EE), trt>>>(W2, p_W2T, FF, DD);
    // 1) layernorm (fp16 out)
    ln_kernel<<<NT, 256>>>(x, ln_g, ln_b);
    // 2) QKV projections (fp16 mma)
    tc16_qkv<<<dim3(DD/128, NT/128, 3), 256, GEMM16_SMEM>>>(p_WqT, p_WkT, p_WvT);
    // 3) flash attention (tf32 mma, fp16 out)
    attn_tc<<<dim3(SS/128, BB*HH), 256, ATT_SMEM>>>(p_q, p_k, p_v);
    // 4) O projection + residual
    tc16_oproj<<<dim3(DD/128, NT/128), 256, GEMM16_SMEM>>>(p_WoT, x);
    // 5) gate + binning
    zero_cnt_kernel<<<1, 32>>>();
    gate_kernel<<<NT, 256>>>(Wg);
    // 6) grouped expert FFN (fp16 mma)
    tc16_ffn1<<<dim3(FF/128, NT/128, EE), 256, GEMM16_SMEM>>>(p_W1T, b1);
    tc16_ffn2<<<dim3(DD/128, NT/128, EE), 256, GEMM16_SMEM>>>(p_W2T, b2);
    // 7) combine + residual 2
    combine_kernel<<<NT, 256>>>(out);
}

// round 10
// speedup vs baseline: 5.5624x; 1.1207x over previous
#include <cuda_runtime.h>
#include <cuda_fp16.h>
#include <cstdint>
#include <math.h>

// Problem dims
#define BB 2
#define SS 2048
#define DD 1024
#define HH 16
#define DH 64
#define FF 4096
#define EE 8
#define NT (BB*SS)   // 4096 tokens

// ---------------- scratch ----------------
__device__ __half g_h16[NT*DD];            // LN output (fp16)
__device__ __half g_q16[NT*DD];            // Q (fp16 token-major)
__device__ __half g_k16[NT*DD];            // K (fp16 token-major)
__device__ __half g_vT16[(size_t)BB*HH*DH*SS];  // V transposed: [bh][d][s]
__device__ __half g_attn16[NT*DD];         // attention out (fp16)
__device__ float  g_x1[NT*DD];             // x + attn@Wo (fp32)
__device__ __half g_x116[NT*DD];           // fp16 shadow
__device__ int    g_cnt[EE];
__device__ int    g_tok[EE*NT];
__device__ int    g_slotid[EE*NT];
__device__ float  g_wt[EE*NT];
__device__ __half g_h116[(size_t)EE*NT*FF];
__device__ float  g_contrib[(size_t)2*NT*DD];
// fp16 transposed weights: [n][k] K-major
__device__ __half g_WqT16[DD*DD];
__device__ __half g_WkT16[DD*DD];
__device__ __half g_WvT16[DD*DD];
__device__ __half g_WoT16[DD*DD];
__device__ __half g_W1T16[(size_t)EE*(size_t)FF*DD];
__device__ __half g_W2T16[(size_t)EE*(size_t)DD*FF];

// ---------------- cp.async helpers ----------------
__device__ __forceinline__ void cpa16(const void* dst, const void* src) {
    unsigned d = (unsigned)__cvta_generic_to_shared(dst);
    asm volatile("cp.async.cg.shared.global [%0], [%1], 16;" :: "r"(d), "l"(src));
}
#define CPA_COMMIT()  asm volatile("cp.async.commit_group;")
#define CPA_WAIT(N)   asm volatile("cp.async.wait_group %0;" :: "n"(N))

// fp16 m16n8k16, fp32 accum
__device__ __forceinline__ void mma16(float (&c)[4], const uint32_t (&a)[4],
                                      uint32_t b0, uint32_t b1) {
    asm volatile("mma.sync.aligned.m16n8k16.row.col.f32.f16.f16.f32 "
        "{%0,%1,%2,%3}, {%4,%5,%6,%7}, {%8,%9}, {%0,%1,%2,%3};"
        : "+f"(c[0]), "+f"(c[1]), "+f"(c[2]), "+f"(c[3])
        : "r"(a[0]), "r"(a[1]), "r"(a[2]), "r"(a[3]), "r"(b0), "r"(b1));
}

// ---------------- fp16 GEMM core (single barrier per K-slab) ----------------
#define HSTR 40
#define STG_HALVES (128*HSTR)
#define GEMM16_SMEM (8*STG_HALVES*2)

__device__ __forceinline__ void gemm16_core(const __half* a_src, const __half* b_src,
                                            int Kd, float (&acc)[4][4][4], __half* smem) {
    const int t = threadIdx.x;
    const int lane = t & 31, warp = t >> 5;
    const int g = lane >> 2, q = lane & 3;
    const int wm = (warp >> 2) * 64, wn = (warp & 3) * 32;
    const int r = t >> 1, h = t & 1;

    __half* Asm = smem;
    __half* Bsm = smem + 4 * STG_HALVES;
    __half* ad0 = Asm + (size_t)r * HSTR + h * 16;
    __half* bd0 = Bsm + (size_t)r * HSTR + h * 16;

#define LD_STAGE(s, buf) { \
        const __half* as_ = a_src + (s) * 32; \
        const __half* bs_ = b_src + (s) * 32; \
        __half* ad_ = ad0 + (buf) * STG_HALVES; \
        __half* bd_ = bd0 + (buf) * STG_HALVES; \
        cpa16(ad_, as_); cpa16(ad_ + 8, as_ + 8); \
        cpa16(bd_, bs_); cpa16(bd_ + 8, bs_ + 8); }

    const int steps = Kd / 32;
    LD_STAGE(0, 0); CPA_COMMIT();
    LD_STAGE(1, 1); CPA_COMMIT();
    LD_STAGE(2, 2); CPA_COMMIT();

    for (int s = 0; s < steps; s++) {
        CPA_WAIT(2);
        __syncthreads();          // single barrier: also protects buffer reuse
        const int nx = s + 3;
        if (nx < steps) LD_STAGE(nx, nx & 3);
        CPA_COMMIT();
        const __half* As = Asm + (s & 3) * STG_HALVES;
        const __half* Bs = Bsm + (s & 3) * STG_HALVES;
#pragma unroll
        for (int ks = 0; ks < 2; ks++) {
            const int ko = ks * 16 + 2 * q;
            uint32_t a[4][4], bf[4][2];
#pragma unroll
            for (int i = 0; i < 4; i++) {
                const __half* ar = As + (wm + i*16 + g) * HSTR;
                a[i][0] = *(const uint32_t*)(ar + ko);
                a[i][1] = *(const uint32_t*)(ar + 8*HSTR + ko);
                a[i][2] = *(const uint32_t*)(ar + ko + 8);
                a[i][3] = *(const uint32_t*)(ar + 8*HSTR + ko + 8);
            }
#pragma unroll
            for (int j = 0; j < 4; j++) {
                const __half* br = Bs + (wn + j*8 + g) * HSTR;
                bf[j][0] = *(const uint32_t*)(br + ko);
                bf[j][1] = *(const uint32_t*)(br + ko + 8);
            }
#pragma unroll
            for (int i = 0; i < 4; i++)
#pragma unroll
                for (int j = 0; j < 4; j++)
                    mma16(acc[i][j], a[i], bf[j][0], bf[j][1]);
        }
    }
#undef LD_STAGE
}

// ---------------- transpose + fp32->fp16 ----------------
__global__ void tr16_kernel(const float* __restrict__ src, __half* __restrict__ dst,
                            int R, int C) {
    __shared__ float tl[32][33];
    const size_t zsrc = (size_t)blockIdx.z * R * C;
    const int bx = blockIdx.x * 32, by = blockIdx.y * 32;
    const int tx = threadIdx.x, ty = threadIdx.y;
#pragma unroll
    for (int i = 0; i < 32; i += 8)
        tl[ty + i][tx] = src[zsrc + (size_t)(by + ty + i) * C + bx + tx];
    __syncthreads();
#pragma unroll
    for (int i = 0; i < 32; i += 8)
        dst[zsrc + (size_t)(bx + ty + i) * R + by + tx] = __float2half(tl[tx][ty + i]);
}

// ---------------- layernorm (fp16 out) ----------------
__global__ void ln_kernel(const float* __restrict__ x, const float* __restrict__ g,
                          const float* __restrict__ b) {
    __shared__ float red[256];
    int t = blockIdx.x, tid = threadIdx.x;
    const float* xr = x + (size_t)t * DD;
    float v[4], s = 0.f, s2 = 0.f;
#pragma unroll
    for (int i = 0; i < 4; i++) {
        float vv = xr[tid + i*256];
        v[i] = vv; s += vv; s2 += vv*vv;
    }
    red[tid] = s; __syncthreads();
    for (int o = 128; o > 0; o >>= 1) { if (tid < o) red[tid] += red[tid+o]; __syncthreads(); }
    float mean = red[0] * (1.f/DD);
    __syncthreads();
    red[tid] = s2; __syncthreads();
    for (int o = 128; o > 0; o >>= 1) { if (tid < o) red[tid] += red[tid+o]; __syncthreads(); }
    float var = red[0] * (1.f/DD) - mean*mean;
    float rs = rsqrtf(var + 1e-5f);
    __half* out = g_h16 + (size_t)t * DD;
#pragma unroll
    for (int i = 0; i < 4; i++) {
        int c = tid + i*256;
        out[c] = __float2half((v[i]-mean)*rs*g[c] + b[c]);
    }
}

// ---------------- QKV (fp16 mma; Q/K fp16 token-major, V transposed) ----------------
__global__ void tc16_qkv(const __half* __restrict__ BqT, const __half* __restrict__ BkT,
                         const __half* __restrict__ BvT) {
    extern __shared__ __half smh[];
    const __half* BT = blockIdx.z == 0 ? BqT : blockIdx.z == 1 ? BkT : BvT;
    const int m0 = blockIdx.y * 128, n0 = blockIdx.x * 128;
    const int t = threadIdx.x, lane = t & 31, warp = t >> 5;
    const int g = lane >> 2, q = lane & 3;
    const int wm = (warp >> 2) * 64, wn = (warp & 3) * 32;
    const int r = t >> 1, h = t & 1;
    float acc[4][4][4] = {};
    const __half* a_src = g_h16 + (size_t)(m0 + r) * DD + h * 16;
    const __half* b_src = BT + (size_t)(n0 + r) * DD + h * 16;
    gemm16_core(a_src, b_src, DD, acc, smh);

    if (blockIdx.z == 2) {
        // V: write transposed g_vT16[bh][d][s]
#pragma unroll
        for (int i = 0; i < 4; i++) {
            int r0 = m0 + wm + i*16 + g;
#pragma unroll
            for (int j = 0; j < 4; j++) {
                int c0 = n0 + wn + j*8 + 2*q;
                int hh = c0 >> 6, dd = c0 & 63;
#pragma unroll
                for (int hf = 0; hf < 2; hf++) {
                    int row = r0 + hf*8;
                    int b_ = row >> 11, s_ = row & 2047;
                    size_t basev = ((size_t)(b_*HH + hh) * DH);
                    g_vT16[(basev + dd)     * SS + s_] = __float2half(acc[i][j][hf*2+0]);
                    g_vT16[(basev + dd + 1) * SS + s_] = __float2half(acc[i][j][hf*2+1]);
                }
            }
        }
    } else {
        __half* C = blockIdx.z == 0 ? g_q16 : g_k16;
#pragma unroll
        for (int i = 0; i < 4; i++) {
            int r0 = m0 + wm + i*16 + g;
#pragma unroll
            for (int j = 0; j < 4; j++) {
                int c0 = n0 + wn + j*8 + 2*q;
                *(__half2*)&C[(size_t)r0 * DD + c0] =
                    __floats2half2_rn(acc[i][j][0], acc[i][j][1]);
                *(__half2*)&C[(size_t)(r0+8) * DD + c0] =
                    __floats2half2_rn(acc[i][j][2], acc[i][j][3]);
            }
        }
    }
}

// ---------------- fp16 flash attention ----------------
// 256 threads (8 warps), Q tile 128 rows, fp16 m16n8k16 for scores and PV.
// Smem tiles stride 72 halves: B-frag word idx (4g+q) mod 32 -> conflict-free.
#define AST 72
#define ATT_SMEM ((128*AST + 2*64*AST + 2*64*AST) * 2)
__global__ void attn16() {
    extern __shared__ __half ash[];
    __half (*Qs)[AST]       = (__half(*)[AST])ash;                       // [128][72], reused as P
    __half (*Ks)[64][AST]   = (__half(*)[64][AST])(ash + 128*AST);       // [2][64][72] (key-major)
    __half (*Vts)[64][AST]  = (__half(*)[64][AST])(ash + 128*AST + 2*64*AST); // [2][64][72] (d-major)

    const int tid = threadIdx.x;
    const int lane = tid & 31, w = tid >> 5;
    const int g = lane >> 2, q = lane & 3;
    const int bh = blockIdx.y, b = bh >> 4, h = bh & 15;
    const int q0 = blockIdx.x * 128;
    const size_t tokbase = ((size_t)b*SS)*DD + h*DH;
    const size_t vtbase  = (size_t)bh * DH * SS;
    const int pr = w * 16;

    { // Q tile (group A, with KV tile 0)
        int r = tid >> 1, cq = (tid & 1) * 32;
        const __half* src = g_q16 + tokbase + (size_t)(q0 + r)*DD + cq;
        cpa16(&Qs[r][cq],      src);      cpa16(&Qs[r][cq + 8],  src + 8);
        cpa16(&Qs[r][cq + 16], src + 16); cpa16(&Qs[r][cq + 24], src + 24);
    }
    {
        int r = tid >> 2, cq = (tid & 3) * 16;
        const __half* ksrc = g_k16 + tokbase + (size_t)r*DD + cq;
        cpa16(&Ks[0][r][cq], ksrc); cpa16(&Ks[0][r][cq + 8], ksrc + 8);
        const __half* vsrc = g_vT16 + vtbase + (size_t)r*SS + cq;
        cpa16(&Vts[0][r][cq], vsrc); cpa16(&Vts[0][r][cq + 8], vsrc + 8);
    }
    CPA_COMMIT();
    { // KV tile 1 (group B)
        int r = tid >> 2, cq = (tid & 3) * 16;
        const __half* ksrc = g_k16 + tokbase + (size_t)(64 + r)*DD + cq;
        cpa16(&Ks[1][r][cq], ksrc); cpa16(&Ks[1][r][cq + 8], ksrc + 8);
        const __half* vsrc = g_vT16 + vtbase + (size_t)r*SS + 64 + cq;
        cpa16(&Vts[1][r][cq], vsrc); cpa16(&Vts[1][r][cq + 8], vsrc + 8);
    }
    CPA_COMMIT();

    CPA_WAIT(1);
    __syncthreads();

    uint32_t aq[4][4];   // Q fragments: rows pr+g/pr+8+g
#pragma unroll
    for (int ks = 0; ks < 4; ks++) {
        const int ko = ks*16 + 2*q;
        aq[ks][0] = *(const uint32_t*)&Qs[pr+g][ko];
        aq[ks][1] = *(const uint32_t*)&Qs[pr+8+g][ko];
        aq[ks][2] = *(const uint32_t*)&Qs[pr+g][ko + 8];
        aq[ks][3] = *(const uint32_t*)&Qs[pr+8+g][ko + 8];
    }
    __half (*Ps)[AST] = Qs;   // Q region dead; reuse for P

    float m0r = -1e30f, m1r = -1e30f, l0 = 0.f, l1 = 0.f;
    float acc_o[8][4];
#pragma unroll
    for (int j = 0; j < 8; j++) { acc_o[j][0]=0.f; acc_o[j][1]=0.f; acc_o[j][2]=0.f; acc_o[j][3]=0.f; }

    for (int kt = 0; kt < SS/64; kt++) {
        CPA_WAIT(1);
        __syncthreads();
        const int buf = kt & 1;

        // scores (fp16 k16)
        float s[8][4];
#pragma unroll
        for (int j = 0; j < 8; j++) { s[j][0]=0.f; s[j][1]=0.f; s[j][2]=0.f; s[j][3]=0.f; }
#pragma unroll
        for (int ks = 0; ks < 4; ks++) {
            const int ko = ks*16 + 2*q;
#pragma unroll
            for (int j = 0; j < 8; j++) {
                uint32_t b0 = *(const uint32_t*)&Ks[buf][j*8+g][ko];
                uint32_t b1 = *(const uint32_t*)&Ks[buf][j*8+g][ko + 8];
                mma16(s[j], aq[ks], b0, b1);
            }
        }
        // online softmax (scale 0.125)
        float mx0 = m0r, mx1 = m1r;
#pragma unroll
        for (int j = 0; j < 8; j++) {
            s[j][0] *= 0.125f; s[j][1] *= 0.125f; s[j][2] *= 0.125f; s[j][3] *= 0.125f;
            mx0 = fmaxf(mx0, fmaxf(s[j][0], s[j][1]));
            mx1 = fmaxf(mx1, fmaxf(s[j][2], s[j][3]));
        }
        mx0 = fmaxf(mx0, __shfl_xor_sync(0xffffffffu, mx0, 1));
        mx0 = fmaxf(mx0, __shfl_xor_sync(0xffffffffu, mx0, 2));
        mx1 = fmaxf(mx1, __shfl_xor_sync(0xffffffffu, mx1, 1));
        mx1 = fmaxf(mx1, __shfl_xor_sync(0xffffffffu, mx1, 2));
        float alpha0 = __expf(m0r - mx0), alpha1 = __expf(m1r - mx1);
        m0r = mx0; m1r = mx1;
        float ps0 = 0.f, ps1 = 0.f;
#pragma unroll
        for (int j = 0; j < 8; j++) {
            s[j][0] = __expf(s[j][0] - mx0); ps0 += s[j][0];
            s[j][1] = __expf(s[j][1] - mx0); ps0 += s[j][1];
            s[j][2] = __expf(s[j][2] - mx1); ps1 += s[j][2];
            s[j][3] = __expf(s[j][3] - mx1); ps1 += s[j][3];
        }
        ps0 += __shfl_xor_sync(0xffffffffu, ps0, 1);
        ps0 += __shfl_xor_sync(0xffffffffu, ps0, 2);
        ps1 += __shfl_xor_sync(0xffffffffu, ps1, 1);
        ps1 += __shfl_xor_sync(0xffffffffu, ps1, 2);
        l0 = l0 * alpha0 + ps0;
        l1 = l1 * alpha1 + ps1;
#pragma unroll
        for (int j = 0; j < 8; j++) {
            acc_o[j][0] *= alpha0; acc_o[j][1] *= alpha0;
            acc_o[j][2] *= alpha1; acc_o[j][3] *= alpha1;
        }
        // stash P (fp16) into warp-local rows
#pragma unroll
        for (int j = 0; j < 8; j++) {
            *(__half2*)&Ps[pr+g][j*8 + 2*q]   = __floats2half2_rn(s[j][0], s[j][1]);
            *(__half2*)&Ps[pr+8+g][j*8 + 2*q] = __floats2half2_rn(s[j][2], s[j][3]);
        }
        __syncwarp();
        // PV (fp16 k16): A = P[row][key], B = Vt[d][key]
#pragma unroll
        for (int ks = 0; ks < 4; ks++) {
            const int ko = ks*16 + 2*q;
            uint32_t ap[4];
            ap[0] = *(const uint32_t*)&Ps[pr+g][ko];
            ap[1] = *(const uint32_t*)&Ps[pr+8+g][ko];
            ap[2] = *(const uint32_t*)&Ps[pr+g][ko + 8];
            ap[3] = *(const uint32_t*)&Ps[pr+8+g][ko + 8];
#pragma unroll
            for (int j = 0; j < 8; j++) {
                uint32_t b0 = *(const uint32_t*)&Vts[buf][j*8+g][ko];
                uint32_t b1 = *(const uint32_t*)&Vts[buf][j*8+g][ko + 8];
                mma16(acc_o[j], ap, b0, b1);
            }
        }
        __syncthreads();   // all warps done with buf before refill
        if (kt + 2 < SS/64) {
            int r = tid >> 2, cq = (tid & 3) * 16;
            const __half* ksrc = g_k16 + tokbase + (size_t)((kt+2)*64 + r)*DD + cq;
            cpa16(&Ks[buf][r][cq], ksrc); cpa16(&Ks[buf][r][cq + 8], ksrc + 8);
            const __half* vsrc = g_vT16 + vtbase + (size_t)r*SS + (kt+2)*64 + cq;
            cpa16(&Vts[buf][r][cq], vsrc); cpa16(&Vts[buf][r][cq + 8], vsrc + 8);
        }
        CPA_COMMIT();
    }
    // epilogue
    float inv0 = 1.f / l0, inv1 = 1.f / l1;
    int row0 = q0 + pr + g;
#pragma unroll
    for (int j = 0; j < 8; j++) {
        int col = j*8 + 2*q;
        *(__half2*)&g_attn16[tokbase + (size_t)row0 * DD + col] =
            __floats2half2_rn(acc_o[j][0]*inv0, acc_o[j][1]*inv0);
        *(__half2*)&g_attn16[tokbase + (size_t)(row0+8) * DD + col] =
            __floats2half2_rn(acc_o[j][2]*inv1, acc_o[j][3]*inv1);
    }
}

// ---------------- O-proj + residual ----------------
__global__ void tc16_oproj(const __half* __restrict__ BT, const float* __restrict__ Rres) {
    extern __shared__ __half smh[];
    const int m0 = blockIdx.y * 128, n0 = blockIdx.x * 128;
    const int t = threadIdx.x, lane = t & 31, warp = t >> 5;
    const int g = lane >> 2, q = lane & 3;
    const int wm = (warp >> 2) * 64, wn = (warp & 3) * 32;
    const int r = t >> 1, h = t & 1;
    float acc[4][4][4] = {};
    const __half* a_src = g_attn16 + (size_t)(m0 + r) * DD + h * 16;
    const __half* b_src = BT + (size_t)(n0 + r) * DD + h * 16;
    gemm16_core(a_src, b_src, DD, acc, smh);
#pragma unroll
    for (int i = 0; i < 4; i++) {
        int r0 = m0 + wm + i*16 + g;
#pragma unroll
        for (int j = 0; j < 4; j++) {
            int c0 = n0 + wn + j*8 + 2*q;
#pragma unroll
            for (int hf = 0; hf < 2; hf++) {
                size_t idx = (size_t)(r0 + hf*8) * DD + c0;
                float2 u = *(const float2*)&Rres[idx];
                float v0 = acc[i][j][hf*2+0] + u.x;
                float v1 = acc[i][j][hf*2+1] + u.y;
                *(float2*)&g_x1[idx] = make_float2(v0, v1);
                *(__half2*)&g_x116[idx] = __floats2half2_rn(v0, v1);
            }
        }
    }
}

// ---------------- FFN1 ----------------
__global__ void tc16_ffn1(const __half* __restrict__ W1T, const float* __restrict__ b1) {
    const int e = blockIdx.z;
    const int cnt = g_cnt[e];
    const int m0 = blockIdx.y * 128;
    if (m0 >= cnt) return;
    extern __shared__ __half smh[];
    const int n0 = blockIdx.x * 128;
    const int t = threadIdx.x, lane = t & 31, warp = t >> 5;
    const int g = lane >> 2, q = lane & 3;
    const int wm = (warp >> 2) * 64, wn = (warp & 3) * 32;
    const int r = t >> 1, h = t & 1;
    int ar = m0 + r; if (ar > cnt - 1) ar = cnt - 1;
    const int tok = g_tok[e * NT + ar];
    float acc[4][4][4] = {};
    const __half* a_src = g_x116 + (size_t)tok * DD + h * 16;
    const __half* b_src = W1T + (size_t)e * FF * DD + (size_t)(n0 + r) * DD + h * 16;
    gemm16_core(a_src, b_src, DD, acc, smh);
#pragma unroll
    for (int i = 0; i < 4; i++) {
        int r0 = m0 + wm + i*16 + g;
#pragma unroll
        for (int j = 0; j < 4; j++) {
            int c0 = n0 + wn + j*8 + 2*q;
            float bb0 = b1[e*FF + c0], bb1 = b1[e*FF + c0 + 1];
#pragma unroll
            for (int hf = 0; hf < 2; hf++) {
                int rr = r0 + hf*8;
                if (rr >= cnt) continue;
                float u0 = acc[i][j][hf*2+0] + bb0;
                float u1 = acc[i][j][hf*2+1] + bb1;
                float g0 = 0.5f*u0*(1.f + tanhf(0.7978845608028654f*(u0 + 0.044715f*u0*u0*u0)));
                float g1 = 0.5f*u1*(1.f + tanhf(0.7978845608028654f*(u1 + 0.044715f*u1*u1*u1)));
                *(__half2*)&g_h116[((size_t)e*NT + rr)*FF + c0] = __floats2half2_rn(g0, g1);
            }
        }
    }
}

// ---------------- FFN2 ----------------
__global__ void tc16_ffn2(const __half* __restrict__ W2T, const float* __restrict__ b2) {
    const int e = blockIdx.z;
    const int cnt = g_cnt[e];
    const int m0 = blockIdx.y * 128;
    if (m0 >= cnt) return;
    extern __shared__ __half smh[];
    const int n0 = blockIdx.x * 128;
    const int t = threadIdx.x, lane = t & 31, warp = t >> 5;
    const int g = lane >> 2, q = lane & 3;
    const int wm = (warp >> 2) * 64, wn = (warp & 3) * 32;
    const int r = t >> 1, h = t & 1;
    int ar = m0 + r; if (ar > cnt - 1) ar = cnt - 1;
    float acc[4][4][4] = {};
    const __half* a_src = g_h116 + ((size_t)e*NT + ar) * FF + h * 16;
    const __half* b_src = W2T + (size_t)e * DD * FF + (size_t)(n0 + r) * FF + h * 16;
    gemm16_core(a_src, b_src, FF, acc, smh);
#pragma unroll
    for (int i = 0; i < 4; i++) {
        int r0 = m0 + wm + i*16 + g;
#pragma unroll
        for (int j = 0; j < 4; j++) {
            int c0 = n0 + wn + j*8 + 2*q;
            float bb0 = b2[e*DD + c0], bb1 = b2[e*DD + c0 + 1];
#pragma unroll
            for (int hf = 0; hf < 2; hf++) {
                int rr = r0 + hf*8;
                if (rr >= cnt) continue;
                int slot = g_slotid[e*NT + rr];
                float w  = g_wt[e*NT + rr];
                *(float2*)&g_contrib[(size_t)slot * DD + c0] =
                    make_float2(w * (acc[i][j][hf*2+0] + bb0),
                                w * (acc[i][j][hf*2+1] + bb1));
            }
        }
    }
}

// ---------------- gate ----------------
__global__ void zero_cnt_kernel() { if (threadIdx.x < EE) g_cnt[threadIdx.x] = 0; }

__global__ void gate_kernel(const float* __restrict__ Wg) {
    __shared__ float lg[EE];
    int t = blockIdx.x, tid = threadIdx.x;
    int w = tid >> 5, lane = tid & 31;
    const float* xr = g_x1 + (size_t)t * DD;
    float s = 0.f;
    for (int d = lane; d < DD; d += 32) s += xr[d] * Wg[d*EE + w];
#pragma unroll
    for (int o = 16; o > 0; o >>= 1) s += __shfl_down_sync(0xffffffffu, s, o);
    if (lane == 0) lg[w] = s;
    __syncthreads();
    if (tid == 0) {
        float v0 = -1e30f; int i0 = 0;
        for (int e = 0; e < EE; e++) if (lg[e] > v0) { v0 = lg[e]; i0 = e; }
        float v1 = -1e30f; int i1 = 0;
        for (int e = 0; e < EE; e++) if (e != i0 && lg[e] > v1) { v1 = lg[e]; i1 = e; }
        float e1 = __expf(v1 - v0);
        float w0 = 1.f / (1.f + e1);
        float w1 = e1 / (1.f + e1);
        int p0 = atomicAdd(&g_cnt[i0], 1);
        g_tok[i0*NT + p0] = t; g_slotid[i0*NT + p0] = 2*t;     g_wt[i0*NT + p0] = w0;
        int p1 = atomicAdd(&g_cnt[i1], 1);
        g_tok[i1*NT + p1] = t; g_slotid[i1*NT + p1] = 2*t + 1; g_wt[i1*NT + p1] = w1;
    }
}

// ---------------- final combine ----------------
__global__ void combine_kernel(float* __restrict__ out) {
    int t = blockIdx.x;
    int c = threadIdx.x * 4;
    size_t idx = (size_t)t * DD + c;
    float4 a  = *(const float4*)&g_x1[idx];
    float4 c0 = *(const float4*)&g_contrib[(size_t)(2*t)*DD + c];
    float4 c1 = *(const float4*)&g_contrib[(size_t)(2*t+1)*DD + c];
    float4 o = make_float4(a.x+c0.x+c1.x, a.y+c0.y+c1.y, a.z+c0.z+c1.z, a.w+c0.w+c1.w);
    *(float4*)&out[idx] = o;
}

// ---------------- launch ----------------
extern "C" void kernel_launch(void* const* d_in, const int* in_sizes, int n_in,
                              void* d_out, int out_size) {
    const float* x    = (const float*)d_in[0];
    const float* ln_g = (const float*)d_in[1];
    const float* ln_b = (const float*)d_in[2];
    const float* Wq   = (const float*)d_in[3];
    const float* Wk   = (const float*)d_in[4];
    const float* Wv   = (const float*)d_in[5];
    const float* Wo   = (const float*)d_in[6];
    const float* Wg   = (const float*)d_in[7];
    const float* W1   = (const float*)d_in[8];
    const float* b1   = (const float*)d_in[9];
    const float* W2   = (const float*)d_in[10];
    const float* b2   = (const float*)d_in[11];
    float* out = (float*)d_out;

    __half *p_WqT, *p_WkT, *p_WvT, *p_WoT, *p_W1T, *p_W2T;
    cudaGetSymbolAddress((void**)&p_WqT, g_WqT16);
    cudaGetSymbolAddress((void**)&p_WkT, g_WkT16);
    cudaGetSymbolAddress((void**)&p_WvT, g_WvT16);
    cudaGetSymbolAddress((void**)&p_WoT, g_WoT16);
    cudaGetSymbolAddress((void**)&p_W1T, g_W1T16);
    cudaGetSymbolAddress((void**)&p_W2T, g_W2T16);

    cudaFuncSetAttribute(tc16_qkv,   cudaFuncAttributeMaxDynamicSharedMemorySize, GEMM16_SMEM);
    cudaFuncSetAttribute(tc16_oproj, cudaFuncAttributeMaxDynamicSharedMemorySize, GEMM16_SMEM);
    cudaFuncSetAttribute(tc16_ffn1,  cudaFuncAttributeMaxDynamicSharedMemorySize, GEMM16_SMEM);
    cudaFuncSetAttribute(tc16_ffn2,  cudaFuncAttributeMaxDynamicSharedMemorySize, GEMM16_SMEM);
    cudaFuncSetAttribute(attn16,     cudaFuncAttributeMaxDynamicSharedMemorySize, ATT_SMEM);

    // 0) weight transpose + fp16 convert
    dim3 trt(32, 8);
    tr16_kernel<<<dim3(32, 32, 1), trt>>>(Wq, p_WqT, DD, DD);
    tr16_kernel<<<dim3(32, 32, 1), trt>>>(Wk, p_WkT, DD, DD);
    tr16_kernel<<<dim3(32, 32, 1), trt>>>(Wv, p_WvT, DD, DD);
    tr16_kernel<<<dim3(32, 32, 1), trt>>>(Wo, p_WoT, DD, DD);
    tr16_kernel<<<dim3(FF/32, DD/32, EE), trt>>>(W1, p_W1T, DD, FF);
    tr16_kernel<<<dim3(DD/32, FF/32, EE), trt>>>(W2, p_W2T, FF, DD);
    // 1) layernorm (fp16 out)
    ln_kernel<<<NT, 256>>>(x, ln_g, ln_b);
    // 2) QKV projections (fp16 mma; V written transposed)
    tc16_qkv<<<dim3(DD/128, NT/128, 3), 256, GEMM16_SMEM>>>(p_WqT, p_WkT, p_WvT);
    // 3) fp16 flash attention
    attn16<<<dim3(SS/128, BB*HH), 256, ATT_SMEM>>>();
    // 4) O projection + residual
    tc16_oproj<<<dim3(DD/128, NT/128), 256, GEMM16_SMEM>>>(p_WoT, x);
    // 5) gate + binning
    zero_cnt_kernel<<<1, 32>>>();
    gate_kernel<<<NT, 256>>>(Wg);
    // 6) grouped expert FFN (fp16 mma)
    tc16_ffn1<<<dim3(FF/128, NT/128, EE), 256, GEMM16_SMEM>>>(p_W1T, b1);
    tc16_ffn2<<<dim3(DD/128, NT/128, EE), 256, GEMM16_SMEM>>>(p_W2T, b2);
    // 7) combine + residual 2
    combine_kernel<<<NT, 256>>>(out);
}

// round 11
// speedup vs baseline: 6.4376x; 1.1573x over previous
#include <cuda_runtime.h>
#include <cuda_fp16.h>
#include <cstdint>
#include <math.h>

// Problem dims
#define BB 2
#define SS 2048
#define DD 1024
#define HH 16
#define DH 64
#define FF 4096
#define EE 8
#define NT (BB*SS)   // 4096 tokens

// ---------------- scratch ----------------
__device__ __half g_h16[NT*DD];            // LN output (fp16)
__device__ __half g_q16[NT*DD];            // Q (fp16 token-major)
__device__ __half g_k16[NT*DD];            // K (fp16 token-major)
__device__ __half g_vT16[(size_t)BB*HH*DH*SS];  // V transposed: [bh][d][s]
__device__ __half g_attn16[NT*DD];         // attention out (fp16)
__device__ float  g_x1[NT*DD];             // x + attn@Wo (fp32)
__device__ __half g_x116[NT*DD];           // fp16 shadow
__device__ int    g_cnt[EE];
__device__ int    g_tok[EE*NT];
__device__ int    g_slotid[EE*NT];
__device__ float  g_wt[EE*NT];
__device__ __half g_h116[(size_t)EE*NT*FF];
__device__ float  g_contrib[(size_t)2*NT*DD];
// fp16 transposed weights: [n][k] K-major
__device__ __half g_WqT16[DD*DD];
__device__ __half g_WkT16[DD*DD];
__device__ __half g_WvT16[DD*DD];
__device__ __half g_WoT16[DD*DD];
__device__ __half g_W1T16[(size_t)EE*(size_t)FF*DD];
__device__ __half g_W2T16[(size_t)EE*(size_t)DD*FF];

// ---------------- cp.async helpers ----------------
__device__ __forceinline__ void cpa16(const void* dst, const void* src) {
    unsigned d = (unsigned)__cvta_generic_to_shared(dst);
    asm volatile("cp.async.cg.shared.global [%0], [%1], 16;" :: "r"(d), "l"(src));
}
#define CPA_COMMIT()  asm volatile("cp.async.commit_group;")
#define CPA_WAIT(N)   asm volatile("cp.async.wait_group %0;" :: "n"(N))

// fp16 m16n8k16, fp32 accum
__device__ __forceinline__ void mma16(float (&c)[4], const uint32_t (&a)[4],
                                      uint32_t b0, uint32_t b1) {
    asm volatile("mma.sync.aligned.m16n8k16.row.col.f32.f16.f16.f32 "
        "{%0,%1,%2,%3}, {%4,%5,%6,%7}, {%8,%9}, {%0,%1,%2,%3};"
        : "+f"(c[0]), "+f"(c[1]), "+f"(c[2]), "+f"(c[3])
        : "r"(a[0]), "r"(a[1]), "r"(a[2]), "r"(a[3]), "r"(b0), "r"(b1));
}
// ldmatrix x4 (b16)
__device__ __forceinline__ void ldsm4(uint32_t (&r)[4], uint32_t addr) {
    asm volatile("ldmatrix.sync.aligned.m8n8.x4.shared.b16 {%0,%1,%2,%3}, [%4];"
        : "=r"(r[0]), "=r"(r[1]), "=r"(r[2]), "=r"(r[3]) : "r"(addr));
}

// ---------------- fp16 GEMM core (ldmatrix fragments, single barrier per K-slab) ----------------
#define HSTR 40
#define STG_HALVES (128*HSTR)
#define GEMM16_SMEM (8*STG_HALVES*2)

__device__ __forceinline__ void gemm16_core(const __half* a_src, const __half* b_src,
                                            int Kd, float (&acc)[4][4][4], __half* smem) {
    const int t = threadIdx.x;
    const int lane = t & 31, warp = t >> 5;
    const int wm = (warp >> 2) * 64, wn = (warp & 3) * 32;
    const int r = t >> 1, h = t & 1;

    __half* Asm = smem;
    __half* Bsm = smem + 4 * STG_HALVES;
    __half* ad0 = Asm + (size_t)r * HSTR + h * 16;
    __half* bd0 = Bsm + (size_t)r * HSTR + h * 16;

    // ldmatrix per-thread offsets (bytes, within a stage buffer)
    const int a_row = (lane & 7) + ((lane >> 3) & 1) * 8;   // A: m8-group select
    const int a_col = (lane >> 4) * 8;                      // A: k8-group select
    const int b_row = (lane & 7) + (lane >> 4) * 8;         // B: n8-pair select
    const int b_col = ((lane >> 3) & 1) * 8;                // B: k8-group select
    uint32_t As_u = (uint32_t)__cvta_generic_to_shared(Asm);
    uint32_t Bs_u = (uint32_t)__cvta_generic_to_shared(Bsm);
    uint32_t aoff[4];
#pragma unroll
    for (int i = 0; i < 4; i++)
        aoff[i] = ((wm + i*16 + a_row) * HSTR + a_col) * 2;
    uint32_t boff0 = ((wn +      b_row) * HSTR + b_col) * 2;
    uint32_t boff1 = ((wn + 16 + b_row) * HSTR + b_col) * 2;

#define LD_STAGE(s, buf) { \
        const __half* as_ = a_src + (s) * 32; \
        const __half* bs_ = b_src + (s) * 32; \
        __half* ad_ = ad0 + (buf) * STG_HALVES; \
        __half* bd_ = bd0 + (buf) * STG_HALVES; \
        cpa16(ad_, as_); cpa16(ad_ + 8, as_ + 8); \
        cpa16(bd_, bs_); cpa16(bd_ + 8, bs_ + 8); }

    const int steps = Kd / 32;
    LD_STAGE(0, 0); CPA_COMMIT();
    LD_STAGE(1, 1); CPA_COMMIT();
    LD_STAGE(2, 2); CPA_COMMIT();

    for (int s = 0; s < steps; s++) {
        CPA_WAIT(2);
        __syncthreads();          // single barrier: also protects buffer reuse
        const int nx = s + 3;
        if (nx < steps) LD_STAGE(nx, nx & 3);
        CPA_COMMIT();
        const uint32_t Asb = As_u + (s & 3) * STG_HALVES * 2;
        const uint32_t Bsb = Bs_u + (s & 3) * STG_HALVES * 2;
#pragma unroll
        for (int ks = 0; ks < 2; ks++) {
            const uint32_t kadd = ks * 32;   // 16 halves
            uint32_t a[4][4], b0[4], b1[4];
#pragma unroll
            for (int i = 0; i < 4; i++) ldsm4(a[i], Asb + aoff[i] + kadd);
            ldsm4(b0, Bsb + boff0 + kadd);   // regs: j0.lo, j0.hi, j1.lo, j1.hi
            ldsm4(b1, Bsb + boff1 + kadd);   // regs: j2.lo, j2.hi, j3.lo, j3.hi
#pragma unroll
            for (int i = 0; i < 4; i++) {
                mma16(acc[i][0], a[i], b0[0], b0[1]);
                mma16(acc[i][1], a[i], b0[2], b0[3]);
                mma16(acc[i][2], a[i], b1[0], b1[1]);
                mma16(acc[i][3], a[i], b1[2], b1[3]);
            }
        }
    }
#undef LD_STAGE
}

// ---------------- transpose + fp32->fp16 ----------------
__global__ void tr16_kernel(const float* __restrict__ src, __half* __restrict__ dst,
                            int R, int C) {
    __shared__ float tl[32][33];
    const size_t zsrc = (size_t)blockIdx.z * R * C;
    const int bx = blockIdx.x * 32, by = blockIdx.y * 32;
    const int tx = threadIdx.x, ty = threadIdx.y;
#pragma unroll
    for (int i = 0; i < 32; i += 8)
        tl[ty + i][tx] = src[zsrc + (size_t)(by + ty + i) * C + bx + tx];
    __syncthreads();
#pragma unroll
    for (int i = 0; i < 32; i += 8)
        dst[zsrc + (size_t)(bx + ty + i) * R + by + tx] = __float2half(tl[tx][ty + i]);
}

// ---------------- layernorm (fp16 out) ----------------
__global__ void ln_kernel(const float* __restrict__ x, const float* __restrict__ g,
                          const float* __restrict__ b) {
    __shared__ float red[256];
    int t = blockIdx.x, tid = threadIdx.x;
    const float* xr = x + (size_t)t * DD;
    float v[4], s = 0.f, s2 = 0.f;
#pragma unroll
    for (int i = 0; i < 4; i++) {
        float vv = xr[tid + i*256];
        v[i] = vv; s += vv; s2 += vv*vv;
    }
    red[tid] = s; __syncthreads();
    for (int o = 128; o > 0; o >>= 1) { if (tid < o) red[tid] += red[tid+o]; __syncthreads(); }
    float mean = red[0] * (1.f/DD);
    __syncthreads();
    red[tid] = s2; __syncthreads();
    for (int o = 128; o > 0; o >>= 1) { if (tid < o) red[tid] += red[tid+o]; __syncthreads(); }
    float var = red[0] * (1.f/DD) - mean*mean;
    float rs = rsqrtf(var + 1e-5f);
    __half* out = g_h16 + (size_t)t * DD;
#pragma unroll
    for (int i = 0; i < 4; i++) {
        int c = tid + i*256;
        out[c] = __float2half((v[i]-mean)*rs*g[c] + b[c]);
    }
}

// ---------------- QKV (fp16 mma; Q/K fp16 token-major, V transposed) ----------------
__global__ void tc16_qkv(const __half* __restrict__ BqT, const __half* __restrict__ BkT,
                         const __half* __restrict__ BvT) {
    extern __shared__ __half smh[];
    const __half* BT = blockIdx.z == 0 ? BqT : blockIdx.z == 1 ? BkT : BvT;
    const int m0 = blockIdx.y * 128, n0 = blockIdx.x * 128;
    const int t = threadIdx.x, lane = t & 31, warp = t >> 5;
    const int g = lane >> 2, q = lane & 3;
    const int wm = (warp >> 2) * 64, wn = (warp & 3) * 32;
    const int r = t >> 1, h = t & 1;
    float acc[4][4][4] = {};
    const __half* a_src = g_h16 + (size_t)(m0 + r) * DD + h * 16;
    const __half* b_src = BT + (size_t)(n0 + r) * DD + h * 16;
    gemm16_core(a_src, b_src, DD, acc, smh);

    if (blockIdx.z == 2) {
        // V: write transposed g_vT16[bh][d][s]
#pragma unroll
        for (int i = 0; i < 4; i++) {
            int r0 = m0 + wm + i*16 + g;
#pragma unroll
            for (int j = 0; j < 4; j++) {
                int c0 = n0 + wn + j*8 + 2*q;
                int hh = c0 >> 6, dd = c0 & 63;
#pragma unroll
                for (int hf = 0; hf < 2; hf++) {
                    int row = r0 + hf*8;
                    int b_ = row >> 11, s_ = row & 2047;
                    size_t basev = ((size_t)(b_*HH + hh) * DH);
                    g_vT16[(basev + dd)     * SS + s_] = __float2half(acc[i][j][hf*2+0]);
                    g_vT16[(basev + dd + 1) * SS + s_] = __float2half(acc[i][j][hf*2+1]);
                }
            }
        }
    } else {
        __half* C = blockIdx.z == 0 ? g_q16 : g_k16;
#pragma unroll
        for (int i = 0; i < 4; i++) {
            int r0 = m0 + wm + i*16 + g;
#pragma unroll
            for (int j = 0; j < 4; j++) {
                int c0 = n0 + wn + j*8 + 2*q;
                *(__half2*)&C[(size_t)r0 * DD + c0] =
                    __floats2half2_rn(acc[i][j][0], acc[i][j][1]);
                *(__half2*)&C[(size_t)(r0+8) * DD + c0] =
                    __floats2half2_rn(acc[i][j][2], acc[i][j][3]);
            }
        }
    }
}

// ---------------- fp16 flash attention (unchanged from R10) ----------------
#define AST 72
#define ATT_SMEM ((128*AST + 2*64*AST + 2*64*AST) * 2)
__global__ void attn16() {
    extern __shared__ __half ash[];
    __half (*Qs)[AST]       = (__half(*)[AST])ash;
    __half (*Ks)[64][AST]   = (__half(*)[64][AST])(ash + 128*AST);
    __half (*Vts)[64][AST]  = (__half(*)[64][AST])(ash + 128*AST + 2*64*AST);

    const int tid = threadIdx.x;
    const int lane = tid & 31, w = tid >> 5;
    const int g = lane >> 2, q = lane & 3;
    const int bh = blockIdx.y, b = bh >> 4, h = bh & 15;
    const int q0 = blockIdx.x * 128;
    const size_t tokbase = ((size_t)b*SS)*DD + h*DH;
    const size_t vtbase  = (size_t)bh * DH * SS;
    const int pr = w * 16;

    {
        int r = tid >> 1, cq = (tid & 1) * 32;
        const __half* src = g_q16 + tokbase + (size_t)(q0 + r)*DD + cq;
        cpa16(&Qs[r][cq],      src);      cpa16(&Qs[r][cq + 8],  src + 8);
        cpa16(&Qs[r][cq + 16], src + 16); cpa16(&Qs[r][cq + 24], src + 24);
    }
    {
        int r = tid >> 2, cq = (tid & 3) * 16;
        const __half* ksrc = g_k16 + tokbase + (size_t)r*DD + cq;
        cpa16(&Ks[0][r][cq], ksrc); cpa16(&Ks[0][r][cq + 8], ksrc + 8);
        const __half* vsrc = g_vT16 + vtbase + (size_t)r*SS + cq;
        cpa16(&Vts[0][r][cq], vsrc); cpa16(&Vts[0][r][cq + 8], vsrc + 8);
    }
    CPA_COMMIT();
    {
        int r = tid >> 2, cq = (tid & 3) * 16;
        const __half* ksrc = g_k16 + tokbase + (size_t)(64 + r)*DD + cq;
        cpa16(&Ks[1][r][cq], ksrc); cpa16(&Ks[1][r][cq + 8], ksrc + 8);
        const __half* vsrc = g_vT16 + vtbase + (size_t)r*SS + 64 + cq;
        cpa16(&Vts[1][r][cq], vsrc); cpa16(&Vts[1][r][cq + 8], vsrc + 8);
    }
    CPA_COMMIT();

    CPA_WAIT(1);
    __syncthreads();

    uint32_t aq[4][4];
#pragma unroll
    for (int ks = 0; ks < 4; ks++) {
        const int ko = ks*16 + 2*q;
        aq[ks][0] = *(const uint32_t*)&Qs[pr+g][ko];
        aq[ks][1] = *(const uint32_t*)&Qs[pr+8+g][ko];
        aq[ks][2] = *(const uint32_t*)&Qs[pr+g][ko + 8];
        aq[ks][3] = *(const uint32_t*)&Qs[pr+8+g][ko + 8];
    }
    __half (*Ps)[AST] = Qs;

    float m0r = -1e30f, m1r = -1e30f, l0 = 0.f, l1 = 0.f;
    float acc_o[8][4];
#pragma unroll
    for (int j = 0; j < 8; j++) { acc_o[j][0]=0.f; acc_o[j][1]=0.f; acc_o[j][2]=0.f; acc_o[j][3]=0.f; }

    for (int kt = 0; kt < SS/64; kt++) {
        CPA_WAIT(1);
        __syncthreads();
        const int buf = kt & 1;

        float s[8][4];
#pragma unroll
        for (int j = 0; j < 8; j++) { s[j][0]=0.f; s[j][1]=0.f; s[j][2]=0.f; s[j][3]=0.f; }
#pragma unroll
        for (int ks = 0; ks < 4; ks++) {
            const int ko = ks*16 + 2*q;
#pragma unroll
            for (int j = 0; j < 8; j++) {
                uint32_t b0 = *(const uint32_t*)&Ks[buf][j*8+g][ko];
                uint32_t b1 = *(const uint32_t*)&Ks[buf][j*8+g][ko + 8];
                mma16(s[j], aq[ks], b0, b1);
            }
        }
        float mx0 = m0r, mx1 = m1r;
#pragma unroll
        for (int j = 0; j < 8; j++) {
            s[j][0] *= 0.125f; s[j][1] *= 0.125f; s[j][2] *= 0.125f; s[j][3] *= 0.125f;
            mx0 = fmaxf(mx0, fmaxf(s[j][0], s[j][1]));
            mx1 = fmaxf(mx1, fmaxf(s[j][2], s[j][3]));
        }
        mx0 = fmaxf(mx0, __shfl_xor_sync(0xffffffffu, mx0, 1));
        mx0 = fmaxf(mx0, __shfl_xor_sync(0xffffffffu, mx0, 2));
        mx1 = fmaxf(mx1, __shfl_xor_sync(0xffffffffu, mx1, 1));
        mx1 = fmaxf(mx1, __shfl_xor_sync(0xffffffffu, mx1, 2));
        float alpha0 = __expf(m0r - mx0), alpha1 = __expf(m1r - mx1);
        m0r = mx0; m1r = mx1;
        float ps0 = 0.f, ps1 = 0.f;
#pragma unroll
        for (int j = 0; j < 8; j++) {
            s[j][0] = __expf(s[j][0] - mx0); ps0 += s[j][0];
            s[j][1] = __expf(s[j][1] - mx0); ps0 += s[j][1];
            s[j][2] = __expf(s[j][2] - mx1); ps1 += s[j][2];
            s[j][3] = __expf(s[j][3] - mx1); ps1 += s[j][3];
        }
        ps0 += __shfl_xor_sync(0xffffffffu, ps0, 1);
        ps0 += __shfl_xor_sync(0xffffffffu, ps0, 2);
        ps1 += __shfl_xor_sync(0xffffffffu, ps1, 1);
        ps1 += __shfl_xor_sync(0xffffffffu, ps1, 2);
        l0 = l0 * alpha0 + ps0;
        l1 = l1 * alpha1 + ps1;
#pragma unroll
        for (int j = 0; j < 8; j++) {
            acc_o[j][0] *= alpha0; acc_o[j][1] *= alpha0;
            acc_o[j][2] *= alpha1; acc_o[j][3] *= alpha1;
        }
#pragma unroll
        for (int j = 0; j < 8; j++) {
            *(__half2*)&Ps[pr+g][j*8 + 2*q]   = __floats2half2_rn(s[j][0], s[j][1]);
            *(__half2*)&Ps[pr+8+g][j*8 + 2*q] = __floats2half2_rn(s[j][2], s[j][3]);
        }
        __syncwarp();
#pragma unroll
        for (int ks = 0; ks < 4; ks++) {
            const int ko = ks*16 + 2*q;
            uint32_t ap[4];
            ap[0] = *(const uint32_t*)&Ps[pr+g][ko];
            ap[1] = *(const uint32_t*)&Ps[pr+8+g][ko];
            ap[2] = *(const uint32_t*)&Ps[pr+g][ko + 8];
            ap[3] = *(const uint32_t*)&Ps[pr+8+g][ko + 8];
#pragma unroll
            for (int j = 0; j < 8; j++) {
                uint32_t b0 = *(const uint32_t*)&Vts[buf][j*8+g][ko];
                uint32_t b1 = *(const uint32_t*)&Vts[buf][j*8+g][ko + 8];
                mma16(acc_o[j], ap, b0, b1);
            }
        }
        __syncthreads();
        if (kt + 2 < SS/64) {
            int r = tid >> 2, cq = (tid & 3) * 16;
            const __half* ksrc = g_k16 + tokbase + (size_t)((kt+2)*64 + r)*DD + cq;
            cpa16(&Ks[buf][r][cq], ksrc); cpa16(&Ks[buf][r][cq + 8], ksrc + 8);
            const __half* vsrc = g_vT16 + vtbase + (size_t)r*SS + (kt+2)*64 + cq;
            cpa16(&Vts[buf][r][cq], vsrc); cpa16(&Vts[buf][r][cq + 8], vsrc + 8);
        }
        CPA_COMMIT();
    }
    float inv0 = 1.f / l0, inv1 = 1.f / l1;
    int row0 = q0 + pr + g;
#pragma unroll
    for (int j = 0; j < 8; j++) {
        int col = j*8 + 2*q;
        *(__half2*)&g_attn16[tokbase + (size_t)row0 * DD + col] =
            __floats2half2_rn(acc_o[j][0]*inv0, acc_o[j][1]*inv0);
        *(__half2*)&g_attn16[tokbase + (size_t)(row0+8) * DD + col] =
            __floats2half2_rn(acc_o[j][2]*inv1, acc_o[j][3]*inv1);
    }
}

// ---------------- O-proj + residual ----------------
__global__ void tc16_oproj(const __half* __restrict__ BT, const float* __restrict__ Rres) {
    extern __shared__ __half smh[];
    const int m0 = blockIdx.y * 128, n0 = blockIdx.x * 128;
    const int t = threadIdx.x, lane = t & 31, warp = t >> 5;
    const int g = lane >> 2, q = lane & 3;
    const int wm = (warp >> 2) * 64, wn = (warp & 3) * 32;
    const int r = t >> 1, h = t & 1;
    float acc[4][4][4] = {};
    const __half* a_src = g_attn16 + (size_t)(m0 + r) * DD + h * 16;
    const __half* b_src = BT + (size_t)(n0 + r) * DD + h * 16;
    gemm16_core(a_src, b_src, DD, acc, smh);
#pragma unroll
    for (int i = 0; i < 4; i++) {
        int r0 = m0 + wm + i*16 + g;
#pragma unroll
        for (int j = 0; j < 4; j++) {
            int c0 = n0 + wn + j*8 + 2*q;
#pragma unroll
            for (int hf = 0; hf < 2; hf++) {
                size_t idx = (size_t)(r0 + hf*8) * DD + c0;
                float2 u = *(const float2*)&Rres[idx];
                float v0 = acc[i][j][hf*2+0] + u.x;
                float v1 = acc[i][j][hf*2+1] + u.y;
                *(float2*)&g_x1[idx] = make_float2(v0, v1);
                *(__half2*)&g_x116[idx] = __floats2half2_rn(v0, v1);
            }
        }
    }
}

// ---------------- FFN1 ----------------
__global__ void tc16_ffn1(const __half* __restrict__ W1T, const float* __restrict__ b1) {
    const int e = blockIdx.z;
    const int cnt = g_cnt[e];
    const int m0 = blockIdx.y * 128;
    if (m0 >= cnt) return;
    extern __shared__ __half smh[];
    const int n0 = blockIdx.x * 128;
    const int t = threadIdx.x, lane = t & 31, warp = t >> 5;
    const int g = lane >> 2, q = lane & 3;
    const int wm = (warp >> 2) * 64, wn = (warp & 3) * 32;
    const int r = t >> 1, h = t & 1;
    int ar = m0 + r; if (ar > cnt - 1) ar = cnt - 1;
    const int tok = g_tok[e * NT + ar];
    float acc[4][4][4] = {};
    const __half* a_src = g_x116 + (size_t)tok * DD + h * 16;
    const __half* b_src = W1T + (size_t)e * FF * DD + (size_t)(n0 + r) * DD + h * 16;
    gemm16_core(a_src, b_src, DD, acc, smh);
#pragma unroll
    for (int i = 0; i < 4; i++) {
        int r0 = m0 + wm + i*16 + g;
#pragma unroll
        for (int j = 0; j < 4; j++) {
            int c0 = n0 + wn + j*8 + 2*q;
            float bb0 = b1[e*FF + c0], bb1 = b1[e*FF + c0 + 1];
#pragma unroll
            for (int hf = 0; hf < 2; hf++) {
                int rr = r0 + hf*8;
                if (rr >= cnt) continue;
                float u0 = acc[i][j][hf*2+0] + bb0;
                float u1 = acc[i][j][hf*2+1] + bb1;
                float g0 = 0.5f*u0*(1.f + tanhf(0.7978845608028654f*(u0 + 0.044715f*u0*u0*u0)));
                float g1 = 0.5f*u1*(1.f + tanhf(0.7978845608028654f*(u1 + 0.044715f*u1*u1*u1)));
                *(__half2*)&g_h116[((size_t)e*NT + rr)*FF + c0] = __floats2half2_rn(g0, g1);
            }
        }
    }
}

// ---------------- FFN2 ----------------
__global__ void tc16_ffn2(const __half* __restrict__ W2T, const float* __restrict__ b2) {
    const int e = blockIdx.z;
    const int cnt = g_cnt[e];
    const int m0 = blockIdx.y * 128;
    if (m0 >= cnt) return;
    extern __shared__ __half smh[];
    const int n0 = blockIdx.x * 128;
    const int t = threadIdx.x, lane = t & 31, warp = t >> 5;
    const int g = lane >> 2, q = lane & 3;
    const int wm = (warp >> 2) * 64, wn = (warp & 3) * 32;
    const int r = t >> 1, h = t & 1;
    int ar = m0 + r; if (ar > cnt - 1) ar = cnt - 1;
    float acc[4][4][4] = {};
    const __half* a_src = g_h116 + ((size_t)e*NT + ar) * FF + h * 16;
    const __half* b_src = W2T + (size_t)e * DD * FF + (size_t)(n0 + r) * FF + h * 16;
    gemm16_core(a_src, b_src, FF, acc, smh);
#pragma unroll
    for (int i = 0; i < 4; i++) {
        int r0 = m0 + wm + i*16 + g;
#pragma unroll
        for (int j = 0; j < 4; j++) {
            int c0 = n0 + wn + j*8 + 2*q;
            float bb0 = b2[e*DD + c0], bb1 = b2[e*DD + c0 + 1];
#pragma unroll
            for (int hf = 0; hf < 2; hf++) {
                int rr = r0 + hf*8;
                if (rr >= cnt) continue;
                int slot = g_slotid[e*NT + rr];
                float w  = g_wt[e*NT + rr];
                *(float2*)&g_contrib[(size_t)slot * DD + c0] =
                    make_float2(w * (acc[i][j][hf*2+0] + bb0),
                                w * (acc[i][j][hf*2+1] + bb1));
            }
        }
    }
}

// ---------------- gate ----------------
__global__ void zero_cnt_kernel() { if (threadIdx.x < EE) g_cnt[threadIdx.x] = 0; }

__global__ void gate_kernel(const float* __restrict__ Wg) {
    __shared__ float lg[EE];
    int t = blockIdx.x, tid = threadIdx.x;
    int w = tid >> 5, lane = tid & 31;
    const float* xr = g_x1 + (size_t)t * DD;
    float s = 0.f;
    for (int d = lane; d < DD; d += 32) s += xr[d] * Wg[d*EE + w];
#pragma unroll
    for (int o = 16; o > 0; o >>= 1) s += __shfl_down_sync(0xffffffffu, s, o);
    if (lane == 0) lg[w] = s;
    __syncthreads();
    if (tid == 0) {
        float v0 = -1e30f; int i0 = 0;
        for (int e = 0; e < EE; e++) if (lg[e] > v0) { v0 = lg[e]; i0 = e; }
        float v1 = -1e30f; int i1 = 0;
        for (int e = 0; e < EE; e++) if (e != i0 && lg[e] > v1) { v1 = lg[e]; i1 = e; }
        float e1 = __expf(v1 - v0);
        float w0 = 1.f / (1.f + e1);
        float w1 = e1 / (1.f + e1);
        int p0 = atomicAdd(&g_cnt[i0], 1);
        g_tok[i0*NT + p0] = t; g_slotid[i0*NT + p0] = 2*t;     g_wt[i0*NT + p0] = w0;
        int p1 = atomicAdd(&g_cnt[i1], 1);
        g_tok[i1*NT + p1] = t; g_slotid[i1*NT + p1] = 2*t + 1; g_wt[i1*NT + p1] = w1;
    }
}

// ---------------- final combine ----------------
__global__ void combine_kernel(float* __restrict__ out) {
    int t = blockIdx.x;
    int c = threadIdx.x * 4;
    size_t idx = (size_t)t * DD + c;
    float4 a  = *(const float4*)&g_x1[idx];
    float4 c0 = *(const float4*)&g_contrib[(size_t)(2*t)*DD + c];
    float4 c1 = *(const float4*)&g_contrib[(size_t)(2*t+1)*DD + c];
    float4 o = make_float4(a.x+c0.x+c1.x, a.y+c0.y+c1.y, a.z+c0.z+c1.z, a.w+c0.w+c1.w);
    *(float4*)&out[idx] = o;
}

// ---------------- launch ----------------
extern "C" void kernel_launch(void* const* d_in, const int* in_sizes, int n_in,
                              void* d_out, int out_size) {
    const float* x    = (const float*)d_in[0];
    const float* ln_g = (const float*)d_in[1];
    const float* ln_b = (const float*)d_in[2];
    const float* Wq   = (const float*)d_in[3];
    const float* Wk   = (const float*)d_in[4];
    const float* Wv   = (const float*)d_in[5];
    const float* Wo   = (const float*)d_in[6];
    const float* Wg   = (const float*)d_in[7];
    const float* W1   = (const float*)d_in[8];
    const float* b1   = (const float*)d_in[9];
    const float* W2   = (const float*)d_in[10];
    const float* b2   = (const float*)d_in[11];
    float* out = (float*)d_out;

    __half *p_WqT, *p_WkT, *p_WvT, *p_WoT, *p_W1T, *p_W2T;
    cudaGetSymbolAddress((void**)&p_WqT, g_WqT16);
    cudaGetSymbolAddress((void**)&p_WkT, g_WkT16);
    cudaGetSymbolAddress((void**)&p_WvT, g_WvT16);
    cudaGetSymbolAddress((void**)&p_WoT, g_WoT16);
    cudaGetSymbolAddress((void**)&p_W1T, g_W1T16);
    cudaGetSymbolAddress((void**)&p_W2T, g_W2T16);

    cudaFuncSetAttribute(tc16_qkv,   cudaFuncAttributeMaxDynamicSharedMemorySize, GEMM16_SMEM);
    cudaFuncSetAttribute(tc16_oproj, cudaFuncAttributeMaxDynamicSharedMemorySize, GEMM16_SMEM);
    cudaFuncSetAttribute(tc16_ffn1,  cudaFuncAttributeMaxDynamicSharedMemorySize, GEMM16_SMEM);
    cudaFuncSetAttribute(tc16_ffn2,  cudaFuncAttributeMaxDynamicSharedMemorySize, GEMM16_SMEM);
    cudaFuncSetAttribute(attn16,     cudaFuncAttributeMaxDynamicSharedMemorySize, ATT_SMEM);

    // 0) weight transpose + fp16 convert
    dim3 trt(32, 8);
    tr16_kernel<<<dim3(32, 32, 1), trt>>>(Wq, p_WqT, DD, DD);
    tr16_kernel<<<dim3(32, 32, 1), trt>>>(Wk, p_WkT, DD, DD);
    tr16_kernel<<<dim3(32, 32, 1), trt>>>(Wv, p_WvT, DD, DD);
    tr16_kernel<<<dim3(32, 32, 1), trt>>>(Wo, p_WoT, DD, DD);
    tr16_kernel<<<dim3(FF/32, DD/32, EE), trt>>>(W1, p_W1T, DD, FF);
    tr16_kernel<<<dim3(DD/32, FF/32, EE), trt>>>(W2, p_W2T, FF, DD);
    // 1) layernorm (fp16 out)
    ln_kernel<<<NT, 256>>>(x, ln_g, ln_b);
    // 2) QKV projections (fp16 mma; V written transposed)
    tc16_qkv<<<dim3(DD/128, NT/128, 3), 256, GEMM16_SMEM>>>(p_WqT, p_WkT, p_WvT);
    // 3) fp16 flash attention
    attn16<<<dim3(SS/128, BB*HH), 256, ATT_SMEM>>>();
    // 4) O projection + residual
    tc16_oproj<<<dim3(DD/128, NT/128), 256, GEMM16_SMEM>>>(p_WoT, x);
    // 5) gate + binning
    zero_cnt_kernel<<<1, 32>>>();
    gate_kernel<<<NT, 256>>>(Wg);
    // 6) grouped expert FFN (fp16 mma)
    tc16_ffn1<<<dim3(FF/128, NT/128, EE), 256, GEMM16_SMEM>>>(p_W1T, b1);
    tc16_ffn2<<<dim3(DD/128, NT/128, EE), 256, GEMM16_SMEM>>>(p_W2T, b2);
    // 7) combine + residual 2
    combine_kernel<<<NT, 256>>>(out);
}

// round 12
// speedup vs baseline: 6.5535x; 1.0180x over previous
#include <cuda_runtime.h>
#include <cuda_fp16.h>
#include <cstdint>
#include <math.h>

// Problem dims
#define BB 2
#define SS 2048
#define DD 1024
#define HH 16
#define DH 64
#define FF 4096
#define EE 8
#define NT (BB*SS)   // 4096 tokens

// ---------------- scratch ----------------
__device__ __half g_h16[NT*DD];
__device__ __half g_q16[NT*DD];
__device__ __half g_k16[NT*DD];
__device__ __half g_vT16[(size_t)BB*HH*DH*SS];  // V transposed: [bh][d][s]
__device__ __half g_attn16[NT*DD];
__device__ float  g_x1[NT*DD];
__device__ __half g_x116[NT*DD];
__device__ int    g_cnt[EE];
__device__ int    g_tok[EE*NT];
__device__ int    g_slotid[EE*NT];
__device__ float  g_wt[EE*NT];
__device__ __half g_h116[(size_t)EE*NT*FF];
__device__ float  g_contrib[(size_t)2*NT*DD];
__device__ __half g_WqT16[DD*DD];
__device__ __half g_WkT16[DD*DD];
__device__ __half g_WvT16[DD*DD];
__device__ __half g_WoT16[DD*DD];
__device__ __half g_W1T16[(size_t)EE*(size_t)FF*DD];
__device__ __half g_W2T16[(size_t)EE*(size_t)DD*FF];

// ---------------- cp.async helpers ----------------
__device__ __forceinline__ void cpa16(const void* dst, const void* src) {
    unsigned d = (unsigned)__cvta_generic_to_shared(dst);
    asm volatile("cp.async.cg.shared.global [%0], [%1], 16;" :: "r"(d), "l"(src));
}
#define CPA_COMMIT()  asm volatile("cp.async.commit_group;")
#define CPA_WAIT(N)   asm volatile("cp.async.wait_group %0;" :: "n"(N))

// fp16 m16n8k16, fp32 accum
__device__ __forceinline__ void mma16(float (&c)[4], const uint32_t (&a)[4],
                                      uint32_t b0, uint32_t b1) {
    asm volatile("mma.sync.aligned.m16n8k16.row.col.f32.f16.f16.f32 "
        "{%0,%1,%2,%3}, {%4,%5,%6,%7}, {%8,%9}, {%0,%1,%2,%3};"
        : "+f"(c[0]), "+f"(c[1]), "+f"(c[2]), "+f"(c[3])
        : "r"(a[0]), "r"(a[1]), "r"(a[2]), "r"(a[3]), "r"(b0), "r"(b1));
}
// ldmatrix x4 (b16)
__device__ __forceinline__ void ldsm4(uint32_t (&r)[4], uint32_t addr) {
    asm volatile("ldmatrix.sync.aligned.m8n8.x4.shared.b16 {%0,%1,%2,%3}, [%4];"
        : "=r"(r[0]), "=r"(r[1]), "=r"(r[2]), "=r"(r[3]) : "r"(addr));
}

// ---------------- fp16 GEMM core (ldmatrix fragments, single barrier per K-slab) ----------------
#define HSTR 40
#define STG_HALVES (128*HSTR)
#define GEMM16_SMEM (8*STG_HALVES*2)

__device__ __forceinline__ void gemm16_core(const __half* a_src, const __half* b_src,
                                            int Kd, float (&acc)[4][4][4], __half* smem) {
    const int t = threadIdx.x;
    const int lane = t & 31, warp = t >> 5;
    const int wm = (warp >> 2) * 64, wn = (warp & 3) * 32;
    const int r = t >> 1, h = t & 1;

    __half* Asm = smem;
    __half* Bsm = smem + 4 * STG_HALVES;
    __half* ad0 = Asm + (size_t)r * HSTR + h * 16;
    __half* bd0 = Bsm + (size_t)r * HSTR + h * 16;

    const int a_row = (lane & 7) + ((lane >> 3) & 1) * 8;
    const int a_col = (lane >> 4) * 8;
    const int b_row = (lane & 7) + (lane >> 4) * 8;
    const int b_col = ((lane >> 3) & 1) * 8;
    uint32_t As_u = (uint32_t)__cvta_generic_to_shared(Asm);
    uint32_t Bs_u = (uint32_t)__cvta_generic_to_shared(Bsm);
    uint32_t aoff[4];
#pragma unroll
    for (int i = 0; i < 4; i++)
        aoff[i] = ((wm + i*16 + a_row) * HSTR + a_col) * 2;
    uint32_t boff0 = ((wn +      b_row) * HSTR + b_col) * 2;
    uint32_t boff1 = ((wn + 16 + b_row) * HSTR + b_col) * 2;

#define LD_STAGE(s, buf) { \
        const __half* as_ = a_src + (s) * 32; \
        const __half* bs_ = b_src + (s) * 32; \
        __half* ad_ = ad0 + (buf) * STG_HALVES; \
        __half* bd_ = bd0 + (buf) * STG_HALVES; \
        cpa16(ad_, as_); cpa16(ad_ + 8, as_ + 8); \
        cpa16(bd_, bs_); cpa16(bd_ + 8, bs_ + 8); }

    const int steps = Kd / 32;
    LD_STAGE(0, 0); CPA_COMMIT();
    LD_STAGE(1, 1); CPA_COMMIT();
    LD_STAGE(2, 2); CPA_COMMIT();

    for (int s = 0; s < steps; s++) {
        CPA_WAIT(2);
        __syncthreads();
        const int nx = s + 3;
        if (nx < steps) LD_STAGE(nx, nx & 3);
        CPA_COMMIT();
        const uint32_t Asb = As_u + (s & 3) * STG_HALVES * 2;
        const uint32_t Bsb = Bs_u + (s & 3) * STG_HALVES * 2;
#pragma unroll
        for (int ks = 0; ks < 2; ks++) {
            const uint32_t kadd = ks * 32;
            uint32_t a[4][4], b0[4], b1[4];
#pragma unroll
            for (int i = 0; i < 4; i++) ldsm4(a[i], Asb + aoff[i] + kadd);
            ldsm4(b0, Bsb + boff0 + kadd);
            ldsm4(b1, Bsb + boff1 + kadd);
#pragma unroll
            for (int i = 0; i < 4; i++) {
                mma16(acc[i][0], a[i], b0[0], b0[1]);
                mma16(acc[i][1], a[i], b0[2], b0[3]);
                mma16(acc[i][2], a[i], b1[0], b1[1]);
                mma16(acc[i][3], a[i], b1[2], b1[3]);
            }
        }
    }
#undef LD_STAGE
}

// ---------------- transpose + fp32->fp16 ----------------
__global__ void tr16_kernel(const float* __restrict__ src, __half* __restrict__ dst,
                            int R, int C) {
    __shared__ float tl[32][33];
    const size_t zsrc = (size_t)blockIdx.z * R * C;
    const int bx = blockIdx.x * 32, by = blockIdx.y * 32;
    const int tx = threadIdx.x, ty = threadIdx.y;
#pragma unroll
    for (int i = 0; i < 32; i += 8)
        tl[ty + i][tx] = src[zsrc + (size_t)(by + ty + i) * C + bx + tx];
    __syncthreads();
#pragma unroll
    for (int i = 0; i < 32; i += 8)
        dst[zsrc + (size_t)(bx + ty + i) * R + by + tx] = __float2half(tl[tx][ty + i]);
}

// ---------------- layernorm (fp16 out) ----------------
__global__ void ln_kernel(const float* __restrict__ x, const float* __restrict__ g,
                          const float* __restrict__ b) {
    __shared__ float red[256];
    int t = blockIdx.x, tid = threadIdx.x;
    const float* xr = x + (size_t)t * DD;
    float v[4], s = 0.f, s2 = 0.f;
#pragma unroll
    for (int i = 0; i < 4; i++) {
        float vv = xr[tid + i*256];
        v[i] = vv; s += vv; s2 += vv*vv;
    }
    red[tid] = s; __syncthreads();
    for (int o = 128; o > 0; o >>= 1) { if (tid < o) red[tid] += red[tid+o]; __syncthreads(); }
    float mean = red[0] * (1.f/DD);
    __syncthreads();
    red[tid] = s2; __syncthreads();
    for (int o = 128; o > 0; o >>= 1) { if (tid < o) red[tid] += red[tid+o]; __syncthreads(); }
    float var = red[0] * (1.f/DD) - mean*mean;
    float rs = rsqrtf(var + 1e-5f);
    __half* out = g_h16 + (size_t)t * DD;
#pragma unroll
    for (int i = 0; i < 4; i++) {
        int c = tid + i*256;
        out[c] = __float2half((v[i]-mean)*rs*g[c] + b[c]);
    }
}

// ---------------- QKV (fp16 mma; Q/K fp16 token-major, V transposed) ----------------
__global__ void tc16_qkv(const __half* __restrict__ BqT, const __half* __restrict__ BkT,
                         const __half* __restrict__ BvT) {
    extern __shared__ __half smh[];
    const __half* BT = blockIdx.z == 0 ? BqT : blockIdx.z == 1 ? BkT : BvT;
    const int m0 = blockIdx.y * 128, n0 = blockIdx.x * 128;
    const int t = threadIdx.x, lane = t & 31, warp = t >> 5;
    const int g = lane >> 2, q = lane & 3;
    const int wm = (warp >> 2) * 64, wn = (warp & 3) * 32;
    const int r = t >> 1, h = t & 1;
    float acc[4][4][4] = {};
    const __half* a_src = g_h16 + (size_t)(m0 + r) * DD + h * 16;
    const __half* b_src = BT + (size_t)(n0 + r) * DD + h * 16;
    gemm16_core(a_src, b_src, DD, acc, smh);

    if (blockIdx.z == 2) {
#pragma unroll
        for (int i = 0; i < 4; i++) {
            int r0 = m0 + wm + i*16 + g;
#pragma unroll
            for (int j = 0; j < 4; j++) {
                int c0 = n0 + wn + j*8 + 2*q;
                int hh = c0 >> 6, dd = c0 & 63;
#pragma unroll
                for (int hf = 0; hf < 2; hf++) {
                    int row = r0 + hf*8;
                    int b_ = row >> 11, s_ = row & 2047;
                    size_t basev = ((size_t)(b_*HH + hh) * DH);
                    g_vT16[(basev + dd)     * SS + s_] = __float2half(acc[i][j][hf*2+0]);
                    g_vT16[(basev + dd + 1) * SS + s_] = __float2half(acc[i][j][hf*2+1]);
                }
            }
        }
    } else {
        __half* C = blockIdx.z == 0 ? g_q16 : g_k16;
#pragma unroll
        for (int i = 0; i < 4; i++) {
            int r0 = m0 + wm + i*16 + g;
#pragma unroll
            for (int j = 0; j < 4; j++) {
                int c0 = n0 + wn + j*8 + 2*q;
                *(__half2*)&C[(size_t)r0 * DD + c0] =
                    __floats2half2_rn(acc[i][j][0], acc[i][j][1]);
                *(__half2*)&C[(size_t)(r0+8) * DD + c0] =
                    __floats2half2_rn(acc[i][j][2], acc[i][j][3]);
            }
        }
    }
}

// ---------------- fp16 flash attention (ldmatrix fragments) ----------------
#define AST 72
#define ATT_SMEM ((128*AST + 2*64*AST + 2*64*AST) * 2)
__global__ void attn16() {
    extern __shared__ __half ash[];
    __half (*Qs)[AST]       = (__half(*)[AST])ash;                       // [128][72], reused as P
    __half (*Ks)[64][AST]   = (__half(*)[64][AST])(ash + 128*AST);
    __half (*Vts)[64][AST]  = (__half(*)[64][AST])(ash + 128*AST + 2*64*AST);

    const int tid = threadIdx.x;
    const int lane = tid & 31, w = tid >> 5;
    const int g = lane >> 2, q = lane & 3;
    const int bh = blockIdx.y, b = bh >> 4, h = bh & 15;
    const int q0 = blockIdx.x * 128;
    const size_t tokbase = ((size_t)b*SS)*DD + h*DH;
    const size_t vtbase  = (size_t)bh * DH * SS;
    const int pr = w * 16;

    // ldmatrix per-thread addressing
    const int a_row = (lane & 7) + ((lane >> 3) & 1) * 8;
    const int a_col = (lane >> 4) * 8;
    const int b_row = (lane & 7) + (lane >> 4) * 8;
    const int b_col = ((lane >> 3) & 1) * 8;
    const uint32_t Qs_u  = (uint32_t)__cvta_generic_to_shared(Qs);
    const uint32_t Ks_u  = (uint32_t)__cvta_generic_to_shared(Ks);
    const uint32_t Vts_u = (uint32_t)__cvta_generic_to_shared(Vts);
    const uint32_t a_off = ((pr + a_row) * AST + a_col) * 2;   // within Qs/Ps
    const uint32_t KBUF = 64 * AST * 2;                        // bytes per K/V buffer

    { // Q tile (group A, with KV tile 0)
        int r = tid >> 1, cq = (tid & 1) * 32;
        const __half* src = g_q16 + tokbase + (size_t)(q0 + r)*DD + cq;
        cpa16(&Qs[r][cq],      src);      cpa16(&Qs[r][cq + 8],  src + 8);
        cpa16(&Qs[r][cq + 16], src + 16); cpa16(&Qs[r][cq + 24], src + 24);
    }
    {
        int r = tid >> 2, cq = (tid & 3) * 16;
        const __half* ksrc = g_k16 + tokbase + (size_t)r*DD + cq;
        cpa16(&Ks[0][r][cq], ksrc); cpa16(&Ks[0][r][cq + 8], ksrc + 8);
        const __half* vsrc = g_vT16 + vtbase + (size_t)r*SS + cq;
        cpa16(&Vts[0][r][cq], vsrc); cpa16(&Vts[0][r][cq + 8], vsrc + 8);
    }
    CPA_COMMIT();
    {
        int r = tid >> 2, cq = (tid & 3) * 16;
        const __half* ksrc = g_k16 + tokbase + (size_t)(64 + r)*DD + cq;
        cpa16(&Ks[1][r][cq], ksrc); cpa16(&Ks[1][r][cq + 8], ksrc + 8);
        const __half* vsrc = g_vT16 + vtbase + (size_t)r*SS + 64 + cq;
        cpa16(&Vts[1][r][cq], vsrc); cpa16(&Vts[1][r][cq + 8], vsrc + 8);
    }
    CPA_COMMIT();

    CPA_WAIT(1);
    __syncthreads();

    uint32_t aq[4][4];
#pragma unroll
    for (int ks = 0; ks < 4; ks++) ldsm4(aq[ks], Qs_u + a_off + ks*32);

    float m0r = -1e30f, m1r = -1e30f, l0 = 0.f, l1 = 0.f;
    float acc_o[8][4];
#pragma unroll
    for (int j = 0; j < 8; j++) { acc_o[j][0]=0.f; acc_o[j][1]=0.f; acc_o[j][2]=0.f; acc_o[j][3]=0.f; }
    __half (*Ps)[AST] = Qs;

    for (int kt = 0; kt < SS/64; kt++) {
        CPA_WAIT(1);
        __syncthreads();
        const uint32_t kb_u = Ks_u  + (kt & 1) * KBUF;
        const uint32_t vb_u = Vts_u + (kt & 1) * KBUF;

        // scores (fp16 k16) — B fragments via ldmatrix
        float s[8][4];
#pragma unroll
        for (int j = 0; j < 8; j++) { s[j][0]=0.f; s[j][1]=0.f; s[j][2]=0.f; s[j][3]=0.f; }
#pragma unroll
        for (int ks = 0; ks < 4; ks++) {
            const uint32_t kadd = ks * 32;
#pragma unroll
            for (int p = 0; p < 4; p++) {
                uint32_t bk[4];
                ldsm4(bk, kb_u + ((p*16 + b_row) * AST + b_col) * 2 + kadd);
                mma16(s[2*p],   aq[ks], bk[0], bk[1]);
                mma16(s[2*p+1], aq[ks], bk[2], bk[3]);
            }
        }
        // online softmax (scale 0.125)
        float mx0 = m0r, mx1 = m1r;
#pragma unroll
        for (int j = 0; j < 8; j++) {
            s[j][0] *= 0.125f; s[j][1] *= 0.125f; s[j][2] *= 0.125f; s[j][3] *= 0.125f;
            mx0 = fmaxf(mx0, fmaxf(s[j][0], s[j][1]));
            mx1 = fmaxf(mx1, fmaxf(s[j][2], s[j][3]));
        }
        mx0 = fmaxf(mx0, __shfl_xor_sync(0xffffffffu, mx0, 1));
        mx0 = fmaxf(mx0, __shfl_xor_sync(0xffffffffu, mx0, 2));
        mx1 = fmaxf(mx1, __shfl_xor_sync(0xffffffffu, mx1, 1));
        mx1 = fmaxf(mx1, __shfl_xor_sync(0xffffffffu, mx1, 2));
        float alpha0 = __expf(m0r - mx0), alpha1 = __expf(m1r - mx1);
        m0r = mx0; m1r = mx1;
        float ps0 = 0.f, ps1 = 0.f;
#pragma unroll
        for (int j = 0; j < 8; j++) {
            s[j][0] = __expf(s[j][0] - mx0); ps0 += s[j][0];
            s[j][1] = __expf(s[j][1] - mx0); ps0 += s[j][1];
            s[j][2] = __expf(s[j][2] - mx1); ps1 += s[j][2];
            s[j][3] = __expf(s[j][3] - mx1); ps1 += s[j][3];
        }
        ps0 += __shfl_xor_sync(0xffffffffu, ps0, 1);
        ps0 += __shfl_xor_sync(0xffffffffu, ps0, 2);
        ps1 += __shfl_xor_sync(0xffffffffu, ps1, 1);
        ps1 += __shfl_xor_sync(0xffffffffu, ps1, 2);
        l0 = l0 * alpha0 + ps0;
        l1 = l1 * alpha1 + ps1;
#pragma unroll
        for (int j = 0; j < 8; j++) {
            acc_o[j][0] *= alpha0; acc_o[j][1] *= alpha0;
            acc_o[j][2] *= alpha1; acc_o[j][3] *= alpha1;
        }
        // stash P (fp16) into warp-local rows
#pragma unroll
        for (int j = 0; j < 8; j++) {
            *(__half2*)&Ps[pr+g][j*8 + 2*q]   = __floats2half2_rn(s[j][0], s[j][1]);
            *(__half2*)&Ps[pr+8+g][j*8 + 2*q] = __floats2half2_rn(s[j][2], s[j][3]);
        }
        __syncwarp();
        // PV (fp16 k16) — A and B fragments via ldmatrix
#pragma unroll
        for (int ks = 0; ks < 4; ks++) {
            const uint32_t kadd = ks * 32;
            uint32_t ap[4];
            ldsm4(ap, Qs_u + a_off + kadd);   // Ps overlays Qs
#pragma unroll
            for (int p = 0; p < 4; p++) {
                uint32_t bv[4];
                ldsm4(bv, vb_u + ((p*16 + b_row) * AST + b_col) * 2 + kadd);
                mma16(acc_o[2*p],   ap, bv[0], bv[1]);
                mma16(acc_o[2*p+1], ap, bv[2], bv[3]);
            }
        }
        __syncthreads();
        if (kt + 2 < SS/64) {
            int r = tid >> 2, cq = (tid & 3) * 16;
            const int buf = kt & 1;
            const __half* ksrc = g_k16 + tokbase + (size_t)((kt+2)*64 + r)*DD + cq;
            cpa16(&Ks[buf][r][cq], ksrc); cpa16(&Ks[buf][r][cq + 8], ksrc + 8);
            const __half* vsrc = g_vT16 + vtbase + (size_t)r*SS + (kt+2)*64 + cq;
            cpa16(&Vts[buf][r][cq], vsrc); cpa16(&Vts[buf][r][cq + 8], vsrc + 8);
        }
        CPA_COMMIT();
    }
    // epilogue
    float inv0 = 1.f / l0, inv1 = 1.f / l1;
    int row0 = q0 + pr + g;
#pragma unroll
    for (int j = 0; j < 8; j++) {
        int col = j*8 + 2*q;
        *(__half2*)&g_attn16[tokbase + (size_t)row0 * DD + col] =
            __floats2half2_rn(acc_o[j][0]*inv0, acc_o[j][1]*inv0);
        *(__half2*)&g_attn16[tokbase + (size_t)(row0+8) * DD + col] =
            __floats2half2_rn(acc_o[j][2]*inv1, acc_o[j][3]*inv1);
    }
}

// ---------------- O-proj + residual ----------------
__global__ void tc16_oproj(const __half* __restrict__ BT, const float* __restrict__ Rres) {
    extern __shared__ __half smh[];
    const int m0 = blockIdx.y * 128, n0 = blockIdx.x * 128;
    const int t = threadIdx.x, lane = t & 31, warp = t >> 5;
    const int g = lane >> 2, q = lane & 3;
    const int wm = (warp >> 2) * 64, wn = (warp & 3) * 32;
    const int r = t >> 1, h = t & 1;
    float acc[4][4][4] = {};
    const __half* a_src = g_attn16 + (size_t)(m0 + r) * DD + h * 16;
    const __half* b_src = BT + (size_t)(n0 + r) * DD + h * 16;
    gemm16_core(a_src, b_src, DD, acc, smh);
#pragma unroll
    for (int i = 0; i < 4; i++) {
        int r0 = m0 + wm + i*16 + g;
#pragma unroll
        for (int j = 0; j < 4; j++) {
            int c0 = n0 + wn + j*8 + 2*q;
#pragma unroll
            for (int hf = 0; hf < 2; hf++) {
                size_t idx = (size_t)(r0 + hf*8) * DD + c0;
                float2 u = *(const float2*)&Rres[idx];
                float v0 = acc[i][j][hf*2+0] + u.x;
                float v1 = acc[i][j][hf*2+1] + u.y;
                *(float2*)&g_x1[idx] = make_float2(v0, v1);
                *(__half2*)&g_x116[idx] = __floats2half2_rn(v0, v1);
            }
        }
    }
}

// ---------------- FFN1 ----------------
__global__ void tc16_ffn1(const __half* __restrict__ W1T, const float* __restrict__ b1) {
    const int e = blockIdx.z;
    const int cnt = g_cnt[e];
    const int m0 = blockIdx.y * 128;
    if (m0 >= cnt) return;
    extern __shared__ __half smh[];
    const int n0 = blockIdx.x * 128;
    const int t = threadIdx.x, lane = t & 31, warp = t >> 5;
    const int g = lane >> 2, q = lane & 3;
    const int wm = (warp >> 2) * 64, wn = (warp & 3) * 32;
    const int r = t >> 1, h = t & 1;
    int ar = m0 + r; if (ar > cnt - 1) ar = cnt - 1;
    const int tok = g_tok[e * NT + ar];
    float acc[4][4][4] = {};
    const __half* a_src = g_x116 + (size_t)tok * DD + h * 16;
    const __half* b_src = W1T + (size_t)e * FF * DD + (size_t)(n0 + r) * DD + h * 16;
    gemm16_core(a_src, b_src, DD, acc, smh);
#pragma unroll
    for (int i = 0; i < 4; i++) {
        int r0 = m0 + wm + i*16 + g;
#pragma unroll
        for (int j = 0; j < 4; j++) {
            int c0 = n0 + wn + j*8 + 2*q;
            float bb0 = b1[e*FF + c0], bb1 = b1[e*FF + c0 + 1];
#pragma unroll
            for (int hf = 0; hf < 2; hf++) {
                int rr = r0 + hf*8;
                if (rr >= cnt) continue;
                float u0 = acc[i][j][hf*2+0] + bb0;
                float u1 = acc[i][j][hf*2+1] + bb1;
                float g0 = 0.5f*u0*(1.f + tanhf(0.7978845608028654f*(u0 + 0.044715f*u0*u0*u0)));
                float g1 = 0.5f*u1*(1.f + tanhf(0.7978845608028654f*(u1 + 0.044715f*u1*u1*u1)));
                *(__half2*)&g_h116[((size_t)e*NT + rr)*FF + c0] = __floats2half2_rn(g0, g1);
            }
        }
    }
}

// ---------------- FFN2 ----------------
__global__ void tc16_ffn2(const __half* __restrict__ W2T, const float* __restrict__ b2) {
    const int e = blockIdx.z;
    const int cnt = g_cnt[e];
    const int m0 = blockIdx.y * 128;
    if (m0 >= cnt) return;
    extern __shared__ __half smh[];
    const int n0 = blockIdx.x * 128;
    const int t = threadIdx.x, lane = t & 31, warp = t >> 5;
    const int g = lane >> 2, q = lane & 3;
    const int wm = (warp >> 2) * 64, wn = (warp & 3) * 32;
    const int r = t >> 1, h = t & 1;
    int ar = m0 + r; if (ar > cnt - 1) ar = cnt - 1;
    float acc[4][4][4] = {};
    const __half* a_src = g_h116 + ((size_t)e*NT + ar) * FF + h * 16;
    const __half* b_src = W2T + (size_t)e * DD * FF + (size_t)(n0 + r) * FF + h * 16;
    gemm16_core(a_src, b_src, FF, acc, smh);
#pragma unroll
    for (int i = 0; i < 4; i++) {
        int r0 = m0 + wm + i*16 + g;
#pragma unroll
        for (int j = 0; j < 4; j++) {
            int c0 = n0 + wn + j*8 + 2*q;
            float bb0 = b2[e*DD + c0], bb1 = b2[e*DD + c0 + 1];
#pragma unroll
            for (int hf = 0; hf < 2; hf++) {
                int rr = r0 + hf*8;
                if (rr >= cnt) continue;
                int slot = g_slotid[e*NT + rr];
                float w  = g_wt[e*NT + rr];
                *(float2*)&g_contrib[(size_t)slot * DD + c0] =
                    make_float2(w * (acc[i][j][hf*2+0] + bb0),
                                w * (acc[i][j][hf*2+1] + bb1));
            }
        }
    }
}

// ---------------- gate ----------------
__global__ void zero_cnt_kernel() { if (threadIdx.x < EE) g_cnt[threadIdx.x] = 0; }

__global__ void gate_kernel(const float* __restrict__ Wg) {
    __shared__ float lg[EE];
    int t = blockIdx.x, tid = threadIdx.x;
    int w = tid >> 5, lane = tid & 31;
    const float* xr = g_x1 + (size_t)t * DD;
    float s = 0.f;
    for (int d = lane; d < DD; d += 32) s += xr[d] * Wg[d*EE + w];
#pragma unroll
    for (int o = 16; o > 0; o >>= 1) s += __shfl_down_sync(0xffffffffu, s, o);
    if (lane == 0) lg[w] = s;
    __syncthreads();
    if (tid == 0) {
        float v0 = -1e30f; int i0 = 0;
        for (int e = 0; e < EE; e++) if (lg[e] > v0) { v0 = lg[e]; i0 = e; }
        float v1 = -1e30f; int i1 = 0;
        for (int e = 0; e < EE; e++) if (e != i0 && lg[e] > v1) { v1 = lg[e]; i1 = e; }
        float e1 = __expf(v1 - v0);
        float w0 = 1.f / (1.f + e1);
        float w1 = e1 / (1.f + e1);
        int p0 = atomicAdd(&g_cnt[i0], 1);
        g_tok[i0*NT + p0] = t; g_slotid[i0*NT + p0] = 2*t;     g_wt[i0*NT + p0] = w0;
        int p1 = atomicAdd(&g_cnt[i1], 1);
        g_tok[i1*NT + p1] = t; g_slotid[i1*NT + p1] = 2*t + 1; g_wt[i1*NT + p1] = w1;
    }
}

// ---------------- final combine ----------------
__global__ void combine_kernel(float* __restrict__ out) {
    int t = blockIdx.x;
    int c = threadIdx.x * 4;
    size_t idx = (size_t)t * DD + c;
    float4 a  = *(const float4*)&g_x1[idx];
    float4 c0 = *(const float4*)&g_contrib[(size_t)(2*t)*DD + c];
    float4 c1 = *(const float4*)&g_contrib[(size_t)(2*t+1)*DD + c];
    float4 o = make_float4(a.x+c0.x+c1.x, a.y+c0.y+c1.y, a.z+c0.z+c1.z, a.w+c0.w+c1.w);
    *(float4*)&out[idx] = o;
}

// ---------------- launch ----------------
extern "C" void kernel_launch(void* const* d_in, const int* in_sizes, int n_in,
                              void* d_out, int out_size) {
    const float* x    = (const float*)d_in[0];
    const float* ln_g = (const float*)d_in[1];
    const float* ln_b = (const float*)d_in[2];
    const float* Wq   = (const float*)d_in[3];
    const float* Wk   = (const float*)d_in[4];
    const float* Wv   = (const float*)d_in[5];
    const float* Wo   = (const float*)d_in[6];
    const float* Wg   = (const float*)d_in[7];
    const float* W1   = (const float*)d_in[8];
    const float* b1   = (const float*)d_in[9];
    const float* W2   = (const float*)d_in[10];
    const float* b2   = (const float*)d_in[11];
    float* out = (float*)d_out;

    __half *p_WqT, *p_WkT, *p_WvT, *p_WoT, *p_W1T, *p_W2T;
    cudaGetSymbolAddress((void**)&p_WqT, g_WqT16);
    cudaGetSymbolAddress((void**)&p_WkT, g_WkT16);
    cudaGetSymbolAddress((void**)&p_WvT, g_WvT16);
    cudaGetSymbolAddress((void**)&p_WoT, g_WoT16);
    cudaGetSymbolAddress((void**)&p_W1T, g_W1T16);
    cudaGetSymbolAddress((void**)&p_W2T, g_W2T16);

    cudaFuncSetAttribute(tc16_qkv,   cudaFuncAttributeMaxDynamicSharedMemorySize, GEMM16_SMEM);
    cudaFuncSetAttribute(tc16_oproj, cudaFuncAttributeMaxDynamicSharedMemorySize, GEMM16_SMEM);
    cudaFuncSetAttribute(tc16_ffn1,  cudaFuncAttributeMaxDynamicSharedMemorySize, GEMM16_SMEM);
    cudaFuncSetAttribute(tc16_ffn2,  cudaFuncAttributeMaxDynamicSharedMemorySize, GEMM16_SMEM);
    cudaFuncSetAttribute(attn16,     cudaFuncAttributeMaxDynamicSharedMemorySize, ATT_SMEM);

    // 0) weight transpose + fp16 convert
    dim3 trt(32, 8);
    tr16_kernel<<<dim3(32, 32, 1), trt>>>(Wq, p_WqT, DD, DD);
    tr16_kernel<<<dim3(32, 32, 1), trt>>>(Wk, p_WkT, DD, DD);
    tr16_kernel<<<dim3(32, 32, 1), trt>>>(Wv, p_WvT, DD, DD);
    tr16_kernel<<<dim3(32, 32, 1), trt>>>(Wo, p_WoT, DD, DD);
    tr16_kernel<<<dim3(FF/32, DD/32, EE), trt>>>(W1, p_W1T, DD, FF);
    tr16_kernel<<<dim3(DD/32, FF/32, EE), trt>>>(W2, p_W2T, FF, DD);
    // 1) layernorm (fp16 out)
    ln_kernel<<<NT, 256>>>(x, ln_g, ln_b);
    // 2) QKV projections (fp16 mma; V written transposed)
    tc16_qkv<<<dim3(DD/128, NT/128, 3), 256, GEMM16_SMEM>>>(p_WqT, p_WkT, p_WvT);
    // 3) fp16 flash attention (ldmatrix)
    attn16<<<dim3(SS/128, BB*HH), 256, ATT_SMEM>>>();
    // 4) O projection + residual
    tc16_oproj<<<dim3(DD/128, NT/128), 256, GEMM16_SMEM>>>(p_WoT, x);
    // 5) gate + binning
    zero_cnt_kernel<<<1, 32>>>();
    gate_kernel<<<NT, 256>>>(Wg);
    // 6) grouped expert FFN (fp16 mma)
    tc16_ffn1<<<dim3(FF/128, NT/128, EE), 256, GEMM16_SMEM>>>(p_W1T, b1);
    tc16_ffn2<<<dim3(DD/128, NT/128, EE), 256, GEMM16_SMEM>>>(p_W2T, b2);
    // 7) combine + residual 2
    combine_kernel<<<NT, 256>>>(out);
}